// round 1
// baseline (speedup 1.0000x reference)
#include <cuda_runtime.h>
#include <math.h>

#define BSZ   64
#define NOBJ  256
#define TTOK  32
#define DIM   512
#define RREL  8
#define DK    64

#define WSTRIDE (BSZ*RREL*NOBJ*DK)   // 8,388,608 elements per projection

// ---- static device scratch (allocations are forbidden at runtime) ----
__device__ float g_proj[5ull * WSTRIDE];              // 160 MB: G1,G2,K,Q,V in (b,r,n,dk) layout
__device__ float g_tmap[(size_t)BSZ * NOBJ * NOBJ];   // 16 MB
__device__ float g_tsum[BSZ * DIM];

// ============================================================
// Kernel 1: text summary  (one block per batch)
// ============================================================
__global__ __launch_bounds__(256) void tsum_kernel(
    const float* __restrict__ t, const float* __restrict__ tmask,
    const float* __restrict__ tcw, const float* __restrict__ tcb)
{
    int bb = blockIdx.x;
    __shared__ float score[TTOK];
    const float* tb = t + (size_t)bb * TTOK * DIM;

    int warp = threadIdx.x >> 5, lane = threadIdx.x & 31;
    // 8 warps x 4 tokens
    for (int tt = warp * 4; tt < warp * 4 + 4; tt++) {
        float s = 0.f;
        for (int d = lane; d < DIM; d += 32) s += tb[tt * DIM + d] * tcw[d];
        #pragma unroll
        for (int o = 16; o > 0; o >>= 1) s += __shfl_xor_sync(0xffffffffu, s, o);
        if (lane == 0) {
            float m = tmask[bb * TTOK + tt];
            if (m == 0.f) {
                score[tt] = 0.f;     // sigmoid(-inf) = 0
            } else {
                float tc = s * m + tcb[0];        // dot on masked t
                float sg = 1.f / (1.f + expf(-tc));
                score[tt] = sg * m;               // fold mask of t_m into score
            }
        }
    }
    __syncthreads();

    for (int d = threadIdx.x; d < DIM; d += 256) {
        float acc = 0.f;
        #pragma unroll
        for (int tt = 0; tt < TTOK; tt++) acc += tb[tt * DIM + d] * score[tt];
        g_tsum[bb * DIM + d] = acc;
    }
}

// ============================================================
// Kernel 2: tmap = relu(t_summary @ tmap_w + tmap_b)
// 256 blocks x 256 threads, one column per thread, all 64 rows in regs
// ============================================================
__global__ __launch_bounds__(256) void tmap_kernel(
    const float* __restrict__ W, const float* __restrict__ bias)
{
    extern __shared__ float sT[];  // 64 x 512 fp32 = 128 KB
    for (int i = threadIdx.x; i < BSZ * DIM / 4; i += 256)
        ((float4*)sT)[i] = ((const float4*)g_tsum)[i];
    __syncthreads();

    int col = blockIdx.x * 256 + threadIdx.x;
    float acc[BSZ];
    #pragma unroll
    for (int r = 0; r < BSZ; r++) acc[r] = 0.f;

    for (int k = 0; k < DIM; k += 4) {
        float w0 = W[(size_t)(k + 0) * 65536 + col];
        float w1 = W[(size_t)(k + 1) * 65536 + col];
        float w2 = W[(size_t)(k + 2) * 65536 + col];
        float w3 = W[(size_t)(k + 3) * 65536 + col];
        #pragma unroll
        for (int r = 0; r < BSZ; r++) {
            float4 tv = *(const float4*)&sT[r * DIM + k];
            acc[r] += tv.x * w0 + tv.y * w1 + tv.z * w2 + tv.w * w3;
        }
    }
    float bv = bias[col];
    #pragma unroll
    for (int r = 0; r < BSZ; r++)
        g_tmap[(size_t)r * 65536 + col] = fmaxf(acc[r] + bv, 0.f);
}

// ============================================================
// Kernel 3: 5 projections, SGEMM 16384x512x512 each
// 128x128 tile, BK=16, 8x8 microtile, 256 threads
// ============================================================
__global__ __launch_bounds__(256) void proj_kernel(
    const float* __restrict__ vin, const float* __restrict__ bmat,
    const float* __restrict__ vmask,
    const float* __restrict__ W0, const float* __restrict__ B0,
    const float* __restrict__ W1, const float* __restrict__ B1,
    const float* __restrict__ W2, const float* __restrict__ B2,
    const float* __restrict__ W3, const float* __restrict__ B3,
    const float* __restrict__ W4, const float* __restrict__ B4)
{
    __shared__ float sA[16][132];   // transposed A tile [k][m]
    __shared__ float sB[16][132];   // B tile [k][n]

    int w = blockIdx.z;
    const float* X = (w < 2) ? bmat : vin;
    const float* W; const float* Bv;
    switch (w) {
        case 0: W = W0; Bv = B0; break;
        case 1: W = W1; Bv = B1; break;
        case 2: W = W2; Bv = B2; break;
        case 3: W = W3; Bv = B3; break;
        default: W = W4; Bv = B4; break;
    }

    int t  = threadIdx.x;
    int tx = t & 15, ty = t >> 4;
    int row0 = blockIdx.y * 128;
    int col0 = blockIdx.x * 128;

    float acc[8][8];
    #pragma unroll
    for (int i = 0; i < 8; i++)
        #pragma unroll
        for (int j = 0; j < 8; j++) acc[i][j] = 0.f;

    for (int k0 = 0; k0 < DIM; k0 += 16) {
        // A tile: 128 rows x 16 k (transposed into smem)
        {
            int row = t >> 2;
            int k4  = (t & 3) * 4;
            #pragma unroll
            for (int p = 0; p < 2; p++) {
                int rr2 = row + p * 64;
                float4 va = *(const float4*)(X + (size_t)(row0 + rr2) * DIM + k0 + k4);
                sA[k4 + 0][rr2] = va.x;
                sA[k4 + 1][rr2] = va.y;
                sA[k4 + 2][rr2] = va.z;
                sA[k4 + 3][rr2] = va.w;
            }
        }
        // B tile: 16 k x 128 cols
        {
            #pragma unroll
            for (int p = 0; p < 2; p++) {
                int idx = t + p * 256;
                int kk  = idx >> 5;
                int c4  = (idx & 31) * 4;
                *(float4*)&sB[kk][c4] =
                    *(const float4*)(W + (size_t)(k0 + kk) * DIM + col0 + c4);
            }
        }
        __syncthreads();
        #pragma unroll
        for (int k = 0; k < 16; k++) {
            float a[8], b[8];
            *(float4*)&a[0] = *(const float4*)&sA[k][ty * 8];
            *(float4*)&a[4] = *(const float4*)&sA[k][ty * 8 + 4];
            *(float4*)&b[0] = *(const float4*)&sB[k][tx * 8];
            *(float4*)&b[4] = *(const float4*)&sB[k][tx * 8 + 4];
            #pragma unroll
            for (int i = 0; i < 8; i++)
                #pragma unroll
                for (int j = 0; j < 8; j++)
                    acc[i][j] += a[i] * b[j];
        }
        __syncthreads();
    }

    // epilogue: bias, optional row mask (G1,G2), scatter to (b,r,n,dk) layout
    float* Pout = g_proj + (size_t)w * WSTRIDE;
    #pragma unroll
    for (int i = 0; i < 8; i++) {
        int row = row0 + ty * 8 + i;
        int bbi = row >> 8;
        int n   = row & 255;
        float m = (w < 2) ? vmask[row] : 1.0f;
        #pragma unroll
        for (int j = 0; j < 8; j++) {
            int c    = col0 + tx * 8 + j;
            int rrel = c >> 6;
            int d    = c & 63;
            float val = (acc[i][j] + Bv[c]) * m;
            Pout[((size_t)(bbi * RREL + rrel) * NOBJ + n) * DK + d] = val;
        }
    }
}

// ============================================================
// Kernel 4: fused attention
// one block per (b, r, 64-row n-tile); 256 threads
// ============================================================
#define PADT 68
#define SPAD 260
#define ATTN_SMEM ((4 * 64 * PADT + 64 * SPAD) * 4)   // 136192 bytes

__device__ __forceinline__ void load_tile_T(float* dst, const float* __restrict__ src)
{
    // src: 64x64 row-major -> dst transposed [k][row] with pad PADT
    int t = threadIdx.x;
    #pragma unroll
    for (int p = 0; p < 4; p++) {
        int idx = (t + p * 256) * 4;
        int row = idx >> 6, k = idx & 63;
        float4 va = *(const float4*)(src + row * 64 + k);
        dst[(k + 0) * PADT + row] = va.x;
        dst[(k + 1) * PADT + row] = va.y;
        dst[(k + 2) * PADT + row] = va.z;
        dst[(k + 3) * PADT + row] = va.w;
    }
}

__device__ __forceinline__ void load_tile_N(float* dst, const float* __restrict__ src)
{
    // src: 64x64 row-major -> dst [row][k] with pad PADT
    int t = threadIdx.x;
    #pragma unroll
    for (int p = 0; p < 4; p++) {
        int idx = (t + p * 256) * 4;
        int row = idx >> 6, k = idx & 63;
        *(float4*)(dst + row * PADT + k) = *(const float4*)(src + row * 64 + k);
    }
}

__global__ __launch_bounds__(256) void attn_kernel(
    const float* __restrict__ vmask, const float* __restrict__ vin,
    float* __restrict__ out)
{
    extern __shared__ float sm[];
    float* sG1 = sm;
    float* sK  = sm + 1 * 64 * PADT;
    float* sX  = sm + 2 * 64 * PADT;
    float* sY  = sm + 3 * 64 * PADT;
    float* sS  = sm + 4 * 64 * PADT;

    int nt = blockIdx.x, r = blockIdx.y, bb = blockIdx.z;
    int t  = threadIdx.x;
    int tx = t & 15, ty = t >> 4;

    size_t pbase = (size_t)(bb * RREL + r) * NOBJ * DK;
    const float* G1 = g_proj + 0ull * WSTRIDE + pbase;
    const float* G2 = g_proj + 1ull * WSTRIDE + pbase;
    const float* Kp = g_proj + 2ull * WSTRIDE + pbase;
    const float* Qp = g_proj + 3ull * WSTRIDE + pbase;
    const float* Vp = g_proj + 4ull * WSTRIDE + pbase;

    load_tile_T(sG1, G1 + nt * 64 * DK);
    load_tile_T(sK,  Kp + nt * 64 * DK);

    const float* tmrow = g_tmap + ((size_t)bb * NOBJ * NOBJ);

    // ---- score phase: fill sS[64][256] ----
    for (int mt = 0; mt < 4; mt++) {
        load_tile_T(sX, G2 + mt * 64 * DK);
        load_tile_T(sY, Qp + mt * 64 * DK);
        __syncthreads();

        float accG[4][4], accS[4][4];
        #pragma unroll
        for (int i = 0; i < 4; i++)
            #pragma unroll
            for (int j = 0; j < 4; j++) { accG[i][j] = 0.f; accS[i][j] = 0.f; }

        #pragma unroll 8
        for (int k = 0; k < 64; k++) {
            float4 a1 = *(const float4*)(sG1 + k * PADT + ty * 4);
            float4 b1 = *(const float4*)(sX  + k * PADT + tx * 4);
            float4 a2 = *(const float4*)(sK  + k * PADT + ty * 4);
            float4 b2 = *(const float4*)(sY  + k * PADT + tx * 4);
            float a1v[4] = {a1.x, a1.y, a1.z, a1.w};
            float b1v[4] = {b1.x, b1.y, b1.z, b1.w};
            float a2v[4] = {a2.x, a2.y, a2.z, a2.w};
            float b2v[4] = {b2.x, b2.y, b2.z, b2.w};
            #pragma unroll
            for (int i = 0; i < 4; i++)
                #pragma unroll
                for (int j = 0; j < 4; j++) {
                    accG[i][j] += a1v[i] * b1v[j];
                    accS[i][j] += a2v[i] * b2v[j];
                }
        }

        float cm[4];
        #pragma unroll
        for (int j = 0; j < 4; j++)
            cm[j] = vmask[bb * NOBJ + mt * 64 + tx * 4 + j];

        #pragma unroll
        for (int i = 0; i < 4; i++) {
            int ng = nt * 64 + ty * 4 + i;
            #pragma unroll
            for (int j = 0; j < 4; j++) {
                int mg = mt * 64 + tx * 4 + j;
                float tm = tmrow[ng * NOBJ + mg];
                float wg = fmaxf(accG[i][j], 0.f) + tm;
                float s  = logf(fmaxf(wg, 1e-6f)) + accS[i][j] * 0.125f;
                if (cm[j] == 0.f) s = -INFINITY;
                sS[(ty * 4 + i) * SPAD + mg] = s;
            }
        }
        __syncthreads();
    }

    // ---- softmax over m (rows of sS) ----
    {
        int rrow = t >> 2;
        int lanei = t & 3;
        float* rowp = sS + rrow * SPAD;
        float mx = -INFINITY;
        for (int m = lanei; m < 256; m += 4) mx = fmaxf(mx, rowp[m]);
        mx = fmaxf(mx, __shfl_xor_sync(0xffffffffu, mx, 1));
        mx = fmaxf(mx, __shfl_xor_sync(0xffffffffu, mx, 2));
        float sum = 0.f;
        for (int m = lanei; m < 256; m += 4) {
            float p = expf(rowp[m] - mx);
            rowp[m] = p;
            sum += p;
        }
        sum += __shfl_xor_sync(0xffffffffu, sum, 1);
        sum += __shfl_xor_sync(0xffffffffu, sum, 2);
        float inv = 1.f / sum;
        for (int m = lanei; m < 256; m += 4) rowp[m] *= inv;
    }
    __syncthreads();

    // ---- PV phase + residual ----
    float accO[4][4];
    #pragma unroll
    for (int i = 0; i < 4; i++)
        #pragma unroll
        for (int j = 0; j < 4; j++) accO[i][j] = 0.f;

    for (int mt = 0; mt < 4; mt++) {
        __syncthreads();
        load_tile_N(sX, Vp + mt * 64 * DK);
        __syncthreads();
        #pragma unroll 4
        for (int m = 0; m < 64; m++) {
            float p0 = sS[(ty * 4 + 0) * SPAD + mt * 64 + m];
            float p1 = sS[(ty * 4 + 1) * SPAD + mt * 64 + m];
            float p2 = sS[(ty * 4 + 2) * SPAD + mt * 64 + m];
            float p3 = sS[(ty * 4 + 3) * SPAD + mt * 64 + m];
            float4 vv = *(const float4*)(sX + m * PADT + tx * 4);
            float vvv[4] = {vv.x, vv.y, vv.z, vv.w};
            #pragma unroll
            for (int j = 0; j < 4; j++) {
                accO[0][j] += p0 * vvv[j];
                accO[1][j] += p1 * vvv[j];
                accO[2][j] += p2 * vvv[j];
                accO[3][j] += p3 * vvv[j];
            }
        }
    }

    #pragma unroll
    for (int i = 0; i < 4; i++) {
        int ng = nt * 64 + ty * 4 + i;
        size_t base = ((size_t)bb * NOBJ + ng) * DIM + r * DK;
        #pragma unroll
        for (int j = 0; j < 4; j++) {
            int d = tx * 4 + j;
            out[base + d] = accO[i][j] + vin[base + d];
        }
    }
}

// ============================================================
extern "C" void kernel_launch(void* const* d_in, const int* in_sizes, int n_in,
                              void* d_out, int out_size)
{
    const float* v      = (const float*)d_in[0];
    const float* bmat   = (const float*)d_in[1];
    const float* vmask  = (const float*)d_in[2];
    const float* t      = (const float*)d_in[3];
    const float* tmask  = (const float*)d_in[4];
    const float* WG1_w  = (const float*)d_in[5];
    const float* WG1_b  = (const float*)d_in[6];
    const float* WG2_w  = (const float*)d_in[7];
    const float* WG2_b  = (const float*)d_in[8];
    const float* WK_w   = (const float*)d_in[9];
    const float* WK_b   = (const float*)d_in[10];
    const float* WQ_w   = (const float*)d_in[11];
    const float* WQ_b   = (const float*)d_in[12];
    const float* WV_w   = (const float*)d_in[13];
    const float* WV_b   = (const float*)d_in[14];
    const float* tc_w   = (const float*)d_in[15];
    const float* tc_b   = (const float*)d_in[16];
    const float* tmap_w = (const float*)d_in[17];
    const float* tmap_b = (const float*)d_in[18];
    float* out = (float*)d_out;

    cudaFuncSetAttribute(tmap_kernel, cudaFuncAttributeMaxDynamicSharedMemorySize, 131072);
    cudaFuncSetAttribute(attn_kernel, cudaFuncAttributeMaxDynamicSharedMemorySize, ATTN_SMEM);

    tsum_kernel<<<BSZ, 256>>>(t, tmask, tc_w, tc_b);
    tmap_kernel<<<256, 256, 131072>>>(tmap_w, tmap_b);
    proj_kernel<<<dim3(4, 128, 5), 256>>>(v, bmat, vmask,
                                          WG1_w, WG1_b, WG2_w, WG2_b,
                                          WK_w, WK_b, WQ_w, WQ_b, WV_w, WV_b);
    attn_kernel<<<dim3(4, RREL, BSZ), 256, ATTN_SMEM>>>(vmask, v, out);
}

// round 3
// speedup vs baseline: 1.4727x; 1.4727x over previous
#include <cuda_runtime.h>
#include <math.h>
#include <stdint.h>

#define BSZ   64
#define NOBJ  256
#define TTOK  32
#define DIM   512
#define RREL  8
#define DK    64

#define WSTRIDE (BSZ*RREL*NOBJ*DK)   // 8,388,608 elements per projection

// ---- static device scratch (allocations are forbidden at runtime) ----
__device__ float g_proj[5ull * WSTRIDE];              // 160 MB
__device__ float g_tmap[(size_t)BSZ * NOBJ * NOBJ];   // 16 MB
__device__ float g_tsum[BSZ * DIM];
__device__ float g_wt[5ull * DIM * DIM];              // transposed weights [n][k]

__device__ __forceinline__ float to_tf32(float x) {
    float y;
    asm("cvt.rna.tf32.f32 %0, %1;" : "=f"(y) : "f"(x));
    return y;
}

__device__ __forceinline__ void mma_tf32(
    float& d0, float& d1, float& d2, float& d3,
    uint32_t a0, uint32_t a1, uint32_t a2, uint32_t a3,
    uint32_t b0, uint32_t b1)
{
    asm volatile(
        "mma.sync.aligned.m16n8k8.row.col.f32.tf32.tf32.f32 "
        "{%0,%1,%2,%3}, {%4,%5,%6,%7}, {%8,%9}, {%0,%1,%2,%3};"
        : "+f"(d0), "+f"(d1), "+f"(d2), "+f"(d3)
        : "r"(a0), "r"(a1), "r"(a2), "r"(a3), "r"(b0), "r"(b1));
}

// ============================================================
// Kernel 1: text summary  (one block per batch)
// ============================================================
__global__ __launch_bounds__(256) void tsum_kernel(
    const float* __restrict__ t, const float* __restrict__ tmask,
    const float* __restrict__ tcw, const float* __restrict__ tcb)
{
    int bb = blockIdx.x;
    __shared__ float score[TTOK];
    const float* tb = t + (size_t)bb * TTOK * DIM;

    int warp = threadIdx.x >> 5, lane = threadIdx.x & 31;
    for (int tt = warp * 4; tt < warp * 4 + 4; tt++) {
        float s = 0.f;
        for (int d = lane; d < DIM; d += 32) s += tb[tt * DIM + d] * tcw[d];
        #pragma unroll
        for (int o = 16; o > 0; o >>= 1) s += __shfl_xor_sync(0xffffffffu, s, o);
        if (lane == 0) {
            float m = tmask[bb * TTOK + tt];
            if (m == 0.f) {
                score[tt] = 0.f;
            } else {
                float tc = s * m + tcb[0];
                float sg = 1.f / (1.f + expf(-tc));
                score[tt] = sg * m;
            }
        }
    }
    __syncthreads();

    for (int d = threadIdx.x; d < DIM; d += 256) {
        float acc = 0.f;
        #pragma unroll
        for (int tt = 0; tt < TTOK; tt++) acc += tb[tt * DIM + d] * score[tt];
        g_tsum[bb * DIM + d] = acc;
    }
}

// ============================================================
// Kernel 2: tmap = relu(t_summary @ tmap_w + tmap_b)
// ============================================================
__global__ __launch_bounds__(256) void tmap_kernel(
    const float* __restrict__ W, const float* __restrict__ bias)
{
    extern __shared__ float sT[];  // 64 x 512 fp32 = 128 KB
    for (int i = threadIdx.x; i < BSZ * DIM / 4; i += 256)
        ((float4*)sT)[i] = ((const float4*)g_tsum)[i];
    __syncthreads();

    int col = blockIdx.x * 256 + threadIdx.x;
    float acc[BSZ];
    #pragma unroll
    for (int r = 0; r < BSZ; r++) acc[r] = 0.f;

    for (int k = 0; k < DIM; k += 4) {
        float w0 = W[(size_t)(k + 0) * 65536 + col];
        float w1 = W[(size_t)(k + 1) * 65536 + col];
        float w2 = W[(size_t)(k + 2) * 65536 + col];
        float w3 = W[(size_t)(k + 3) * 65536 + col];
        #pragma unroll
        for (int r = 0; r < BSZ; r++) {
            float4 tv = *(const float4*)&sT[r * DIM + k];
            acc[r] += tv.x * w0 + tv.y * w1 + tv.z * w2 + tv.w * w3;
        }
    }
    float bv = bias[col];
    #pragma unroll
    for (int r = 0; r < BSZ; r++)
        g_tmap[(size_t)r * 65536 + col] = fmaxf(acc[r] + bv, 0.f);
}

// ============================================================
// Kernel 2b: transpose the 5 projection weights  W[k][n] -> Wt[n][k]
// ============================================================
__global__ __launch_bounds__(256) void wtrans_kernel(
    const float* __restrict__ W0, const float* __restrict__ W1,
    const float* __restrict__ W2, const float* __restrict__ W3,
    const float* __restrict__ W4)
{
    __shared__ float tile[32][33];
    int w = blockIdx.z;
    const float* W;
    switch (w) {
        case 0: W = W0; break; case 1: W = W1; break; case 2: W = W2; break;
        case 3: W = W3; break; default: W = W4; break;
    }
    float* Wt = g_wt + (size_t)w * DIM * DIM;

    int tx = threadIdx.x & 31, ty = threadIdx.x >> 5;   // 32x8
    int K0 = blockIdx.y * 32, N0 = blockIdx.x * 32;
    #pragma unroll
    for (int i = 0; i < 32; i += 8)
        tile[ty + i][tx] = W[(size_t)(K0 + ty + i) * DIM + N0 + tx];
    __syncthreads();
    #pragma unroll
    for (int i = 0; i < 32; i += 8)
        Wt[(size_t)(N0 + ty + i) * DIM + K0 + tx] = tile[tx][ty + i];
}

// ============================================================
// Kernel 3: 5 projections via mma.sync tf32
// block tile 128(M) x 256(N), BK=32, 8 warps (2M x 4N), warp tile 64x64
//
// smem layout (fragment-permuted, dynamic):
//   sA: [ka(4)][ma(8)][lane(32)][reg(4)]  = 4096 floats (16 KB)
//   sB: [ka(4)][pair(16)][lane(32)][reg(4)] = 8192 floats (32 KB)
//   sBias: 256 floats (1 KB)
// ============================================================
#define PJA_OFF  0
#define PJB_OFF  4096
#define PJBIAS_OFF 12288
#define PJ_SMEM ((12288 + 256) * 4)

__global__ __launch_bounds__(256, 1) void proj_mma_kernel(
    const float* __restrict__ vin, const float* __restrict__ bmat,
    const float* __restrict__ vmask,
    const float* __restrict__ B0, const float* __restrict__ B1,
    const float* __restrict__ B2, const float* __restrict__ B3,
    const float* __restrict__ B4)
{
    extern __shared__ float smem[];
    float* sA = smem + PJA_OFF;
    float* sB = smem + PJB_OFF;
    float* sBias = smem + PJBIAS_OFF;

    int t = threadIdx.x;
    int wid = t >> 5, lane = t & 31;
    int mw = wid >> 2, nw = wid & 3;
    int g = lane >> 2, tg = lane & 3;

    int w  = blockIdx.z;
    int m0 = blockIdx.y * 128;
    int n0 = blockIdx.x * 256;

    const float* X = (w < 2) ? bmat : vin;
    const float* Bv;
    switch (w) {
        case 0: Bv = B0; break; case 1: Bv = B1; break; case 2: Bv = B2; break;
        case 3: Bv = B3; break; default: Bv = B4; break;
    }
    const float* Wt = g_wt + (size_t)w * DIM * DIM;

    sBias[t] = Bv[n0 + t];

    const float* Asrc = X  + (size_t)m0 * DIM;
    const float* Bsrc = Wt + (size_t)n0 * DIM;

    float acc[4][8][4];
    #pragma unroll
    for (int i = 0; i < 4; i++)
        #pragma unroll
        for (int j = 0; j < 8; j++)
            #pragma unroll
            for (int q = 0; q < 4; q++) acc[i][j][q] = 0.f;

    for (int c = 0; c < 16; c++) {
        int k0 = c * 32;
        __syncthreads();

        // ---- stage A: 128x32, fragment-permuted ----
        #pragma unroll
        for (int i = 0; i < 4; i++) {
            int idx = t + i * 256;          // 0..1023
            int row = idx >> 3;
            int j   = idx & 7;
            float4 va = *(const float4*)(Asrc + (size_t)row * DIM + k0 + j * 4);
            int ka  = j >> 1;
            int chi = j & 1;
            int ma  = row >> 4;
            int rr  = row & 15;
            int rhi = rr >> 3;
            int rl  = rr & 7;
            int reg = rhi + 2 * chi;
            int base = ((ka * 8 + ma) * 32 + rl * 4) * 4 + reg;
            sA[base +  0] = to_tf32(va.x);
            sA[base +  4] = to_tf32(va.y);
            sA[base +  8] = to_tf32(va.z);
            sA[base + 12] = to_tf32(va.w);
        }
        // ---- stage B: 256x32, fragment-permuted (pairs of N-atoms) ----
        #pragma unroll
        for (int i = 0; i < 8; i++) {
            int idx = t + i * 256;          // 0..2047
            int n   = idx >> 3;
            int j   = idx & 7;
            float4 vb = *(const float4*)(Bsrc + (size_t)n * DIM + k0 + j * 4);
            int ka  = j >> 1;
            int chi = j & 1;
            int na  = n >> 3;
            int p   = na >> 1;
            int sub = na & 1;
            int nl  = n & 7;
            int reg = sub * 2 + chi;
            int base = ((ka * 16 + p) * 32 + nl * 4) * 4 + reg;
            sB[base +  0] = to_tf32(vb.x);
            sB[base +  4] = to_tf32(vb.y);
            sB[base +  8] = to_tf32(vb.z);
            sB[base + 12] = to_tf32(vb.w);
        }
        __syncthreads();

        // ---- compute 4 k-atoms ----
        #pragma unroll
        for (int ka = 0; ka < 4; ka++) {
            uint4 af[4];
            uint4 bf[4];
            #pragma unroll
            for (int ml = 0; ml < 4; ml++)
                af[ml] = *(const uint4*)&sA[((ka * 8 + mw * 4 + ml) * 32 + lane) * 4];
            #pragma unroll
            for (int pl = 0; pl < 4; pl++)
                bf[pl] = *(const uint4*)&sB[((ka * 16 + nw * 4 + pl) * 32 + lane) * 4];
            #pragma unroll
            for (int ml = 0; ml < 4; ml++) {
                #pragma unroll
                for (int pl = 0; pl < 4; pl++) {
                    mma_tf32(acc[ml][pl*2][0], acc[ml][pl*2][1],
                             acc[ml][pl*2][2], acc[ml][pl*2][3],
                             af[ml].x, af[ml].y, af[ml].z, af[ml].w,
                             bf[pl].x, bf[pl].y);
                    mma_tf32(acc[ml][pl*2+1][0], acc[ml][pl*2+1][1],
                             acc[ml][pl*2+1][2], acc[ml][pl*2+1][3],
                             af[ml].x, af[ml].y, af[ml].z, af[ml].w,
                             bf[pl].z, bf[pl].w);
                }
            }
        }
    }
    __syncthreads();

    // ---- epilogue: bias + mask, scatter to (b,r,n,dk) ----
    float* Pout = g_proj + (size_t)w * WSTRIDE;
    #pragma unroll
    for (int ml = 0; ml < 4; ml++) {
        int gm0 = m0 + mw * 64 + ml * 16 + g;       // rows gm0, gm0+8
        int gm1 = gm0 + 8;
        float msk0 = (w < 2) ? vmask[gm0] : 1.0f;
        float msk1 = (w < 2) ? vmask[gm1] : 1.0f;
        int bbi0 = gm0 >> 8, nn0 = gm0 & 255;
        int bbi1 = gm1 >> 8, nn1 = gm1 & 255;
        #pragma unroll
        for (int nl = 0; nl < 8; nl++) {
            int cl = (nw * 8 + nl) * 8 + tg * 2;    // col within block (0..255)
            int cg = n0 + cl;
            int rrel = cg >> 6, d = cg & 63;
            float b0 = sBias[cl], b1 = sBias[cl + 1];
            float2 v0, v1;
            v0.x = (acc[ml][nl][0] + b0) * msk0;
            v0.y = (acc[ml][nl][1] + b1) * msk0;
            v1.x = (acc[ml][nl][2] + b0) * msk1;
            v1.y = (acc[ml][nl][3] + b1) * msk1;
            *(float2*)&Pout[((size_t)(bbi0 * RREL + rrel) * NOBJ + nn0) * DK + d] = v0;
            *(float2*)&Pout[((size_t)(bbi1 * RREL + rrel) * NOBJ + nn1) * DK + d] = v1;
        }
    }
}

// ============================================================
// Kernel 4: fused attention (unchanged)
// ============================================================
#define PADT 68
#define SPAD 260
#define ATTN_SMEM ((4 * 64 * PADT + 64 * SPAD) * 4)   // 136192 bytes

__device__ __forceinline__ void load_tile_T(float* dst, const float* __restrict__ src)
{
    int t = threadIdx.x;
    #pragma unroll
    for (int p = 0; p < 4; p++) {
        int idx = (t + p * 256) * 4;
        int row = idx >> 6, k = idx & 63;
        float4 va = *(const float4*)(src + row * 64 + k);
        dst[(k + 0) * PADT + row] = va.x;
        dst[(k + 1) * PADT + row] = va.y;
        dst[(k + 2) * PADT + row] = va.z;
        dst[(k + 3) * PADT + row] = va.w;
    }
}

__device__ __forceinline__ void load_tile_N(float* dst, const float* __restrict__ src)
{
    int t = threadIdx.x;
    #pragma unroll
    for (int p = 0; p < 4; p++) {
        int idx = (t + p * 256) * 4;
        int row = idx >> 6, k = idx & 63;
        *(float4*)(dst + row * PADT + k) = *(const float4*)(src + row * 64 + k);
    }
}

__global__ __launch_bounds__(256) void attn_kernel(
    const float* __restrict__ vmask, const float* __restrict__ vin,
    float* __restrict__ out)
{
    extern __shared__ float sm[];
    float* sG1 = sm;
    float* sK  = sm + 1 * 64 * PADT;
    float* sX  = sm + 2 * 64 * PADT;
    float* sY  = sm + 3 * 64 * PADT;
    float* sS  = sm + 4 * 64 * PADT;

    int nt = blockIdx.x, r = blockIdx.y, bb = blockIdx.z;
    int t  = threadIdx.x;
    int tx = t & 15, ty = t >> 4;

    size_t pbase = (size_t)(bb * RREL + r) * NOBJ * DK;
    const float* G1 = g_proj + 0ull * WSTRIDE + pbase;
    const float* G2 = g_proj + 1ull * WSTRIDE + pbase;
    const float* Kp = g_proj + 2ull * WSTRIDE + pbase;
    const float* Qp = g_proj + 3ull * WSTRIDE + pbase;
    const float* Vp = g_proj + 4ull * WSTRIDE + pbase;

    load_tile_T(sG1, G1 + nt * 64 * DK);
    load_tile_T(sK,  Kp + nt * 64 * DK);

    const float* tmrow = g_tmap + ((size_t)bb * NOBJ * NOBJ);

    for (int mt = 0; mt < 4; mt++) {
        load_tile_T(sX, G2 + mt * 64 * DK);
        load_tile_T(sY, Qp + mt * 64 * DK);
        __syncthreads();

        float accG[4][4], accS[4][4];
        #pragma unroll
        for (int i = 0; i < 4; i++)
            #pragma unroll
            for (int j = 0; j < 4; j++) { accG[i][j] = 0.f; accS[i][j] = 0.f; }

        #pragma unroll 8
        for (int k = 0; k < 64; k++) {
            float4 a1 = *(const float4*)(sG1 + k * PADT + ty * 4);
            float4 b1 = *(const float4*)(sX  + k * PADT + tx * 4);
            float4 a2 = *(const float4*)(sK  + k * PADT + ty * 4);
            float4 b2 = *(const float4*)(sY  + k * PADT + tx * 4);
            float a1v[4] = {a1.x, a1.y, a1.z, a1.w};
            float b1v[4] = {b1.x, b1.y, b1.z, b1.w};
            float a2v[4] = {a2.x, a2.y, a2.z, a2.w};
            float b2v[4] = {b2.x, b2.y, b2.z, b2.w};
            #pragma unroll
            for (int i = 0; i < 4; i++)
                #pragma unroll
                for (int j = 0; j < 4; j++) {
                    accG[i][j] += a1v[i] * b1v[j];
                    accS[i][j] += a2v[i] * b2v[j];
                }
        }

        float cm[4];
        #pragma unroll
        for (int j = 0; j < 4; j++)
            cm[j] = vmask[bb * NOBJ + mt * 64 + tx * 4 + j];

        #pragma unroll
        for (int i = 0; i < 4; i++) {
            int ng = nt * 64 + ty * 4 + i;
            #pragma unroll
            for (int j = 0; j < 4; j++) {
                int mg = mt * 64 + tx * 4 + j;
                float tm = tmrow[ng * NOBJ + mg];
                float wg = fmaxf(accG[i][j], 0.f) + tm;
                float s  = logf(fmaxf(wg, 1e-6f)) + accS[i][j] * 0.125f;
                if (cm[j] == 0.f) s = -INFINITY;
                sS[(ty * 4 + i) * SPAD + mg] = s;
            }
        }
        __syncthreads();
    }

    {
        int rrow = t >> 2;
        int lanei = t & 3;
        float* rowp = sS + rrow * SPAD;
        float mx = -INFINITY;
        for (int m = lanei; m < 256; m += 4) mx = fmaxf(mx, rowp[m]);
        mx = fmaxf(mx, __shfl_xor_sync(0xffffffffu, mx, 1));
        mx = fmaxf(mx, __shfl_xor_sync(0xffffffffu, mx, 2));
        float sum = 0.f;
        for (int m = lanei; m < 256; m += 4) {
            float p = expf(rowp[m] - mx);
            rowp[m] = p;
            sum += p;
        }
        sum += __shfl_xor_sync(0xffffffffu, sum, 1);
        sum += __shfl_xor_sync(0xffffffffu, sum, 2);
        float inv = 1.f / sum;
        for (int m = lanei; m < 256; m += 4) rowp[m] *= inv;
    }
    __syncthreads();

    float accO[4][4];
    #pragma unroll
    for (int i = 0; i < 4; i++)
        #pragma unroll
        for (int j = 0; j < 4; j++) accO[i][j] = 0.f;

    for (int mt = 0; mt < 4; mt++) {
        __syncthreads();
        load_tile_N(sX, Vp + mt * 64 * DK);
        __syncthreads();
        #pragma unroll 4
        for (int m = 0; m < 64; m++) {
            float p0 = sS[(ty * 4 + 0) * SPAD + mt * 64 + m];
            float p1 = sS[(ty * 4 + 1) * SPAD + mt * 64 + m];
            float p2 = sS[(ty * 4 + 2) * SPAD + mt * 64 + m];
            float p3 = sS[(ty * 4 + 3) * SPAD + mt * 64 + m];
            float4 vv = *(const float4*)(sX + m * PADT + tx * 4);
            float vvv[4] = {vv.x, vv.y, vv.z, vv.w};
            #pragma unroll
            for (int j = 0; j < 4; j++) {
                accO[0][j] += p0 * vvv[j];
                accO[1][j] += p1 * vvv[j];
                accO[2][j] += p2 * vvv[j];
                accO[3][j] += p3 * vvv[j];
            }
        }
    }

    #pragma unroll
    for (int i = 0; i < 4; i++) {
        int ng = nt * 64 + ty * 4 + i;
        size_t base = ((size_t)bb * NOBJ + ng) * DIM + r * DK;
        #pragma unroll
        for (int j = 0; j < 4; j++) {
            int d = tx * 4 + j;
            out[base + d] = accO[i][j] + vin[base + d];
        }
    }
}

// ============================================================
extern "C" void kernel_launch(void* const* d_in, const int* in_sizes, int n_in,
                              void* d_out, int out_size)
{
    const float* v      = (const float*)d_in[0];
    const float* bmat   = (const float*)d_in[1];
    const float* vmask  = (const float*)d_in[2];
    const float* t      = (const float*)d_in[3];
    const float* tmask  = (const float*)d_in[4];
    const float* WG1_w  = (const float*)d_in[5];
    const float* WG1_b  = (const float*)d_in[6];
    const float* WG2_w  = (const float*)d_in[7];
    const float* WG2_b  = (const float*)d_in[8];
    const float* WK_w   = (const float*)d_in[9];
    const float* WK_b   = (const float*)d_in[10];
    const float* WQ_w   = (const float*)d_in[11];
    const float* WQ_b   = (const float*)d_in[12];
    const float* WV_w   = (const float*)d_in[13];
    const float* WV_b   = (const float*)d_in[14];
    const float* tc_w   = (const float*)d_in[15];
    const float* tc_b   = (const float*)d_in[16];
    const float* tmap_w = (const float*)d_in[17];
    const float* tmap_b = (const float*)d_in[18];
    float* out = (float*)d_out;

    cudaFuncSetAttribute(tmap_kernel, cudaFuncAttributeMaxDynamicSharedMemorySize, 131072);
    cudaFuncSetAttribute(attn_kernel, cudaFuncAttributeMaxDynamicSharedMemorySize, ATTN_SMEM);
    cudaFuncSetAttribute(proj_mma_kernel, cudaFuncAttributeMaxDynamicSharedMemorySize, PJ_SMEM);

    tsum_kernel<<<BSZ, 256>>>(t, tmask, tc_w, tc_b);
    wtrans_kernel<<<dim3(16, 16, 5), 256>>>(WG1_w, WG2_w, WK_w, WQ_w, WV_w);
    tmap_kernel<<<256, 256, 131072>>>(tmap_w, tmap_b);
    proj_mma_kernel<<<dim3(2, 128, 5), 256, PJ_SMEM>>>(
        v, bmat, vmask, WG1_b, WG2_b, WK_b, WQ_b, WV_b);
    attn_kernel<<<dim3(4, RREL, BSZ), 256, ATTN_SMEM>>>(vmask, v, out);
}

// round 4
// speedup vs baseline: 1.5952x; 1.0832x over previous
#include <cuda_runtime.h>
#include <math.h>
#include <stdint.h>

#define BSZ   64
#define NOBJ  256
#define TTOK  32
#define DIM   512
#define RREL  8
#define DK    64

#define WSTRIDE (BSZ*RREL*NOBJ*DK)   // 8,388,608 elements per projection

// ---- static device scratch (allocations are forbidden at runtime) ----
__device__ float g_proj[5ull * WSTRIDE];              // 160 MB
__device__ float g_tmap[(size_t)BSZ * NOBJ * NOBJ];   // 16 MB
__device__ float g_tsum[BSZ * DIM];
__device__ float g_wt[5ull * DIM * DIM];              // transposed weights [n][k]

__device__ __forceinline__ float to_tf32(float x) {
    float y;
    asm("cvt.rna.tf32.f32 %0, %1;" : "=f"(y) : "f"(x));
    return y;
}

__device__ __forceinline__ void mma_tf32(
    float& d0, float& d1, float& d2, float& d3,
    uint32_t a0, uint32_t a1, uint32_t a2, uint32_t a3,
    uint32_t b0, uint32_t b1)
{
    asm volatile(
        "mma.sync.aligned.m16n8k8.row.col.f32.tf32.tf32.f32 "
        "{%0,%1,%2,%3}, {%4,%5,%6,%7}, {%8,%9}, {%0,%1,%2,%3};"
        : "+f"(d0), "+f"(d1), "+f"(d2), "+f"(d3)
        : "r"(a0), "r"(a1), "r"(a2), "r"(a3), "r"(b0), "r"(b1));
}

// ============================================================
// Kernel 1: text summary  (one block per batch)
// ============================================================
__global__ __launch_bounds__(256) void tsum_kernel(
    const float* __restrict__ t, const float* __restrict__ tmask,
    const float* __restrict__ tcw, const float* __restrict__ tcb)
{
    int bb = blockIdx.x;
    __shared__ float score[TTOK];
    const float* tb = t + (size_t)bb * TTOK * DIM;

    int warp = threadIdx.x >> 5, lane = threadIdx.x & 31;
    for (int tt = warp * 4; tt < warp * 4 + 4; tt++) {
        float s = 0.f;
        for (int d = lane; d < DIM; d += 32) s += tb[tt * DIM + d] * tcw[d];
        #pragma unroll
        for (int o = 16; o > 0; o >>= 1) s += __shfl_xor_sync(0xffffffffu, s, o);
        if (lane == 0) {
            float m = tmask[bb * TTOK + tt];
            if (m == 0.f) {
                score[tt] = 0.f;
            } else {
                float tc = s * m + tcb[0];
                float sg = 1.f / (1.f + expf(-tc));
                score[tt] = sg * m;
            }
        }
    }
    __syncthreads();

    for (int d = threadIdx.x; d < DIM; d += 256) {
        float acc = 0.f;
        #pragma unroll
        for (int tt = 0; tt < TTOK; tt++) acc += tb[tt * DIM + d] * score[tt];
        g_tsum[bb * DIM + d] = acc;
    }
}

// ============================================================
// Kernel 2: tmap = relu(t_summary @ tmap_w + tmap_b)
// ============================================================
__global__ __launch_bounds__(256) void tmap_kernel(
    const float* __restrict__ W, const float* __restrict__ bias)
{
    extern __shared__ float sT[];  // 64 x 512 fp32 = 128 KB
    for (int i = threadIdx.x; i < BSZ * DIM / 4; i += 256)
        ((float4*)sT)[i] = ((const float4*)g_tsum)[i];
    __syncthreads();

    int col = blockIdx.x * 256 + threadIdx.x;
    float acc[BSZ];
    #pragma unroll
    for (int r = 0; r < BSZ; r++) acc[r] = 0.f;

    for (int k = 0; k < DIM; k += 4) {
        float w0 = W[(size_t)(k + 0) * 65536 + col];
        float w1 = W[(size_t)(k + 1) * 65536 + col];
        float w2 = W[(size_t)(k + 2) * 65536 + col];
        float w3 = W[(size_t)(k + 3) * 65536 + col];
        #pragma unroll
        for (int r = 0; r < BSZ; r++) {
            float4 tv = *(const float4*)&sT[r * DIM + k];
            acc[r] += tv.x * w0 + tv.y * w1 + tv.z * w2 + tv.w * w3;
        }
    }
    float bv = bias[col];
    #pragma unroll
    for (int r = 0; r < BSZ; r++)
        g_tmap[(size_t)r * 65536 + col] = fmaxf(acc[r] + bv, 0.f);
}

// ============================================================
// Kernel 2b: transpose the 5 projection weights  W[k][n] -> Wt[n][k]
// ============================================================
__global__ __launch_bounds__(256) void wtrans_kernel(
    const float* __restrict__ W0, const float* __restrict__ W1,
    const float* __restrict__ W2, const float* __restrict__ W3,
    const float* __restrict__ W4)
{
    __shared__ float tile[32][33];
    int w = blockIdx.z;
    const float* W;
    switch (w) {
        case 0: W = W0; break; case 1: W = W1; break; case 2: W = W2; break;
        case 3: W = W3; break; default: W = W4; break;
    }
    float* Wt = g_wt + (size_t)w * DIM * DIM;

    int tx = threadIdx.x & 31, ty = threadIdx.x >> 5;   // 32x8
    int K0 = blockIdx.y * 32, N0 = blockIdx.x * 32;
    #pragma unroll
    for (int i = 0; i < 32; i += 8)
        tile[ty + i][tx] = W[(size_t)(K0 + ty + i) * DIM + N0 + tx];
    __syncthreads();
    #pragma unroll
    for (int i = 0; i < 32; i += 8)
        Wt[(size_t)(N0 + ty + i) * DIM + K0 + tx] = tile[tx][ty + i];
}

// ============================================================
// Kernel 3: 5 projections via mma.sync tf32, software-pipelined
// block tile 128(M) x 256(N), BK=32, 8 warps (2M x 4N), warp tile 64x64
// double-buffered smem + register prefetch
// ============================================================
#define PJ_A0   0
#define PJ_A1   4096
#define PJ_B0   8192
#define PJ_B1   16384
#define PJBIAS_OFF 24576
#define PJ_SMEM ((24576 + 256) * 4)

__global__ __launch_bounds__(256, 1) void proj_mma_kernel(
    const float* __restrict__ vin, const float* __restrict__ bmat,
    const float* __restrict__ vmask,
    const float* __restrict__ B0, const float* __restrict__ B1,
    const float* __restrict__ B2, const float* __restrict__ B3,
    const float* __restrict__ B4)
{
    extern __shared__ float smem[];
    float* sBias = smem + PJBIAS_OFF;

    int t = threadIdx.x;
    int wid = t >> 5, lane = t & 31;
    int mw = wid >> 2, nw = wid & 3;
    int g = lane >> 2, tg = lane & 3;

    int w  = blockIdx.z;
    int m0 = blockIdx.y * 128;
    int n0 = blockIdx.x * 256;

    const float* X = (w < 2) ? bmat : vin;
    const float* Bv;
    switch (w) {
        case 0: Bv = B0; break; case 1: Bv = B1; break; case 2: Bv = B2; break;
        case 3: Bv = B3; break; default: Bv = B4; break;
    }
    const float* Wt = g_wt + (size_t)w * DIM * DIM;

    sBias[t] = Bv[n0 + t];

    const float* Asrc = X  + (size_t)m0 * DIM;
    const float* Bsrc = Wt + (size_t)n0 * DIM;

    // per-thread permuted smem store offsets (chunk-invariant)
    int aoffs[4], boffs[8];
    const float* aptr[4];
    const float* bptr[8];
    #pragma unroll
    for (int i = 0; i < 4; i++) {
        int idx = t + i * 256;
        int row = idx >> 3, j = idx & 7;
        int ka = j >> 1, chi = j & 1;
        int ma = row >> 4, rr = row & 15, rhi = rr >> 3, rl = rr & 7;
        aoffs[i] = ((ka * 8 + ma) * 32 + rl * 4) * 4 + (rhi + 2 * chi);
        aptr[i]  = Asrc + (size_t)row * DIM + j * 4;
    }
    #pragma unroll
    for (int i = 0; i < 8; i++) {
        int idx = t + i * 256;
        int n = idx >> 3, j = idx & 7;
        int ka = j >> 1, chi = j & 1;
        int na = n >> 3, p = na >> 1, sub = na & 1, nl = n & 7;
        boffs[i] = ((ka * 16 + p) * 32 + nl * 4) * 4 + (sub * 2 + chi);
        bptr[i]  = Bsrc + (size_t)n * DIM + j * 4;
    }

    float acc[4][8][4];
    #pragma unroll
    for (int i = 0; i < 4; i++)
        #pragma unroll
        for (int j = 0; j < 8; j++)
            #pragma unroll
            for (int q = 0; q < 4; q++) acc[i][j][q] = 0.f;

    float4 pa[4], pb[8];

    // ---- prologue: load + store chunk 0 ----
    #pragma unroll
    for (int i = 0; i < 4; i++) pa[i] = *(const float4*)(aptr[i]);
    #pragma unroll
    for (int i = 0; i < 8; i++) pb[i] = *(const float4*)(bptr[i]);
    #pragma unroll
    for (int i = 0; i < 4; i++) {
        float* d = smem + PJ_A0 + aoffs[i];
        d[0] = to_tf32(pa[i].x); d[4] = to_tf32(pa[i].y);
        d[8] = to_tf32(pa[i].z); d[12] = to_tf32(pa[i].w);
    }
    #pragma unroll
    for (int i = 0; i < 8; i++) {
        float* d = smem + PJ_B0 + boffs[i];
        d[0] = to_tf32(pb[i].x); d[4] = to_tf32(pb[i].y);
        d[8] = to_tf32(pb[i].z); d[12] = to_tf32(pb[i].w);
    }
    __syncthreads();

    #pragma unroll 2
    for (int c = 0; c < 16; c++) {
        const float* sA = smem + ((c & 1) ? PJ_A1 : PJ_A0);
        const float* sB = smem + ((c & 1) ? PJ_B1 : PJ_B0);

        // prefetch chunk c+1 into registers (hidden under mma work)
        if (c < 15) {
            int ko = (c + 1) * 32;
            #pragma unroll
            for (int i = 0; i < 4; i++) pa[i] = *(const float4*)(aptr[i] + ko);
            #pragma unroll
            for (int i = 0; i < 8; i++) pb[i] = *(const float4*)(bptr[i] + ko);
        }

        // ---- compute 4 k-atoms from current buffers ----
        #pragma unroll
        for (int ka = 0; ka < 4; ka++) {
            uint4 af[4];
            uint4 bf[4];
            #pragma unroll
            for (int ml = 0; ml < 4; ml++)
                af[ml] = *(const uint4*)&sA[((ka * 8 + mw * 4 + ml) * 32 + lane) * 4];
            #pragma unroll
            for (int pl = 0; pl < 4; pl++)
                bf[pl] = *(const uint4*)&sB[((ka * 16 + nw * 4 + pl) * 32 + lane) * 4];
            #pragma unroll
            for (int ml = 0; ml < 4; ml++) {
                #pragma unroll
                for (int pl = 0; pl < 4; pl++) {
                    mma_tf32(acc[ml][pl*2][0], acc[ml][pl*2][1],
                             acc[ml][pl*2][2], acc[ml][pl*2][3],
                             af[ml].x, af[ml].y, af[ml].z, af[ml].w,
                             bf[pl].x, bf[pl].y);
                    mma_tf32(acc[ml][pl*2+1][0], acc[ml][pl*2+1][1],
                             acc[ml][pl*2+1][2], acc[ml][pl*2+1][3],
                             af[ml].x, af[ml].y, af[ml].z, af[ml].w,
                             bf[pl].z, bf[pl].w);
                }
            }
        }

        // store chunk c+1 into the other buffers
        if (c < 15) {
            float* dA = smem + ((c & 1) ? PJ_A0 : PJ_A1);
            float* dB = smem + ((c & 1) ? PJ_B0 : PJ_B1);
            #pragma unroll
            for (int i = 0; i < 4; i++) {
                float* d = dA + aoffs[i];
                d[0] = to_tf32(pa[i].x); d[4] = to_tf32(pa[i].y);
                d[8] = to_tf32(pa[i].z); d[12] = to_tf32(pa[i].w);
            }
            #pragma unroll
            for (int i = 0; i < 8; i++) {
                float* d = dB + boffs[i];
                d[0] = to_tf32(pb[i].x); d[4] = to_tf32(pb[i].y);
                d[8] = to_tf32(pb[i].z); d[12] = to_tf32(pb[i].w);
            }
        }
        __syncthreads();
    }

    // ---- epilogue: bias + mask, scatter to (b,r,n,dk) ----
    float* Pout = g_proj + (size_t)w * WSTRIDE;
    #pragma unroll
    for (int ml = 0; ml < 4; ml++) {
        int gm0 = m0 + mw * 64 + ml * 16 + g;       // rows gm0, gm0+8
        int gm1 = gm0 + 8;
        float msk0 = (w < 2) ? vmask[gm0] : 1.0f;
        float msk1 = (w < 2) ? vmask[gm1] : 1.0f;
        int bbi0 = gm0 >> 8, nn0 = gm0 & 255;
        int bbi1 = gm1 >> 8, nn1 = gm1 & 255;
        #pragma unroll
        for (int nl = 0; nl < 8; nl++) {
            int cl = (nw * 8 + nl) * 8 + tg * 2;    // col within block (0..255)
            int cg = n0 + cl;
            int rrel = cg >> 6, d = cg & 63;
            float b0 = sBias[cl], b1 = sBias[cl + 1];
            float2 v0, v1;
            v0.x = (acc[ml][nl][0] + b0) * msk0;
            v0.y = (acc[ml][nl][1] + b1) * msk0;
            v1.x = (acc[ml][nl][2] + b0) * msk1;
            v1.y = (acc[ml][nl][3] + b1) * msk1;
            *(float2*)&Pout[((size_t)(bbi0 * RREL + rrel) * NOBJ + nn0) * DK + d] = v0;
            *(float2*)&Pout[((size_t)(bbi1 * RREL + rrel) * NOBJ + nn1) * DK + d] = v1;
        }
    }
}

// ============================================================
// Kernel 4: fused attention — log-free softmax
// softmax(log(wgc)+sd) == wgc*exp(sd) / sum(wgc*exp(sd))
// ============================================================
#define PADT 68
#define SPAD 260
#define SINV_OFF (4 * 64 * PADT + 64 * SPAD)
#define ATTN_SMEM ((SINV_OFF + 64) * 4)

__device__ __forceinline__ void load_tile_T(float* dst, const float* __restrict__ src)
{
    int t = threadIdx.x;
    #pragma unroll
    for (int p = 0; p < 4; p++) {
        int idx = (t + p * 256) * 4;
        int row = idx >> 6, k = idx & 63;
        float4 va = *(const float4*)(src + row * 64 + k);
        dst[(k + 0) * PADT + row] = va.x;
        dst[(k + 1) * PADT + row] = va.y;
        dst[(k + 2) * PADT + row] = va.z;
        dst[(k + 3) * PADT + row] = va.w;
    }
}

__device__ __forceinline__ void load_tile_N(float* dst, const float* __restrict__ src)
{
    int t = threadIdx.x;
    #pragma unroll
    for (int p = 0; p < 4; p++) {
        int idx = (t + p * 256) * 4;
        int row = idx >> 6, k = idx & 63;
        *(float4*)(dst + row * PADT + k) = *(const float4*)(src + row * 64 + k);
    }
}

__global__ __launch_bounds__(256) void attn_kernel(
    const float* __restrict__ vmask, const float* __restrict__ vin,
    float* __restrict__ out)
{
    extern __shared__ float sm[];
    float* sG1 = sm;
    float* sK  = sm + 1 * 64 * PADT;
    float* sX  = sm + 2 * 64 * PADT;
    float* sY  = sm + 3 * 64 * PADT;
    float* sS  = sm + 4 * 64 * PADT;
    float* sInv = sm + SINV_OFF;

    int nt = blockIdx.x, r = blockIdx.y, bb = blockIdx.z;
    int t  = threadIdx.x;
    int tx = t & 15, ty = t >> 4;

    size_t pbase = (size_t)(bb * RREL + r) * NOBJ * DK;
    const float* G1 = g_proj + 0ull * WSTRIDE + pbase;
    const float* G2 = g_proj + 1ull * WSTRIDE + pbase;
    const float* Kp = g_proj + 2ull * WSTRIDE + pbase;
    const float* Qp = g_proj + 3ull * WSTRIDE + pbase;
    const float* Vp = g_proj + 4ull * WSTRIDE + pbase;

    load_tile_T(sG1, G1 + nt * 64 * DK);
    load_tile_T(sK,  Kp + nt * 64 * DK);

    const float* tmrow = g_tmap + ((size_t)bb * NOBJ * NOBJ);

    for (int mt = 0; mt < 4; mt++) {
        load_tile_T(sX, G2 + mt * 64 * DK);
        load_tile_T(sY, Qp + mt * 64 * DK);
        __syncthreads();

        float accG[4][4], accS[4][4];
        #pragma unroll
        for (int i = 0; i < 4; i++)
            #pragma unroll
            for (int j = 0; j < 4; j++) { accG[i][j] = 0.f; accS[i][j] = 0.f; }

        #pragma unroll 8
        for (int k = 0; k < 64; k++) {
            float4 a1 = *(const float4*)(sG1 + k * PADT + ty * 4);
            float4 b1 = *(const float4*)(sX  + k * PADT + tx * 4);
            float4 a2 = *(const float4*)(sK  + k * PADT + ty * 4);
            float4 b2 = *(const float4*)(sY  + k * PADT + tx * 4);
            float a1v[4] = {a1.x, a1.y, a1.z, a1.w};
            float b1v[4] = {b1.x, b1.y, b1.z, b1.w};
            float a2v[4] = {a2.x, a2.y, a2.z, a2.w};
            float b2v[4] = {b2.x, b2.y, b2.z, b2.w};
            #pragma unroll
            for (int i = 0; i < 4; i++)
                #pragma unroll
                for (int j = 0; j < 4; j++) {
                    accG[i][j] += a1v[i] * b1v[j];
                    accS[i][j] += a2v[i] * b2v[j];
                }
        }

        float cm[4];
        #pragma unroll
        for (int j = 0; j < 4; j++)
            cm[j] = vmask[bb * NOBJ + mt * 64 + tx * 4 + j];

        #pragma unroll
        for (int i = 0; i < 4; i++) {
            int ng = nt * 64 + ty * 4 + i;
            #pragma unroll
            for (int j = 0; j < 4; j++) {
                int mg = mt * 64 + tx * 4 + j;
                float tm = tmrow[ng * NOBJ + mg];
                float wgc = fmaxf(fmaxf(accG[i][j], 0.f) + tm, 1e-6f);
                float sd  = fminf(accS[i][j] * 0.125f, 60.f);
                float tv  = wgc * __expf(sd);
                if (cm[j] == 0.f) tv = 0.f;
                sS[(ty * 4 + i) * SPAD + mg] = tv;
            }
        }
        __syncthreads();
    }

    // ---- row sums -> 1/sum (no max pass, no log, no exp here) ----
    {
        int rrow = t >> 2;
        int lanei = t & 3;
        const float* rowp = sS + rrow * SPAD;
        float sum = 0.f;
        for (int m = lanei; m < 256; m += 4) sum += rowp[m];
        sum += __shfl_xor_sync(0xffffffffu, sum, 1);
        sum += __shfl_xor_sync(0xffffffffu, sum, 2);
        if (lanei == 0) sInv[rrow] = 1.f / sum;
    }
    __syncthreads();

    // ---- PV phase (unnormalized) + normalization + residual ----
    float accO[4][4];
    #pragma unroll
    for (int i = 0; i < 4; i++)
        #pragma unroll
        for (int j = 0; j < 4; j++) accO[i][j] = 0.f;

    for (int mt = 0; mt < 4; mt++) {
        __syncthreads();
        load_tile_N(sX, Vp + mt * 64 * DK);
        __syncthreads();
        #pragma unroll 4
        for (int m = 0; m < 64; m++) {
            float p0 = sS[(ty * 4 + 0) * SPAD + mt * 64 + m];
            float p1 = sS[(ty * 4 + 1) * SPAD + mt * 64 + m];
            float p2 = sS[(ty * 4 + 2) * SPAD + mt * 64 + m];
            float p3 = sS[(ty * 4 + 3) * SPAD + mt * 64 + m];
            float4 vv = *(const float4*)(sX + m * PADT + tx * 4);
            float vvv[4] = {vv.x, vv.y, vv.z, vv.w};
            #pragma unroll
            for (int j = 0; j < 4; j++) {
                accO[0][j] += p0 * vvv[j];
                accO[1][j] += p1 * vvv[j];
                accO[2][j] += p2 * vvv[j];
                accO[3][j] += p3 * vvv[j];
            }
        }
    }

    #pragma unroll
    for (int i = 0; i < 4; i++) {
        int ng = nt * 64 + ty * 4 + i;
        float inv = sInv[ty * 4 + i];
        size_t base = ((size_t)bb * NOBJ + ng) * DIM + r * DK;
        #pragma unroll
        for (int j = 0; j < 4; j++) {
            int d = tx * 4 + j;
            out[base + d] = accO[i][j] * inv + vin[base + d];
        }
    }
}

// ============================================================
extern "C" void kernel_launch(void* const* d_in, const int* in_sizes, int n_in,
                              void* d_out, int out_size)
{
    const float* v      = (const float*)d_in[0];
    const float* bmat   = (const float*)d_in[1];
    const float* vmask  = (const float*)d_in[2];
    const float* t      = (const float*)d_in[3];
    const float* tmask  = (const float*)d_in[4];
    const float* WG1_w  = (const float*)d_in[5];
    const float* WG1_b  = (const float*)d_in[6];
    const float* WG2_w  = (const float*)d_in[7];
    const float* WG2_b  = (const float*)d_in[8];
    const float* WK_w   = (const float*)d_in[9];
    const float* WK_b   = (const float*)d_in[10];
    const float* WQ_w   = (const float*)d_in[11];
    const float* WQ_b   = (const float*)d_in[12];
    const float* WV_w   = (const float*)d_in[13];
    const float* WV_b   = (const float*)d_in[14];
    const float* tc_w   = (const float*)d_in[15];
    const float* tc_b   = (const float*)d_in[16];
    const float* tmap_w = (const float*)d_in[17];
    const float* tmap_b = (const float*)d_in[18];
    float* out = (float*)d_out;

    cudaFuncSetAttribute(tmap_kernel, cudaFuncAttributeMaxDynamicSharedMemorySize, 131072);
    cudaFuncSetAttribute(attn_kernel, cudaFuncAttributeMaxDynamicSharedMemorySize, ATTN_SMEM);
    cudaFuncSetAttribute(proj_mma_kernel, cudaFuncAttributeMaxDynamicSharedMemorySize, PJ_SMEM);

    tsum_kernel<<<BSZ, 256>>>(t, tmask, tc_w, tc_b);
    wtrans_kernel<<<dim3(16, 16, 5), 256>>>(WG1_w, WG2_w, WK_w, WQ_w, WV_w);
    tmap_kernel<<<256, 256, 131072>>>(tmap_w, tmap_b);
    proj_mma_kernel<<<dim3(2, 128, 5), 256, PJ_SMEM>>>(
        v, bmat, vmask, WG1_b, WG2_b, WK_b, WQ_b, WV_b);
    attn_kernel<<<dim3(4, RREL, BSZ), 256, ATTN_SMEM>>>(vmask, v, out);
}

// round 5
// speedup vs baseline: 1.8406x; 1.1538x over previous
#include <cuda_runtime.h>
#include <math.h>
#include <stdint.h>

#define BSZ   64
#define NOBJ  256
#define TTOK  32
#define DIM   512
#define RREL  8
#define DK    64

#define WSTRIDE (BSZ*RREL*NOBJ*DK)   // 8,388,608 elements per projection

// ---- static device scratch ----
__device__ float g_proj[5ull * WSTRIDE];              // 160 MB
__device__ float g_tmap[(size_t)BSZ * NOBJ * NOBJ];   // 16 MB
__device__ float g_tsum[BSZ * DIM];

__device__ __forceinline__ uint32_t smem_to_u32(const void* smem_ptr) {
    uint32_t addr;
    asm("{ .reg .u64 tmp; cvta.to.shared.u64 tmp, %1; cvt.u32.u64 %0, tmp; }"
        : "=r"(addr) : "l"(smem_ptr));
    return addr;
}

__device__ __forceinline__ void cp_async16(uint32_t dst, const void* src) {
    asm volatile("cp.async.cg.shared.global [%0], [%1], 16;"
                 :: "r"(dst), "l"(src) : "memory");
}
#define CP_COMMIT() asm volatile("cp.async.commit_group;" ::: "memory")
#define CP_WAIT2()  asm volatile("cp.async.wait_group 2;" ::: "memory")

__device__ __forceinline__ void mma_tf32(
    float& d0, float& d1, float& d2, float& d3,
    uint32_t a0, uint32_t a1, uint32_t a2, uint32_t a3,
    uint32_t b0, uint32_t b1)
{
    asm volatile(
        "mma.sync.aligned.m16n8k8.row.col.f32.tf32.tf32.f32 "
        "{%0,%1,%2,%3}, {%4,%5,%6,%7}, {%8,%9}, {%0,%1,%2,%3};"
        : "+f"(d0), "+f"(d1), "+f"(d2), "+f"(d3)
        : "r"(a0), "r"(a1), "r"(a2), "r"(a3), "r"(b0), "r"(b1));
}

#define FMA2(d, a, b) \
    asm("fma.rn.f32x2 %0, %1, %2, %0;" : "+l"(d) : "l"(a), "l"(b))
#define PACK2(d, lo, hi) \
    asm("mov.b64 %0, {%1, %2};" : "=l"(d) : "r"(lo), "r"(hi))
#define UNPACK2(lo, hi, d) \
    asm("mov.b64 {%0, %1}, %2;" : "=r"(lo), "=r"(hi) : "l"(d))

// ============================================================
// Kernel 1: text summary  (one block per batch)
// ============================================================
__global__ __launch_bounds__(256) void tsum_kernel(
    const float* __restrict__ t, const float* __restrict__ tmask,
    const float* __restrict__ tcw, const float* __restrict__ tcb)
{
    int bb = blockIdx.x;
    __shared__ float score[TTOK];
    const float* tb = t + (size_t)bb * TTOK * DIM;

    int warp = threadIdx.x >> 5, lane = threadIdx.x & 31;
    for (int tt = warp * 4; tt < warp * 4 + 4; tt++) {
        float s = 0.f;
        for (int d = lane; d < DIM; d += 32) s += tb[tt * DIM + d] * tcw[d];
        #pragma unroll
        for (int o = 16; o > 0; o >>= 1) s += __shfl_xor_sync(0xffffffffu, s, o);
        if (lane == 0) {
            float m = tmask[bb * TTOK + tt];
            if (m == 0.f) {
                score[tt] = 0.f;
            } else {
                float tc = s * m + tcb[0];
                float sg = 1.f / (1.f + expf(-tc));
                score[tt] = sg * m;
            }
        }
    }
    __syncthreads();

    for (int d = threadIdx.x; d < DIM; d += 256) {
        float acc = 0.f;
        #pragma unroll
        for (int tt = 0; tt < TTOK; tt++) acc += tb[tt * DIM + d] * score[tt];
        g_tsum[bb * DIM + d] = acc;
    }
}

// ============================================================
// Kernel 2: tmap = relu(t_summary @ tmap_w + tmap_b)  — f32x2 pipe
// grid 256, block 256; thread: 4 cols (float4), 16 batch rows
// ============================================================
__global__ __launch_bounds__(256) void tmap_kernel(
    const float* __restrict__ W, const float* __restrict__ bias)
{
    extern __shared__ float sT[];  // 64 x 512 fp32 = 128 KB
    for (int i = threadIdx.x; i < BSZ * DIM / 4; i += 256)
        ((float4*)sT)[i] = ((const float4*)g_tsum)[i];
    __syncthreads();

    int c4 = blockIdx.x * 64 + (threadIdx.x & 63);   // float4 column index
    int bg = threadIdx.x >> 6;                        // batch group 0..3
    const float* tb = sT + bg * 16 * DIM;
    const float4* W4 = (const float4*)W;

    unsigned long long a01[16], a23[16];
    #pragma unroll
    for (int r = 0; r < 16; r++) { a01[r] = 0ull; a23[r] = 0ull; }

    #pragma unroll 4
    for (int k = 0; k < DIM; k++) {
        float4 wv = W4[(size_t)k * 16384 + c4];
        unsigned long long w01, w23;
        PACK2(w01, __float_as_uint(wv.x), __float_as_uint(wv.y));
        PACK2(w23, __float_as_uint(wv.z), __float_as_uint(wv.w));
        #pragma unroll
        for (int r = 0; r < 16; r++) {
            uint32_t ts = __float_as_uint(tb[r * DIM + k]);
            unsigned long long td;
            PACK2(td, ts, ts);
            FMA2(a01[r], td, w01);
            FMA2(a23[r], td, w23);
        }
    }

    float4 bv = ((const float4*)bias)[c4];
    #pragma unroll
    for (int r = 0; r < 16; r++) {
        uint32_t u0, u1, u2, u3;
        UNPACK2(u0, u1, a01[r]);
        UNPACK2(u2, u3, a23[r]);
        float4 o;
        o.x = fmaxf(__uint_as_float(u0) + bv.x, 0.f);
        o.y = fmaxf(__uint_as_float(u1) + bv.y, 0.f);
        o.z = fmaxf(__uint_as_float(u2) + bv.z, 0.f);
        o.w = fmaxf(__uint_as_float(u3) + bv.w, 0.f);
        int row = bg * 16 + r;
        *(float4*)&g_tmap[(size_t)row * 65536 + (size_t)c4 * 4] = o;
    }
}

// ============================================================
// Kernel 3: 5 projections via mma.sync tf32, cp.async 3-stage pipeline
// block tile 128(M) x 256(N), BK=32, 8 warps (2M x 4N)
// smem: A tile row-major [128][36], B tile k-major [32][264], x3 stages
// ============================================================
#define PJ_ASTRIDE 36
#define PJ_BSTRIDE 264
#define PJ_A_FLOATS (128 * PJ_ASTRIDE)                 // 4608
#define PJ_STAGE_FLOATS (PJ_A_FLOATS + 32 * PJ_BSTRIDE) // 13056
#define PJ_STAGE_BYTES (PJ_STAGE_FLOATS * 4)            // 52224
#define PJ_SMEM ((3 * PJ_STAGE_FLOATS + 256) * 4)       // 157696

__global__ __launch_bounds__(256, 1) void proj_mma_kernel(
    const float* __restrict__ vin, const float* __restrict__ bmat,
    const float* __restrict__ vmask,
    const float* __restrict__ W0, const float* __restrict__ B0,
    const float* __restrict__ W1, const float* __restrict__ B1,
    const float* __restrict__ W2, const float* __restrict__ B2,
    const float* __restrict__ W3, const float* __restrict__ B3,
    const float* __restrict__ W4, const float* __restrict__ B4)
{
    extern __shared__ float smem[];
    uint32_t sbase = smem_to_u32(smem);
    float* sBias = smem + 3 * PJ_STAGE_FLOATS;

    int t = threadIdx.x;
    int wid = t >> 5, lane = t & 31;
    int mw = wid >> 2, nw = wid & 3;
    int g = lane >> 2, tg = lane & 3;

    int w  = blockIdx.z;
    int m0 = blockIdx.y * 128;
    int n0 = blockIdx.x * 256;

    const float* X = (w < 2) ? bmat : vin;
    const float* Wm; const float* Bv;
    switch (w) {
        case 0: Wm = W0; Bv = B0; break;
        case 1: Wm = W1; Bv = B1; break;
        case 2: Wm = W2; Bv = B2; break;
        case 3: Wm = W3; Bv = B3; break;
        default: Wm = W4; Bv = B4; break;
    }

    sBias[t] = Bv[n0 + t];

    // per-thread cp.async source/dest descriptors
    const float* asrc[4]; uint32_t adst[4];
    #pragma unroll
    for (int i = 0; i < 4; i++) {
        int idx = t + i * 256;          // 0..1023
        int row = idx >> 3, gc = idx & 7;
        asrc[i] = X + (size_t)(m0 + row) * DIM + gc * 4;
        adst[i] = (uint32_t)(row * PJ_ASTRIDE + gc * 4) * 4;
    }
    const float* bsrc[8]; uint32_t bdst[8];
    #pragma unroll
    for (int i = 0; i < 8; i++) {
        int idx = t + i * 256;          // 0..2047
        int kr = idx >> 6, gc = idx & 63;
        bsrc[i] = Wm + (size_t)kr * DIM + n0 + gc * 4;
        bdst[i] = (uint32_t)(PJ_A_FLOATS + kr * PJ_BSTRIDE + gc * 4) * 4;
    }

    // prologue: issue stages 0,1,2
    #pragma unroll
    for (int c = 0; c < 3; c++) {
        uint32_t sb = sbase + (uint32_t)c * PJ_STAGE_BYTES;
        int k0 = c * 32;
        #pragma unroll
        for (int i = 0; i < 4; i++) cp_async16(sb + adst[i], asrc[i] + k0);
        #pragma unroll
        for (int i = 0; i < 8; i++) cp_async16(sb + bdst[i], bsrc[i] + (size_t)k0 * DIM);
        CP_COMMIT();
    }

    float acc[4][8][4];
    #pragma unroll
    for (int i = 0; i < 4; i++)
        #pragma unroll
        for (int j = 0; j < 8; j++)
            #pragma unroll
            for (int q = 0; q < 4; q++) acc[i][j][q] = 0.f;

    for (int c = 0; c < 16; c++) {
        CP_WAIT2();
        __syncthreads();
        const float* sA = smem + (c % 3) * PJ_STAGE_FLOATS;
        const float* sB = sA + PJ_A_FLOATS;

        #pragma unroll
        for (int ka = 0; ka < 4; ka++) {
            uint32_t af[4][4], bf[4][4];
            #pragma unroll
            for (int ml = 0; ml < 4; ml++) {
                const uint32_t* p0 = (const uint32_t*)(sA
                    + (mw * 64 + ml * 16 + g) * PJ_ASTRIDE + ka * 8 + tg);
                af[ml][0] = p0[0];
                af[ml][1] = p0[8 * PJ_ASTRIDE];
                af[ml][2] = p0[4];
                af[ml][3] = p0[8 * PJ_ASTRIDE + 4];
            }
            #pragma unroll
            for (int pl = 0; pl < 4; pl++) {
                const uint32_t* q0 = (const uint32_t*)(sB
                    + (ka * 8 + tg) * PJ_BSTRIDE + nw * 64 + pl * 16 + g);
                bf[pl][0] = q0[0];
                bf[pl][1] = q0[4 * PJ_BSTRIDE];
                bf[pl][2] = q0[8];
                bf[pl][3] = q0[4 * PJ_BSTRIDE + 8];
            }
            #pragma unroll
            for (int ml = 0; ml < 4; ml++) {
                #pragma unroll
                for (int pl = 0; pl < 4; pl++) {
                    mma_tf32(acc[ml][pl*2][0], acc[ml][pl*2][1],
                             acc[ml][pl*2][2], acc[ml][pl*2][3],
                             af[ml][0], af[ml][1], af[ml][2], af[ml][3],
                             bf[pl][0], bf[pl][1]);
                    mma_tf32(acc[ml][pl*2+1][0], acc[ml][pl*2+1][1],
                             acc[ml][pl*2+1][2], acc[ml][pl*2+1][3],
                             af[ml][0], af[ml][1], af[ml][2], af[ml][3],
                             bf[pl][2], bf[pl][3]);
                }
            }
        }
        __syncthreads();

        if (c + 3 < 16) {
            int cc = c + 3;
            uint32_t sb = sbase + (uint32_t)(cc % 3) * PJ_STAGE_BYTES;
            int k0 = cc * 32;
            #pragma unroll
            for (int i = 0; i < 4; i++) cp_async16(sb + adst[i], asrc[i] + k0);
            #pragma unroll
            for (int i = 0; i < 8; i++) cp_async16(sb + bdst[i], bsrc[i] + (size_t)k0 * DIM);
            CP_COMMIT();
        }
    }

    // ---- epilogue: bias + mask, scatter to (b,r,n,dk) ----
    float* Pout = g_proj + (size_t)w * WSTRIDE;
    #pragma unroll
    for (int ml = 0; ml < 4; ml++) {
        int gm0 = m0 + mw * 64 + ml * 16 + g;
        int gm1 = gm0 + 8;
        float msk0 = (w < 2) ? vmask[gm0] : 1.0f;
        float msk1 = (w < 2) ? vmask[gm1] : 1.0f;
        int bbi0 = gm0 >> 8, nn0 = gm0 & 255;
        int bbi1 = gm1 >> 8, nn1 = gm1 & 255;
        #pragma unroll
        for (int nl = 0; nl < 8; nl++) {
            int cl = (nw * 8 + nl) * 8 + tg * 2;
            int cg = n0 + cl;
            int rrel = cg >> 6, d = cg & 63;
            float b0 = sBias[cl], b1 = sBias[cl + 1];
            float2 v0, v1;
            v0.x = (acc[ml][nl][0] + b0) * msk0;
            v0.y = (acc[ml][nl][1] + b1) * msk0;
            v1.x = (acc[ml][nl][2] + b0) * msk1;
            v1.y = (acc[ml][nl][3] + b1) * msk1;
            *(float2*)&Pout[((size_t)(bbi0 * RREL + rrel) * NOBJ + nn0) * DK + d] = v0;
            *(float2*)&Pout[((size_t)(bbi1 * RREL + rrel) * NOBJ + nn1) * DK + d] = v1;
        }
    }
}

// ============================================================
// Kernel 4: fused attention — log-free softmax + register prefetch
// ============================================================
#define PADT 68
#define SPAD 260
#define SINV_OFF (4 * 64 * PADT + 64 * SPAD)
#define ATTN_SMEM ((SINV_OFF + 64) * 4)

__device__ __forceinline__ void tile_ldg(float4* r, const float* __restrict__ src)
{
    int t = threadIdx.x;
    #pragma unroll
    for (int p = 0; p < 4; p++) {
        int idx = (t + p * 256) * 4;
        int row = idx >> 6, k = idx & 63;
        r[p] = *(const float4*)(src + row * 64 + k);
    }
}

__device__ __forceinline__ void tile_sts_T(float* dst, const float4* r)
{
    int t = threadIdx.x;
    #pragma unroll
    for (int p = 0; p < 4; p++) {
        int idx = (t + p * 256) * 4;
        int row = idx >> 6, k = idx & 63;
        dst[(k + 0) * PADT + row] = r[p].x;
        dst[(k + 1) * PADT + row] = r[p].y;
        dst[(k + 2) * PADT + row] = r[p].z;
        dst[(k + 3) * PADT + row] = r[p].w;
    }
}

__device__ __forceinline__ void tile_sts_N(float* dst, const float4* r)
{
    int t = threadIdx.x;
    #pragma unroll
    for (int p = 0; p < 4; p++) {
        int idx = (t + p * 256) * 4;
        int row = idx >> 6, k = idx & 63;
        *(float4*)(dst + row * PADT + k) = r[p];
    }
}

__global__ __launch_bounds__(256) void attn_kernel(
    const float* __restrict__ vmask, const float* __restrict__ vin,
    float* __restrict__ out)
{
    extern __shared__ float sm[];
    float* sG1 = sm;
    float* sK  = sm + 1 * 64 * PADT;
    float* sX  = sm + 2 * 64 * PADT;
    float* sY  = sm + 3 * 64 * PADT;
    float* sS  = sm + 4 * 64 * PADT;
    float* sInv = sm + SINV_OFF;

    int nt = blockIdx.x, r = blockIdx.y, bb = blockIdx.z;
    int t  = threadIdx.x;
    int tx = t & 15, ty = t >> 4;

    size_t pbase = (size_t)(bb * RREL + r) * NOBJ * DK;
    const float* G1 = g_proj + 0ull * WSTRIDE + pbase;
    const float* G2 = g_proj + 1ull * WSTRIDE + pbase;
    const float* Kp = g_proj + 2ull * WSTRIDE + pbase;
    const float* Qp = g_proj + 3ull * WSTRIDE + pbase;
    const float* Vp = g_proj + 4ull * WSTRIDE + pbase;

    {
        float4 rg[4], rk[4];
        tile_ldg(rg, G1 + nt * 64 * DK);
        tile_ldg(rk, Kp + nt * 64 * DK);
        tile_sts_T(sG1, rg);
        tile_sts_T(sK, rk);
    }

    const float* tmrow = g_tmap + ((size_t)bb * NOBJ * NOBJ);

    float4 px[4], py[4];
    tile_ldg(px, G2);
    tile_ldg(py, Qp);

    for (int mt = 0; mt < 4; mt++) {
        tile_sts_T(sX, px);
        tile_sts_T(sY, py);
        __syncthreads();

        if (mt < 3) {
            tile_ldg(px, G2 + (mt + 1) * 64 * DK);
            tile_ldg(py, Qp + (mt + 1) * 64 * DK);
        }

        float accG[4][4], accS[4][4];
        #pragma unroll
        for (int i = 0; i < 4; i++)
            #pragma unroll
            for (int j = 0; j < 4; j++) { accG[i][j] = 0.f; accS[i][j] = 0.f; }

        #pragma unroll 8
        for (int k = 0; k < 64; k++) {
            float4 a1 = *(const float4*)(sG1 + k * PADT + ty * 4);
            float4 b1 = *(const float4*)(sX  + k * PADT + tx * 4);
            float4 a2 = *(const float4*)(sK  + k * PADT + ty * 4);
            float4 b2 = *(const float4*)(sY  + k * PADT + tx * 4);
            float a1v[4] = {a1.x, a1.y, a1.z, a1.w};
            float b1v[4] = {b1.x, b1.y, b1.z, b1.w};
            float a2v[4] = {a2.x, a2.y, a2.z, a2.w};
            float b2v[4] = {b2.x, b2.y, b2.z, b2.w};
            #pragma unroll
            for (int i = 0; i < 4; i++)
                #pragma unroll
                for (int j = 0; j < 4; j++) {
                    accG[i][j] += a1v[i] * b1v[j];
                    accS[i][j] += a2v[i] * b2v[j];
                }
        }

        float cm[4];
        #pragma unroll
        for (int j = 0; j < 4; j++)
            cm[j] = vmask[bb * NOBJ + mt * 64 + tx * 4 + j];

        #pragma unroll
        for (int i = 0; i < 4; i++) {
            int ng = nt * 64 + ty * 4 + i;
            #pragma unroll
            for (int j = 0; j < 4; j++) {
                int mg = mt * 64 + tx * 4 + j;
                float tm = tmrow[ng * NOBJ + mg];
                float wgc = fmaxf(fmaxf(accG[i][j], 0.f) + tm, 1e-6f);
                float sd  = fminf(accS[i][j] * 0.125f, 60.f);
                float tv  = wgc * __expf(sd);
                if (cm[j] == 0.f) tv = 0.f;
                sS[(ty * 4 + i) * SPAD + mg] = tv;
            }
        }
        __syncthreads();
    }

    // ---- row sums -> 1/sum ----
    {
        int rrow = t >> 2;
        int lanei = t & 3;
        const float* rowp = sS + rrow * SPAD;
        float sum = 0.f;
        for (int m = lanei; m < 256; m += 4) sum += rowp[m];
        sum += __shfl_xor_sync(0xffffffffu, sum, 1);
        sum += __shfl_xor_sync(0xffffffffu, sum, 2);
        if (lanei == 0) sInv[rrow] = 1.f / sum;
    }
    __syncthreads();

    // ---- PV phase (unnormalized) + normalization + residual ----
    float accO[4][4];
    #pragma unroll
    for (int i = 0; i < 4; i++)
        #pragma unroll
        for (int j = 0; j < 4; j++) accO[i][j] = 0.f;

    float4 pv[4];
    tile_ldg(pv, Vp);

    for (int mt = 0; mt < 4; mt++) {
        tile_sts_N(sX, pv);
        __syncthreads();
        if (mt < 3) tile_ldg(pv, Vp + (mt + 1) * 64 * DK);

        #pragma unroll 4
        for (int m = 0; m < 64; m++) {
            float p0 = sS[(ty * 4 + 0) * SPAD + mt * 64 + m];
            float p1 = sS[(ty * 4 + 1) * SPAD + mt * 64 + m];
            float p2 = sS[(ty * 4 + 2) * SPAD + mt * 64 + m];
            float p3 = sS[(ty * 4 + 3) * SPAD + mt * 64 + m];
            float4 vv = *(const float4*)(sX + m * PADT + tx * 4);
            float vvv[4] = {vv.x, vv.y, vv.z, vv.w};
            #pragma unroll
            for (int j = 0; j < 4; j++) {
                accO[0][j] += p0 * vvv[j];
                accO[1][j] += p1 * vvv[j];
                accO[2][j] += p2 * vvv[j];
                accO[3][j] += p3 * vvv[j];
            }
        }
        __syncthreads();
    }

    #pragma unroll
    for (int i = 0; i < 4; i++) {
        int ng = nt * 64 + ty * 4 + i;
        float inv = sInv[ty * 4 + i];
        size_t base = ((size_t)bb * NOBJ + ng) * DIM + r * DK;
        #pragma unroll
        for (int j = 0; j < 4; j++) {
            int d = tx * 4 + j;
            out[base + d] = accO[i][j] * inv + vin[base + d];
        }
    }
}

// ============================================================
extern "C" void kernel_launch(void* const* d_in, const int* in_sizes, int n_in,
                              void* d_out, int out_size)
{
    const float* v      = (const float*)d_in[0];
    const float* bmat   = (const float*)d_in[1];
    const float* vmask  = (const float*)d_in[2];
    const float* t      = (const float*)d_in[3];
    const float* tmask  = (const float*)d_in[4];
    const float* WG1_w  = (const float*)d_in[5];
    const float* WG1_b  = (const float*)d_in[6];
    const float* WG2_w  = (const float*)d_in[7];
    const float* WG2_b  = (const float*)d_in[8];
    const float* WK_w   = (const float*)d_in[9];
    const float* WK_b   = (const float*)d_in[10];
    const float* WQ_w   = (const float*)d_in[11];
    const float* WQ_b   = (const float*)d_in[12];
    const float* WV_w   = (const float*)d_in[13];
    const float* WV_b   = (const float*)d_in[14];
    const float* tc_w   = (const float*)d_in[15];
    const float* tc_b   = (const float*)d_in[16];
    const float* tmap_w = (const float*)d_in[17];
    const float* tmap_b = (const float*)d_in[18];
    float* out = (float*)d_out;

    cudaFuncSetAttribute(tmap_kernel, cudaFuncAttributeMaxDynamicSharedMemorySize, 131072);
    cudaFuncSetAttribute(attn_kernel, cudaFuncAttributeMaxDynamicSharedMemorySize, ATTN_SMEM);
    cudaFuncSetAttribute(proj_mma_kernel, cudaFuncAttributeMaxDynamicSharedMemorySize, PJ_SMEM);

    tsum_kernel<<<BSZ, 256>>>(t, tmask, tc_w, tc_b);
    tmap_kernel<<<256, 256, 131072>>>(tmap_w, tmap_b);
    proj_mma_kernel<<<dim3(2, 128, 5), 256, PJ_SMEM>>>(
        v, bmat, vmask,
        WG1_w, WG1_b, WG2_w, WG2_b, WK_w, WK_b, WQ_w, WQ_b, WV_w, WV_b);
    attn_kernel<<<dim3(4, RREL, BSZ), 256, ATTN_SMEM>>>(vmask, v, out);
}

// round 6
// speedup vs baseline: 2.4572x; 1.3350x over previous
#include <cuda_runtime.h>
#include <math.h>
#include <stdint.h>

#define BSZ   64
#define NOBJ  256
#define TTOK  32
#define DIM   512
#define RREL  8
#define DK    64

#define WSTRIDE (BSZ*RREL*NOBJ*DK)   // 8,388,608 elements per projection

// ---- static device scratch ----
__device__ float g_proj[5ull * WSTRIDE];              // 160 MB
__device__ float g_tmap[(size_t)BSZ * NOBJ * NOBJ];   // 16 MB
__device__ float g_tsum[BSZ * DIM];

__device__ __forceinline__ uint32_t smem_to_u32(const void* smem_ptr) {
    uint32_t addr;
    asm("{ .reg .u64 tmp; cvta.to.shared.u64 tmp, %1; cvt.u32.u64 %0, tmp; }"
        : "=r"(addr) : "l"(smem_ptr));
    return addr;
}

__device__ __forceinline__ void cp_async16(uint32_t dst, const void* src) {
    asm volatile("cp.async.cg.shared.global [%0], [%1], 16;"
                 :: "r"(dst), "l"(src) : "memory");
}
#define CP_COMMIT() asm volatile("cp.async.commit_group;" ::: "memory")
#define CP_WAIT2()  asm volatile("cp.async.wait_group 2;" ::: "memory")

__device__ __forceinline__ void mma_tf32(
    float& d0, float& d1, float& d2, float& d3,
    uint32_t a0, uint32_t a1, uint32_t a2, uint32_t a3,
    uint32_t b0, uint32_t b1)
{
    asm volatile(
        "mma.sync.aligned.m16n8k8.row.col.f32.tf32.tf32.f32 "
        "{%0,%1,%2,%3}, {%4,%5,%6,%7}, {%8,%9}, {%0,%1,%2,%3};"
        : "+f"(d0), "+f"(d1), "+f"(d2), "+f"(d3)
        : "r"(a0), "r"(a1), "r"(a2), "r"(a3), "r"(b0), "r"(b1));
}

#define FMA2(d, a, b) \
    asm("fma.rn.f32x2 %0, %1, %2, %0;" : "+l"(d) : "l"(a), "l"(b))
#define PACK2(d, lo, hi) \
    asm("mov.b64 %0, {%1, %2};" : "=l"(d) : "r"(lo), "r"(hi))
#define UNPACK2(lo, hi, d) \
    asm("mov.b64 {%0, %1}, %2;" : "=r"(lo), "=r"(hi) : "l"(d))

// ============================================================
// Kernel 1: text summary  (one block per batch)
// ============================================================
__global__ __launch_bounds__(256) void tsum_kernel(
    const float* __restrict__ t, const float* __restrict__ tmask,
    const float* __restrict__ tcw, const float* __restrict__ tcb)
{
    int bb = blockIdx.x;
    __shared__ float score[TTOK];
    const float* tb = t + (size_t)bb * TTOK * DIM;

    int warp = threadIdx.x >> 5, lane = threadIdx.x & 31;
    for (int tt = warp * 4; tt < warp * 4 + 4; tt++) {
        float s = 0.f;
        for (int d = lane; d < DIM; d += 32) s += tb[tt * DIM + d] * tcw[d];
        #pragma unroll
        for (int o = 16; o > 0; o >>= 1) s += __shfl_xor_sync(0xffffffffu, s, o);
        if (lane == 0) {
            float m = tmask[bb * TTOK + tt];
            if (m == 0.f) {
                score[tt] = 0.f;
            } else {
                float tc = s * m + tcb[0];
                float sg = 1.f / (1.f + expf(-tc));
                score[tt] = sg * m;
            }
        }
    }
    __syncthreads();

    for (int d = threadIdx.x; d < DIM; d += 256) {
        float acc = 0.f;
        #pragma unroll
        for (int tt = 0; tt < TTOK; tt++) acc += tb[tt * DIM + d] * score[tt];
        g_tsum[bb * DIM + d] = acc;
    }
}

// ============================================================
// Kernel 2: tmap = relu(t_summary @ tmap_w + tmap_b)  — f32x2 pipe
// ============================================================
__global__ __launch_bounds__(256) void tmap_kernel(
    const float* __restrict__ W, const float* __restrict__ bias)
{
    extern __shared__ float sT[];  // 64 x 512 fp32 = 128 KB
    for (int i = threadIdx.x; i < BSZ * DIM / 4; i += 256)
        ((float4*)sT)[i] = ((const float4*)g_tsum)[i];
    __syncthreads();

    int c4 = blockIdx.x * 64 + (threadIdx.x & 63);
    int bg = threadIdx.x >> 6;
    const float* tb = sT + bg * 16 * DIM;
    const float4* W4 = (const float4*)W;

    unsigned long long a01[16], a23[16];
    #pragma unroll
    for (int r = 0; r < 16; r++) { a01[r] = 0ull; a23[r] = 0ull; }

    #pragma unroll 4
    for (int k = 0; k < DIM; k++) {
        float4 wv = W4[(size_t)k * 16384 + c4];
        unsigned long long w01, w23;
        PACK2(w01, __float_as_uint(wv.x), __float_as_uint(wv.y));
        PACK2(w23, __float_as_uint(wv.z), __float_as_uint(wv.w));
        #pragma unroll
        for (int r = 0; r < 16; r++) {
            uint32_t ts = __float_as_uint(tb[r * DIM + k]);
            unsigned long long td;
            PACK2(td, ts, ts);
            FMA2(a01[r], td, w01);
            FMA2(a23[r], td, w23);
        }
    }

    float4 bv = ((const float4*)bias)[c4];
    #pragma unroll
    for (int r = 0; r < 16; r++) {
        uint32_t u0, u1, u2, u3;
        UNPACK2(u0, u1, a01[r]);
        UNPACK2(u2, u3, a23[r]);
        float4 o;
        o.x = fmaxf(__uint_as_float(u0) + bv.x, 0.f);
        o.y = fmaxf(__uint_as_float(u1) + bv.y, 0.f);
        o.z = fmaxf(__uint_as_float(u2) + bv.z, 0.f);
        o.w = fmaxf(__uint_as_float(u3) + bv.w, 0.f);
        int row = bg * 16 + r;
        *(float4*)&g_tmap[(size_t)row * 65536 + (size_t)c4 * 4] = o;
    }
}

// ============================================================
// Kernel 3: 5 projections via mma.sync tf32, cp.async 3-stage pipeline
// ============================================================
#define PJ_ASTRIDE 36
#define PJ_BSTRIDE 264
#define PJ_A_FLOATS (128 * PJ_ASTRIDE)
#define PJ_STAGE_FLOATS (PJ_A_FLOATS + 32 * PJ_BSTRIDE)
#define PJ_STAGE_BYTES (PJ_STAGE_FLOATS * 4)
#define PJ_SMEM ((3 * PJ_STAGE_FLOATS + 256) * 4)

__global__ __launch_bounds__(256, 1) void proj_mma_kernel(
    const float* __restrict__ vin, const float* __restrict__ bmat,
    const float* __restrict__ vmask,
    const float* __restrict__ W0, const float* __restrict__ B0,
    const float* __restrict__ W1, const float* __restrict__ B1,
    const float* __restrict__ W2, const float* __restrict__ B2,
    const float* __restrict__ W3, const float* __restrict__ B3,
    const float* __restrict__ W4, const float* __restrict__ B4)
{
    extern __shared__ float smem[];
    uint32_t sbase = smem_to_u32(smem);
    float* sBias = smem + 3 * PJ_STAGE_FLOATS;

    int t = threadIdx.x;
    int wid = t >> 5, lane = t & 31;
    int mw = wid >> 2, nw = wid & 3;
    int g = lane >> 2, tg = lane & 3;

    int w  = blockIdx.z;
    int m0 = blockIdx.y * 128;
    int n0 = blockIdx.x * 256;

    const float* X = (w < 2) ? bmat : vin;
    const float* Wm; const float* Bv;
    switch (w) {
        case 0: Wm = W0; Bv = B0; break;
        case 1: Wm = W1; Bv = B1; break;
        case 2: Wm = W2; Bv = B2; break;
        case 3: Wm = W3; Bv = B3; break;
        default: Wm = W4; Bv = B4; break;
    }

    sBias[t] = Bv[n0 + t];

    const float* asrc[4]; uint32_t adst[4];
    #pragma unroll
    for (int i = 0; i < 4; i++) {
        int idx = t + i * 256;
        int row = idx >> 3, gc = idx & 7;
        asrc[i] = X + (size_t)(m0 + row) * DIM + gc * 4;
        adst[i] = (uint32_t)(row * PJ_ASTRIDE + gc * 4) * 4;
    }
    const float* bsrc[8]; uint32_t bdst[8];
    #pragma unroll
    for (int i = 0; i < 8; i++) {
        int idx = t + i * 256;
        int kr = idx >> 6, gc = idx & 63;
        bsrc[i] = Wm + (size_t)kr * DIM + n0 + gc * 4;
        bdst[i] = (uint32_t)(PJ_A_FLOATS + kr * PJ_BSTRIDE + gc * 4) * 4;
    }

    #pragma unroll
    for (int c = 0; c < 3; c++) {
        uint32_t sb = sbase + (uint32_t)c * PJ_STAGE_BYTES;
        int k0 = c * 32;
        #pragma unroll
        for (int i = 0; i < 4; i++) cp_async16(sb + adst[i], asrc[i] + k0);
        #pragma unroll
        for (int i = 0; i < 8; i++) cp_async16(sb + bdst[i], bsrc[i] + (size_t)k0 * DIM);
        CP_COMMIT();
    }

    float acc[4][8][4];
    #pragma unroll
    for (int i = 0; i < 4; i++)
        #pragma unroll
        for (int j = 0; j < 8; j++)
            #pragma unroll
            for (int q = 0; q < 4; q++) acc[i][j][q] = 0.f;

    for (int c = 0; c < 16; c++) {
        CP_WAIT2();
        __syncthreads();
        const float* sA = smem + (c % 3) * PJ_STAGE_FLOATS;
        const float* sB = sA + PJ_A_FLOATS;

        #pragma unroll
        for (int ka = 0; ka < 4; ka++) {
            uint32_t af[4][4], bf[4][4];
            #pragma unroll
            for (int ml = 0; ml < 4; ml++) {
                const uint32_t* p0 = (const uint32_t*)(sA
                    + (mw * 64 + ml * 16 + g) * PJ_ASTRIDE + ka * 8 + tg);
                af[ml][0] = p0[0];
                af[ml][1] = p0[8 * PJ_ASTRIDE];
                af[ml][2] = p0[4];
                af[ml][3] = p0[8 * PJ_ASTRIDE + 4];
            }
            #pragma unroll
            for (int pl = 0; pl < 4; pl++) {
                const uint32_t* q0 = (const uint32_t*)(sB
                    + (ka * 8 + tg) * PJ_BSTRIDE + nw * 64 + pl * 16 + g);
                bf[pl][0] = q0[0];
                bf[pl][1] = q0[4 * PJ_BSTRIDE];
                bf[pl][2] = q0[8];
                bf[pl][3] = q0[4 * PJ_BSTRIDE + 8];
            }
            #pragma unroll
            for (int ml = 0; ml < 4; ml++) {
                #pragma unroll
                for (int pl = 0; pl < 4; pl++) {
                    mma_tf32(acc[ml][pl*2][0], acc[ml][pl*2][1],
                             acc[ml][pl*2][2], acc[ml][pl*2][3],
                             af[ml][0], af[ml][1], af[ml][2], af[ml][3],
                             bf[pl][0], bf[pl][1]);
                    mma_tf32(acc[ml][pl*2+1][0], acc[ml][pl*2+1][1],
                             acc[ml][pl*2+1][2], acc[ml][pl*2+1][3],
                             af[ml][0], af[ml][1], af[ml][2], af[ml][3],
                             bf[pl][2], bf[pl][3]);
                }
            }
        }
        __syncthreads();

        if (c + 3 < 16) {
            int cc = c + 3;
            uint32_t sb = sbase + (uint32_t)(cc % 3) * PJ_STAGE_BYTES;
            int k0 = cc * 32;
            #pragma unroll
            for (int i = 0; i < 4; i++) cp_async16(sb + adst[i], asrc[i] + k0);
            #pragma unroll
            for (int i = 0; i < 8; i++) cp_async16(sb + bdst[i], bsrc[i] + (size_t)k0 * DIM);
            CP_COMMIT();
        }
    }

    float* Pout = g_proj + (size_t)w * WSTRIDE;
    #pragma unroll
    for (int ml = 0; ml < 4; ml++) {
        int gm0 = m0 + mw * 64 + ml * 16 + g;
        int gm1 = gm0 + 8;
        float msk0 = (w < 2) ? vmask[gm0] : 1.0f;
        float msk1 = (w < 2) ? vmask[gm1] : 1.0f;
        int bbi0 = gm0 >> 8, nn0 = gm0 & 255;
        int bbi1 = gm1 >> 8, nn1 = gm1 & 255;
        #pragma unroll
        for (int nl = 0; nl < 8; nl++) {
            int cl = (nw * 8 + nl) * 8 + tg * 2;
            int cg = n0 + cl;
            int rrel = cg >> 6, d = cg & 63;
            float b0 = sBias[cl], b1 = sBias[cl + 1];
            float2 v0, v1;
            v0.x = (acc[ml][nl][0] + b0) * msk0;
            v0.y = (acc[ml][nl][1] + b1) * msk0;
            v1.x = (acc[ml][nl][2] + b0) * msk1;
            v1.y = (acc[ml][nl][3] + b1) * msk1;
            *(float2*)&Pout[((size_t)(bbi0 * RREL + rrel) * NOBJ + nn0) * DK + d] = v0;
            *(float2*)&Pout[((size_t)(bbi1 * RREL + rrel) * NOBJ + nn1) * DK + d] = v1;
        }
    }
}

// ============================================================
// Kernel 4: fused attention — fully tensorized (mma.sync tf32)
//
// Block = (nt, r, bb): 64 score rows x 256 cols. 8 warps (2Mx4N).
// smem: 4 natural tiles [64][68] (G1,K | G2,Q chunks), overlaid by
//       Vt [64][260] in PV phase; S [64][260]; row inv [64].
// ============================================================
#define TPAD 68
#define SPAD 260
#define TILE_F (64 * TPAD)
#define SS_OFF  (4 * TILE_F)
#define SINV_OFF (SS_OFF + 64 * SPAD)
#define ATTN_SMEM ((SINV_OFF + 64) * 4)   // 136448 bytes

__device__ __forceinline__ void tile_ldg(float4* r, const float* __restrict__ src)
{
    int t = threadIdx.x;
    #pragma unroll
    for (int p = 0; p < 4; p++) {
        int idx = (t + p * 256) * 4;
        int row = idx >> 6, k = idx & 63;
        r[p] = *(const float4*)(src + row * 64 + k);
    }
}

__device__ __forceinline__ void tile_sts_rows(float* dst, const float4* r)
{
    int t = threadIdx.x;
    #pragma unroll
    for (int p = 0; p < 4; p++) {
        int idx = (t + p * 256) * 4;
        int row = idx >> 6, k = idx & 63;
        *(float4*)(dst + row * TPAD + k) = r[p];
    }
}

__global__ __launch_bounds__(256) void attn_kernel(
    const float* __restrict__ vmask, const float* __restrict__ vin,
    float* __restrict__ out)
{
    extern __shared__ float sm[];
    float* sG1 = sm;
    float* sK  = sm + TILE_F;
    float* sX  = sm + 2 * TILE_F;
    float* sY  = sm + 3 * TILE_F;
    float* sVt = sm;                 // overlay (PV phase)
    float* sS  = sm + SS_OFF;
    float* sInv = sm + SINV_OFF;

    int nt = blockIdx.x, r = blockIdx.y, bb = blockIdx.z;
    int t  = threadIdx.x;
    int wid = t >> 5, lane = t & 31;
    int g = lane >> 2, tg = lane & 3;
    int wm = wid >> 2, wn = wid & 3;

    size_t pbase = (size_t)(bb * RREL + r) * NOBJ * DK;
    const float* G1 = g_proj + 0ull * WSTRIDE + pbase;
    const float* G2 = g_proj + 1ull * WSTRIDE + pbase;
    const float* Kp = g_proj + 2ull * WSTRIDE + pbase;
    const float* Qp = g_proj + 3ull * WSTRIDE + pbase;
    const float* Vp = g_proj + 4ull * WSTRIDE + pbase;

    // stage G1, K tiles (natural row-major [n][64], stride 68)
    {
        float4 rg[4], rk[4];
        tile_ldg(rg, G1 + nt * 64 * DK);
        tile_ldg(rk, Kp + nt * 64 * DK);
        tile_sts_rows(sG1, rg);
        tile_sts_rows(sK, rk);
    }

    const float* tmrow = g_tmap + ((size_t)bb * NOBJ * NOBJ);

    float4 px[4], py[4];
    tile_ldg(px, G2);
    tile_ldg(py, Qp);

    // ---- score phase ----
    for (int mt = 0; mt < 4; mt++) {
        tile_sts_rows(sX, px);
        tile_sts_rows(sY, py);
        __syncthreads();

        if (mt < 3) {
            tile_ldg(px, G2 + (mt + 1) * 64 * DK);
            tile_ldg(py, Qp + (mt + 1) * 64 * DK);
        }

        float accG[2][2][4], accS[2][2][4];
        #pragma unroll
        for (int i = 0; i < 2; i++)
            #pragma unroll
            for (int j = 0; j < 2; j++)
                #pragma unroll
                for (int q = 0; q < 4; q++) { accG[i][j][q] = 0.f; accS[i][j][q] = 0.f; }

        #pragma unroll
        for (int ks = 0; ks < 8; ks++) {
            int k0 = ks * 8;
            uint32_t aG[2][4], aK[2][4];
            #pragma unroll
            for (int ma = 0; ma < 2; ma++) {
                int rb = wm * 32 + ma * 16 + g;
                const uint32_t* p1 = (const uint32_t*)(sG1 + rb * TPAD + k0 + tg);
                aG[ma][0] = p1[0]; aG[ma][1] = p1[8 * TPAD];
                aG[ma][2] = p1[4]; aG[ma][3] = p1[8 * TPAD + 4];
                const uint32_t* p2 = (const uint32_t*)(sK + rb * TPAD + k0 + tg);
                aK[ma][0] = p2[0]; aK[ma][1] = p2[8 * TPAD];
                aK[ma][2] = p2[4]; aK[ma][3] = p2[8 * TPAD + 4];
            }
            uint32_t bX[2][2], bY[2][2];
            #pragma unroll
            for (int na = 0; na < 2; na++) {
                int cb = wn * 16 + na * 8 + g;
                const uint32_t* q1 = (const uint32_t*)(sX + cb * TPAD + k0 + tg);
                bX[na][0] = q1[0]; bX[na][1] = q1[4];
                const uint32_t* q2 = (const uint32_t*)(sY + cb * TPAD + k0 + tg);
                bY[na][0] = q2[0]; bY[na][1] = q2[4];
            }
            #pragma unroll
            for (int ma = 0; ma < 2; ma++)
                #pragma unroll
                for (int na = 0; na < 2; na++) {
                    mma_tf32(accG[ma][na][0], accG[ma][na][1],
                             accG[ma][na][2], accG[ma][na][3],
                             aG[ma][0], aG[ma][1], aG[ma][2], aG[ma][3],
                             bX[na][0], bX[na][1]);
                    mma_tf32(accS[ma][na][0], accS[ma][na][1],
                             accS[ma][na][2], accS[ma][na][3],
                             aK[ma][0], aK[ma][1], aK[ma][2], aK[ma][3],
                             bY[na][0], bY[na][1]);
                }
        }

        // epilogue: relu + tmap + exp + mask -> sS
        #pragma unroll
        for (int ma = 0; ma < 2; ma++) {
            #pragma unroll
            for (int na = 0; na < 2; na++) {
                int col = wn * 16 + na * 8 + tg * 2;
                int mg  = mt * 64 + col;
                float2 vm = *(const float2*)&vmask[bb * NOBJ + mg];
                #pragma unroll
                for (int h = 0; h < 2; h++) {
                    int row = wm * 32 + ma * 16 + g + h * 8;
                    int ng  = nt * 64 + row;
                    float2 tm = *(const float2*)&tmrow[(size_t)ng * NOBJ + mg];
                    float cG0 = accG[ma][na][h * 2], cG1 = accG[ma][na][h * 2 + 1];
                    float cS0 = accS[ma][na][h * 2], cS1 = accS[ma][na][h * 2 + 1];
                    float wg0 = fmaxf(fmaxf(cG0, 0.f) + tm.x, 1e-6f);
                    float wg1 = fmaxf(fmaxf(cG1, 0.f) + tm.y, 1e-6f);
                    float t0 = wg0 * __expf(fminf(cS0 * 0.125f, 60.f));
                    float t1 = wg1 * __expf(fminf(cS1 * 0.125f, 60.f));
                    if (vm.x == 0.f) t0 = 0.f;
                    if (vm.y == 0.f) t1 = 0.f;
                    float2 sv = {t0, t1};
                    *(float2*)&sS[row * SPAD + mg] = sv;
                }
            }
        }
        __syncthreads();
    }

    // ---- row sums -> 1/sum ----
    {
        int rrow = t >> 2;
        int lanei = t & 3;
        const float* rowp = sS + rrow * SPAD;
        float sum = 0.f;
        for (int m = lanei; m < 256; m += 4) sum += rowp[m];
        sum += __shfl_xor_sync(0xffffffffu, sum, 1);
        sum += __shfl_xor_sync(0xffffffffu, sum, 2);
        if (lanei == 0) sInv[rrow] = 1.f / sum;
    }
    __syncthreads();

    // ---- stage V^T into overlay region: sVt[dk][m], stride SPAD ----
    for (int mt = 0; mt < 4; mt++) {
        int mb = mt * 64;
        #pragma unroll
        for (int p = 0; p < 4; p++) {
            int idx = (t + p * 256) * 4;
            int m = idx >> 6, k4 = idx & 63;
            float4 vv = *(const float4*)(Vp + (size_t)(mb + m) * DK + k4);
            sVt[(k4 + 0) * SPAD + mb + m] = vv.x;
            sVt[(k4 + 1) * SPAD + mb + m] = vv.y;
            sVt[(k4 + 2) * SPAD + mb + m] = vv.z;
            sVt[(k4 + 3) * SPAD + mb + m] = vv.w;
        }
    }
    __syncthreads();

    // ---- PV via mma: O[64][64] = P[64][256] @ V[256][64] ----
    float accO[2][2][4];
    #pragma unroll
    for (int i = 0; i < 2; i++)
        #pragma unroll
        for (int j = 0; j < 2; j++)
            #pragma unroll
            for (int q = 0; q < 4; q++) accO[i][j][q] = 0.f;

    #pragma unroll 4
    for (int ks = 0; ks < 32; ks++) {
        int k0 = ks * 8;
        uint32_t aP[2][4];
        #pragma unroll
        for (int ma = 0; ma < 2; ma++) {
            int rb = wm * 32 + ma * 16 + g;
            const uint32_t* p1 = (const uint32_t*)(sS + rb * SPAD + k0 + tg);
            aP[ma][0] = p1[0]; aP[ma][1] = p1[8 * SPAD];
            aP[ma][2] = p1[4]; aP[ma][3] = p1[8 * SPAD + 4];
        }
        uint32_t bV[2][2];
        #pragma unroll
        for (int na = 0; na < 2; na++) {
            int cb = wn * 16 + na * 8 + g;
            const uint32_t* q1 = (const uint32_t*)(sVt + cb * SPAD + k0 + tg);
            bV[na][0] = q1[0]; bV[na][1] = q1[4];
        }
        #pragma unroll
        for (int ma = 0; ma < 2; ma++)
            #pragma unroll
            for (int na = 0; na < 2; na++)
                mma_tf32(accO[ma][na][0], accO[ma][na][1],
                         accO[ma][na][2], accO[ma][na][3],
                         aP[ma][0], aP[ma][1], aP[ma][2], aP[ma][3],
                         bV[na][0], bV[na][1]);
    }

    // ---- normalize + residual + store ----
    #pragma unroll
    for (int ma = 0; ma < 2; ma++) {
        #pragma unroll
        for (int h = 0; h < 2; h++) {
            int row = wm * 32 + ma * 16 + g + h * 8;
            int ng  = nt * 64 + row;
            float inv = sInv[row];
            size_t base = ((size_t)bb * NOBJ + ng) * DIM + r * DK;
            #pragma unroll
            for (int na = 0; na < 2; na++) {
                int d = wn * 16 + na * 8 + tg * 2;
                float2 vres = *(const float2*)&vin[base + d];
                float2 o;
                o.x = accO[ma][na][h * 2]     * inv + vres.x;
                o.y = accO[ma][na][h * 2 + 1] * inv + vres.y;
                *(float2*)&out[base + d] = o;
            }
        }
    }
}

// ============================================================
extern "C" void kernel_launch(void* const* d_in, const int* in_sizes, int n_in,
                              void* d_out, int out_size)
{
    const float* v      = (const float*)d_in[0];
    const float* bmat   = (const float*)d_in[1];
    const float* vmask  = (const float*)d_in[2];
    const float* t      = (const float*)d_in[3];
    const float* tmask  = (const float*)d_in[4];
    const float* WG1_w  = (const float*)d_in[5];
    const float* WG1_b  = (const float*)d_in[6];
    const float* WG2_w  = (const float*)d_in[7];
    const float* WG2_b  = (const float*)d_in[8];
    const float* WK_w   = (const float*)d_in[9];
    const float* WK_b   = (const float*)d_in[10];
    const float* WQ_w   = (const float*)d_in[11];
    const float* WQ_b   = (const float*)d_in[12];
    const float* WV_w   = (const float*)d_in[13];
    const float* WV_b   = (const float*)d_in[14];
    const float* tc_w   = (const float*)d_in[15];
    const float* tc_b   = (const float*)d_in[16];
    const float* tmap_w = (const float*)d_in[17];
    const float* tmap_b = (const float*)d_in[18];
    float* out = (float*)d_out;

    cudaFuncSetAttribute(tmap_kernel, cudaFuncAttributeMaxDynamicSharedMemorySize, 131072);
    cudaFuncSetAttribute(attn_kernel, cudaFuncAttributeMaxDynamicSharedMemorySize, ATTN_SMEM);
    cudaFuncSetAttribute(proj_mma_kernel, cudaFuncAttributeMaxDynamicSharedMemorySize, PJ_SMEM);

    tsum_kernel<<<BSZ, 256>>>(t, tmask, tc_w, tc_b);
    tmap_kernel<<<256, 256, 131072>>>(tmap_w, tmap_b);
    proj_mma_kernel<<<dim3(2, 128, 5), 256, PJ_SMEM>>>(
        v, bmat, vmask,
        WG1_w, WG1_b, WG2_w, WG2_b, WK_w, WK_b, WQ_w, WQ_b, WV_w, WV_b);
    attn_kernel<<<dim3(4, RREL, BSZ), 256, ATTN_SMEM>>>(vmask, v, out);
}

// round 8
// speedup vs baseline: 4.3149x; 1.7560x over previous
#include <cuda_runtime.h>
#include <cuda_bf16.h>
#include <math.h>
#include <stdint.h>

#define BSZ   64
#define NOBJ  256
#define TTOK  32
#define DIM   512
#define RREL  8
#define DK    64

#define WSTRIDE (BSZ*RREL*NOBJ*DK)   // 8,388,608 elements per projection

// ---- static device scratch ----
__device__ float g_proj[4ull * WSTRIDE];              // G1,G2,K,Q fp32 [b,r,n,dk]
__device__ __nv_bfloat16 g_vth[1ull * WSTRIDE];       // V^T bf16 [b,r,dk,n]
__device__ float g_tmap[(size_t)BSZ * NOBJ * NOBJ];
__device__ float g_tsum[BSZ * DIM];

__device__ __forceinline__ uint32_t smem_to_u32(const void* smem_ptr) {
    uint32_t addr;
    asm("{ .reg .u64 tmp; cvta.to.shared.u64 tmp, %1; cvt.u32.u64 %0, tmp; }"
        : "=r"(addr) : "l"(smem_ptr));
    return addr;
}

__device__ __forceinline__ void cp_async16(uint32_t dst, const void* src) {
    asm volatile("cp.async.cg.shared.global [%0], [%1], 16;"
                 :: "r"(dst), "l"(src) : "memory");
}
#define CP_COMMIT() asm volatile("cp.async.commit_group;" ::: "memory")
#define CP_WAIT2()  asm volatile("cp.async.wait_group 2;" ::: "memory")

__device__ __forceinline__ void mma_tf32(
    float& d0, float& d1, float& d2, float& d3,
    uint32_t a0, uint32_t a1, uint32_t a2, uint32_t a3,
    uint32_t b0, uint32_t b1)
{
    asm volatile(
        "mma.sync.aligned.m16n8k8.row.col.f32.tf32.tf32.f32 "
        "{%0,%1,%2,%3}, {%4,%5,%6,%7}, {%8,%9}, {%0,%1,%2,%3};"
        : "+f"(d0), "+f"(d1), "+f"(d2), "+f"(d3)
        : "r"(a0), "r"(a1), "r"(a2), "r"(a3), "r"(b0), "r"(b1));
}

__device__ __forceinline__ void mma_bf16(
    float& d0, float& d1, float& d2, float& d3,
    uint32_t a0, uint32_t a1, uint32_t a2, uint32_t a3,
    uint32_t b0, uint32_t b1)
{
    asm volatile(
        "mma.sync.aligned.m16n8k16.row.col.f32.bf16.bf16.f32 "
        "{%0,%1,%2,%3}, {%4,%5,%6,%7}, {%8,%9}, {%0,%1,%2,%3};"
        : "+f"(d0), "+f"(d1), "+f"(d2), "+f"(d3)
        : "r"(a0), "r"(a1), "r"(a2), "r"(a3), "r"(b0), "r"(b1));
}

__device__ __forceinline__ uint32_t pack_bf16(float x, float y) {
    __nv_bfloat162 h = __floats2bfloat162_rn(x, y);
    return *(uint32_t*)&h;
}

// ============================================================
// Kernel 1: text summary  (one block per batch)
// ============================================================
__global__ __launch_bounds__(256) void tsum_kernel(
    const float* __restrict__ t, const float* __restrict__ tmask,
    const float* __restrict__ tcw, const float* __restrict__ tcb)
{
    int bb = blockIdx.x;
    __shared__ float score[TTOK];
    const float* tb = t + (size_t)bb * TTOK * DIM;

    int warp = threadIdx.x >> 5, lane = threadIdx.x & 31;
    for (int tt = warp * 4; tt < warp * 4 + 4; tt++) {
        float s = 0.f;
        for (int d = lane; d < DIM; d += 32) s += tb[tt * DIM + d] * tcw[d];
        #pragma unroll
        for (int o = 16; o > 0; o >>= 1) s += __shfl_xor_sync(0xffffffffu, s, o);
        if (lane == 0) {
            float m = tmask[bb * TTOK + tt];
            if (m == 0.f) {
                score[tt] = 0.f;
            } else {
                float tc = s * m + tcb[0];
                float sg = 1.f / (1.f + expf(-tc));
                score[tt] = sg * m;
            }
        }
    }
    __syncthreads();

    for (int d = threadIdx.x; d < DIM; d += 256) {
        float acc = 0.f;
        #pragma unroll
        for (int tt = 0; tt < TTOK; tt++) acc += tb[tt * DIM + d] * score[tt];
        g_tsum[bb * DIM + d] = acc;
    }
}

// ============================================================
// Kernel 2: tmap = relu(t_summary @ tmap_w + tmap_b)
// tf32 mma GEMM: M=64, N=65536, K=512, cp.async 3-stage
// ============================================================
#define TM_ASTRIDE 36
#define TM_A_FLOATS (64 * TM_ASTRIDE)
#define TM_STAGE_FLOATS (TM_A_FLOATS + 32 * 264)
#define TM_STAGE_BYTES (TM_STAGE_FLOATS * 4)
#define TM_SMEM ((3 * TM_STAGE_FLOATS + 256) * 4)

__global__ __launch_bounds__(256, 1) void tmap_mma_kernel(
    const float* __restrict__ W, const float* __restrict__ bias)
{
    extern __shared__ float smem[];
    uint32_t sbase = smem_to_u32(smem);
    float* sBias = smem + 3 * TM_STAGE_FLOATS;

    int t = threadIdx.x;
    int wid = t >> 5, lane = t & 31;
    int mw = wid >> 2, nw = wid & 3;
    int g = lane >> 2, tg = lane & 3;
    int n0 = blockIdx.x * 256;

    sBias[t] = bias[n0 + t];

    const float* asrc[2]; uint32_t adst[2];
    #pragma unroll
    for (int i = 0; i < 2; i++) {
        int idx = t + i * 256;
        int row = idx >> 3, gc = idx & 7;
        asrc[i] = g_tsum + row * DIM + gc * 4;
        adst[i] = (uint32_t)(row * TM_ASTRIDE + gc * 4) * 4;
    }
    const float* bsrc[8]; uint32_t bdst[8];
    #pragma unroll
    for (int i = 0; i < 8; i++) {
        int idx = t + i * 256;
        int kr = idx >> 6, gc = idx & 63;
        bsrc[i] = W + (size_t)kr * 65536 + n0 + gc * 4;
        bdst[i] = (uint32_t)(TM_A_FLOATS + kr * 264 + gc * 4) * 4;
    }

    #pragma unroll
    for (int c = 0; c < 3; c++) {
        uint32_t sb = sbase + (uint32_t)c * TM_STAGE_BYTES;
        int k0 = c * 32;
        #pragma unroll
        for (int i = 0; i < 2; i++) cp_async16(sb + adst[i], asrc[i] + k0);
        #pragma unroll
        for (int i = 0; i < 8; i++) cp_async16(sb + bdst[i], bsrc[i] + (size_t)k0 * 65536);
        CP_COMMIT();
    }

    float acc[2][8][4];
    #pragma unroll
    for (int i = 0; i < 2; i++)
        #pragma unroll
        for (int j = 0; j < 8; j++)
            #pragma unroll
            for (int q = 0; q < 4; q++) acc[i][j][q] = 0.f;

    for (int c = 0; c < 16; c++) {
        CP_WAIT2();
        __syncthreads();
        const float* sA = smem + (c % 3) * TM_STAGE_FLOATS;
        const float* sB = sA + TM_A_FLOATS;

        #pragma unroll
        for (int ka = 0; ka < 4; ka++) {
            uint32_t af[2][4], bf[4][4];
            #pragma unroll
            for (int ml = 0; ml < 2; ml++) {
                const uint32_t* p0 = (const uint32_t*)(sA
                    + (mw * 32 + ml * 16 + g) * TM_ASTRIDE + ka * 8 + tg);
                af[ml][0] = p0[0];
                af[ml][1] = p0[8 * TM_ASTRIDE];
                af[ml][2] = p0[4];
                af[ml][3] = p0[8 * TM_ASTRIDE + 4];
            }
            #pragma unroll
            for (int pl = 0; pl < 4; pl++) {
                const uint32_t* q0 = (const uint32_t*)(sB
                    + (ka * 8 + tg) * 264 + nw * 64 + pl * 16 + g);
                bf[pl][0] = q0[0];
                bf[pl][1] = q0[4 * 264];
                bf[pl][2] = q0[8];
                bf[pl][3] = q0[4 * 264 + 8];
            }
            #pragma unroll
            for (int ml = 0; ml < 2; ml++) {
                #pragma unroll
                for (int pl = 0; pl < 4; pl++) {
                    mma_tf32(acc[ml][pl*2][0], acc[ml][pl*2][1],
                             acc[ml][pl*2][2], acc[ml][pl*2][3],
                             af[ml][0], af[ml][1], af[ml][2], af[ml][3],
                             bf[pl][0], bf[pl][1]);
                    mma_tf32(acc[ml][pl*2+1][0], acc[ml][pl*2+1][1],
                             acc[ml][pl*2+1][2], acc[ml][pl*2+1][3],
                             af[ml][0], af[ml][1], af[ml][2], af[ml][3],
                             bf[pl][2], bf[pl][3]);
                }
            }
        }
        __syncthreads();

        if (c + 3 < 16) {
            int cc = c + 3;
            uint32_t sb = sbase + (uint32_t)(cc % 3) * TM_STAGE_BYTES;
            int k0 = cc * 32;
            #pragma unroll
            for (int i = 0; i < 2; i++) cp_async16(sb + adst[i], asrc[i] + k0);
            #pragma unroll
            for (int i = 0; i < 8; i++) cp_async16(sb + bdst[i], bsrc[i] + (size_t)k0 * 65536);
            CP_COMMIT();
        }
    }

    #pragma unroll
    for (int ml = 0; ml < 2; ml++) {
        int gm0 = mw * 32 + ml * 16 + g;
        int gm1 = gm0 + 8;
        #pragma unroll
        for (int nl = 0; nl < 8; nl++) {
            int cl = (nw * 8 + nl) * 8 + tg * 2;
            float b0 = sBias[cl], b1 = sBias[cl + 1];
            float2 v0, v1;
            v0.x = fmaxf(acc[ml][nl][0] + b0, 0.f);
            v0.y = fmaxf(acc[ml][nl][1] + b1, 0.f);
            v1.x = fmaxf(acc[ml][nl][2] + b0, 0.f);
            v1.y = fmaxf(acc[ml][nl][3] + b1, 0.f);
            *(float2*)&g_tmap[(size_t)gm0 * 65536 + n0 + cl] = v0;
            *(float2*)&g_tmap[(size_t)gm1 * 65536 + n0 + cl] = v1;
        }
    }
}

// ============================================================
// Kernel 3: 5 projections via mma.sync tf32, cp.async 3-stage pipeline
// G1,G2,K,Q -> g_proj fp32 [b,r,n,dk];  V -> g_vth bf16 [b,r,dk,n]
// ============================================================
#define PJ_ASTRIDE 36
#define PJ_BSTRIDE 264
#define PJ_A_FLOATS (128 * PJ_ASTRIDE)
#define PJ_STAGE_FLOATS (PJ_A_FLOATS + 32 * PJ_BSTRIDE)
#define PJ_STAGE_BYTES (PJ_STAGE_FLOATS * 4)
#define PJ_SMEM ((3 * PJ_STAGE_FLOATS + 256) * 4)

__global__ __launch_bounds__(256, 1) void proj_mma_kernel(
    const float* __restrict__ vin, const float* __restrict__ bmat,
    const float* __restrict__ vmask,
    const float* __restrict__ W0, const float* __restrict__ B0,
    const float* __restrict__ W1, const float* __restrict__ B1,
    const float* __restrict__ W2, const float* __restrict__ B2,
    const float* __restrict__ W3, const float* __restrict__ B3,
    const float* __restrict__ W4, const float* __restrict__ B4)
{
    extern __shared__ float smem[];
    uint32_t sbase = smem_to_u32(smem);
    float* sBias = smem + 3 * PJ_STAGE_FLOATS;

    int t = threadIdx.x;
    int wid = t >> 5, lane = t & 31;
    int mw = wid >> 2, nw = wid & 3;
    int g = lane >> 2, tg = lane & 3;

    int w  = blockIdx.z;
    int m0 = blockIdx.y * 128;
    int n0 = blockIdx.x * 256;

    const float* X = (w < 2) ? bmat : vin;
    const float* Wm; const float* Bv;
    switch (w) {
        case 0: Wm = W0; Bv = B0; break;
        case 1: Wm = W1; Bv = B1; break;
        case 2: Wm = W2; Bv = B2; break;
        case 3: Wm = W3; Bv = B3; break;
        default: Wm = W4; Bv = B4; break;
    }

    sBias[t] = Bv[n0 + t];

    const float* asrc[4]; uint32_t adst[4];
    #pragma unroll
    for (int i = 0; i < 4; i++) {
        int idx = t + i * 256;
        int row = idx >> 3, gc = idx & 7;
        asrc[i] = X + (size_t)(m0 + row) * DIM + gc * 4;
        adst[i] = (uint32_t)(row * PJ_ASTRIDE + gc * 4) * 4;
    }
    const float* bsrc[8]; uint32_t bdst[8];
    #pragma unroll
    for (int i = 0; i < 8; i++) {
        int idx = t + i * 256;
        int kr = idx >> 6, gc = idx & 63;
        bsrc[i] = Wm + (size_t)kr * DIM + n0 + gc * 4;
        bdst[i] = (uint32_t)(PJ_A_FLOATS + kr * PJ_BSTRIDE + gc * 4) * 4;
    }

    #pragma unroll
    for (int c = 0; c < 3; c++) {
        uint32_t sb = sbase + (uint32_t)c * PJ_STAGE_BYTES;
        int k0 = c * 32;
        #pragma unroll
        for (int i = 0; i < 4; i++) cp_async16(sb + adst[i], asrc[i] + k0);
        #pragma unroll
        for (int i = 0; i < 8; i++) cp_async16(sb + bdst[i], bsrc[i] + (size_t)k0 * DIM);
        CP_COMMIT();
    }

    float acc[4][8][4];
    #pragma unroll
    for (int i = 0; i < 4; i++)
        #pragma unroll
        for (int j = 0; j < 8; j++)
            #pragma unroll
            for (int q = 0; q < 4; q++) acc[i][j][q] = 0.f;

    for (int c = 0; c < 16; c++) {
        CP_WAIT2();
        __syncthreads();
        const float* sA = smem + (c % 3) * PJ_STAGE_FLOATS;
        const float* sB = sA + PJ_A_FLOATS;

        #pragma unroll
        for (int ka = 0; ka < 4; ka++) {
            uint32_t af[4][4], bf[4][4];
            #pragma unroll
            for (int ml = 0; ml < 4; ml++) {
                const uint32_t* p0 = (const uint32_t*)(sA
                    + (mw * 64 + ml * 16 + g) * PJ_ASTRIDE + ka * 8 + tg);
                af[ml][0] = p0[0];
                af[ml][1] = p0[8 * PJ_ASTRIDE];
                af[ml][2] = p0[4];
                af[ml][3] = p0[8 * PJ_ASTRIDE + 4];
            }
            #pragma unroll
            for (int pl = 0; pl < 4; pl++) {
                const uint32_t* q0 = (const uint32_t*)(sB
                    + (ka * 8 + tg) * PJ_BSTRIDE + nw * 64 + pl * 16 + g);
                bf[pl][0] = q0[0];
                bf[pl][1] = q0[4 * PJ_BSTRIDE];
                bf[pl][2] = q0[8];
                bf[pl][3] = q0[4 * PJ_BSTRIDE + 8];
            }
            #pragma unroll
            for (int ml = 0; ml < 4; ml++) {
                #pragma unroll
                for (int pl = 0; pl < 4; pl++) {
                    mma_tf32(acc[ml][pl*2][0], acc[ml][pl*2][1],
                             acc[ml][pl*2][2], acc[ml][pl*2][3],
                             af[ml][0], af[ml][1], af[ml][2], af[ml][3],
                             bf[pl][0], bf[pl][1]);
                    mma_tf32(acc[ml][pl*2+1][0], acc[ml][pl*2+1][1],
                             acc[ml][pl*2+1][2], acc[ml][pl*2+1][3],
                             af[ml][0], af[ml][1], af[ml][2], af[ml][3],
                             bf[pl][2], bf[pl][3]);
                }
            }
        }
        __syncthreads();

        if (c + 3 < 16) {
            int cc = c + 3;
            uint32_t sb = sbase + (uint32_t)(cc % 3) * PJ_STAGE_BYTES;
            int k0 = cc * 32;
            #pragma unroll
            for (int i = 0; i < 4; i++) cp_async16(sb + adst[i], asrc[i] + k0);
            #pragma unroll
            for (int i = 0; i < 8; i++) cp_async16(sb + bdst[i], bsrc[i] + (size_t)k0 * DIM);
            CP_COMMIT();
        }
    }

    // ---- epilogue ----
    #pragma unroll
    for (int ml = 0; ml < 4; ml++) {
        int gm0 = m0 + mw * 64 + ml * 16 + g;
        int gm1 = gm0 + 8;
        float msk0 = (w < 2) ? vmask[gm0] : 1.0f;
        float msk1 = (w < 2) ? vmask[gm1] : 1.0f;
        int bbi = gm0 >> 8;
        int nn0 = gm0 & 255, nn1 = gm1 & 255;
        #pragma unroll
        for (int nl = 0; nl < 8; nl++) {
            int cl = (nw * 8 + nl) * 8 + tg * 2;
            int cg = n0 + cl;
            int rrel = cg >> 6, d = cg & 63;
            float b0 = sBias[cl], b1 = sBias[cl + 1];
            float x0 = (acc[ml][nl][0] + b0) * msk0;
            float y0 = (acc[ml][nl][1] + b1) * msk0;
            float x1 = (acc[ml][nl][2] + b0) * msk1;
            float y1 = (acc[ml][nl][3] + b1) * msk1;
            if (w < 4) {
                float* Pout = g_proj + (size_t)w * WSTRIDE;
                float2 v0 = {x0, y0}, v1 = {x1, y1};
                *(float2*)&Pout[((size_t)(bbi * RREL + rrel) * NOBJ + nn0) * DK + d] = v0;
                *(float2*)&Pout[((size_t)(bbi * RREL + rrel) * NOBJ + nn1) * DK + d] = v1;
            } else {
                size_t vb = (size_t)(bbi * RREL + rrel) * DK;
                g_vth[(vb + d)     * NOBJ + nn0] = __float2bfloat16(x0);
                g_vth[(vb + d + 1) * NOBJ + nn0] = __float2bfloat16(y0);
                g_vth[(vb + d)     * NOBJ + nn1] = __float2bfloat16(x1);
                g_vth[(vb + d + 1) * NOBJ + nn1] = __float2bfloat16(y1);
            }
        }
    }
}

// ============================================================
// Kernel 4: fused attention — tf32 scores + bf16 PV, 2 blocks/SM
// smem: 4 fp32 tiles [64][68] (69.6 KB), S bf16 [64][264] (33 KB),
//       Vt bf16 overlays score tiles, inv fp32[64].  total 101.25 KB
// ============================================================
#define TPAD 68
#define TILE_F (64 * TPAD)               // floats per tile
#define SPH   264                        // bf16 S/Vt row stride
#define SS_B  (4 * TILE_F * 4)           // 69632 (byte offset of S)
#define INV_B (SS_B + 64 * SPH * 2)      // 103424
#define ATTN_SMEM (INV_B + 256)          // 103680

__device__ __forceinline__ void tile_ldg(float4* r, const float* __restrict__ src)
{
    int t = threadIdx.x;
    #pragma unroll
    for (int p = 0; p < 4; p++) {
        int idx = (t + p * 256) * 4;
        int row = idx >> 6, k = idx & 63;
        r[p] = *(const float4*)(src + row * 64 + k);
    }
}

__device__ __forceinline__ void tile_sts_rows(float* dst, const float4* r)
{
    int t = threadIdx.x;
    #pragma unroll
    for (int p = 0; p < 4; p++) {
        int idx = (t + p * 256) * 4;
        int row = idx >> 6, k = idx & 63;
        *(float4*)(dst + row * TPAD + k) = r[p];
    }
}

__global__ __launch_bounds__(256, 2) void attn_kernel(
    const float* __restrict__ vmask, const float* __restrict__ vin,
    float* __restrict__ out)
{
    extern __shared__ char smc[];
    float* sG1 = (float*)(smc);
    float* sK  = (float*)(smc + TILE_F * 4);
    float* sX  = (float*)(smc + 2 * TILE_F * 4);
    float* sY  = (float*)(smc + 3 * TILE_F * 4);
    uint16_t* sVt = (uint16_t*)(smc);            // overlay (PV phase)
    uint16_t* sSb = (uint16_t*)(smc + SS_B);
    float*    sInv = (float*)(smc + INV_B);

    int nt = blockIdx.x, r = blockIdx.y, bb = blockIdx.z;
    int t  = threadIdx.x;
    int wid = t >> 5, lane = t & 31;
    int g = lane >> 2, tg = lane & 3;
    int wm = wid >> 2, wn = wid & 3;

    size_t pbase = (size_t)(bb * RREL + r) * NOBJ * DK;
    const float* G1 = g_proj + 0ull * WSTRIDE + pbase;
    const float* G2 = g_proj + 1ull * WSTRIDE + pbase;
    const float* Kp = g_proj + 2ull * WSTRIDE + pbase;
    const float* Qp = g_proj + 3ull * WSTRIDE + pbase;
    const __nv_bfloat16* Vth = g_vth + pbase;    // [dk][n]

    {
        float4 rg[4], rk[4];
        tile_ldg(rg, G1 + nt * 64 * DK);
        tile_ldg(rk, Kp + nt * 64 * DK);
        tile_sts_rows(sG1, rg);
        tile_sts_rows(sK, rk);
    }

    const float* tmrow = g_tmap + ((size_t)bb * NOBJ * NOBJ);

    float4 px[4], py[4];
    tile_ldg(px, G2);
    tile_ldg(py, Qp);

    // ---- score phase (tf32) ----
    for (int mt = 0; mt < 4; mt++) {
        tile_sts_rows(sX, px);
        tile_sts_rows(sY, py);
        __syncthreads();

        if (mt < 3) {
            tile_ldg(px, G2 + (mt + 1) * 64 * DK);
            tile_ldg(py, Qp + (mt + 1) * 64 * DK);
        }

        float accG[2][2][4], accS[2][2][4];
        #pragma unroll
        for (int i = 0; i < 2; i++)
            #pragma unroll
            for (int j = 0; j < 2; j++)
                #pragma unroll
                for (int q = 0; q < 4; q++) { accG[i][j][q] = 0.f; accS[i][j][q] = 0.f; }

        #pragma unroll
        for (int ks = 0; ks < 8; ks++) {
            int k0 = ks * 8;
            uint32_t aG[2][4], aK[2][4];
            #pragma unroll
            for (int ma = 0; ma < 2; ma++) {
                int rb = wm * 32 + ma * 16 + g;
                const uint32_t* p1 = (const uint32_t*)(sG1 + rb * TPAD + k0 + tg);
                aG[ma][0] = p1[0]; aG[ma][1] = p1[8 * TPAD];
                aG[ma][2] = p1[4]; aG[ma][3] = p1[8 * TPAD + 4];
                const uint32_t* p2 = (const uint32_t*)(sK + rb * TPAD + k0 + tg);
                aK[ma][0] = p2[0]; aK[ma][1] = p2[8 * TPAD];
                aK[ma][2] = p2[4]; aK[ma][3] = p2[8 * TPAD + 4];
            }
            uint32_t bX[2][2], bY[2][2];
            #pragma unroll
            for (int na = 0; na < 2; na++) {
                int cb = wn * 16 + na * 8 + g;
                const uint32_t* q1 = (const uint32_t*)(sX + cb * TPAD + k0 + tg);
                bX[na][0] = q1[0]; bX[na][1] = q1[4];
                const uint32_t* q2 = (const uint32_t*)(sY + cb * TPAD + k0 + tg);
                bY[na][0] = q2[0]; bY[na][1] = q2[4];
            }
            #pragma unroll
            for (int ma = 0; ma < 2; ma++)
                #pragma unroll
                for (int na = 0; na < 2; na++) {
                    mma_tf32(accG[ma][na][0], accG[ma][na][1],
                             accG[ma][na][2], accG[ma][na][3],
                             aG[ma][0], aG[ma][1], aG[ma][2], aG[ma][3],
                             bX[na][0], bX[na][1]);
                    mma_tf32(accS[ma][na][0], accS[ma][na][1],
                             accS[ma][na][2], accS[ma][na][3],
                             aK[ma][0], aK[ma][1], aK[ma][2], aK[ma][3],
                             bY[na][0], bY[na][1]);
                }
        }

        // epilogue: relu + tmap + exp + mask -> sSb (bf16 pairs)
        #pragma unroll
        for (int ma = 0; ma < 2; ma++) {
            #pragma unroll
            for (int na = 0; na < 2; na++) {
                int col = wn * 16 + na * 8 + tg * 2;
                int mg  = mt * 64 + col;
                float2 vm = *(const float2*)&vmask[bb * NOBJ + mg];
                #pragma unroll
                for (int h = 0; h < 2; h++) {
                    int row = wm * 32 + ma * 16 + g + h * 8;
                    int ng  = nt * 64 + row;
                    float2 tm = *(const float2*)&tmrow[(size_t)ng * NOBJ + mg];
                    float cG0 = accG[ma][na][h * 2], cG1 = accG[ma][na][h * 2 + 1];
                    float cS0 = accS[ma][na][h * 2], cS1 = accS[ma][na][h * 2 + 1];
                    float wg0 = fmaxf(fmaxf(cG0, 0.f) + tm.x, 1e-6f);
                    float wg1 = fmaxf(fmaxf(cG1, 0.f) + tm.y, 1e-6f);
                    float t0 = wg0 * __expf(fminf(cS0 * 0.125f, 60.f));
                    float t1 = wg1 * __expf(fminf(cS1 * 0.125f, 60.f));
                    if (vm.x == 0.f) t0 = 0.f;
                    if (vm.y == 0.f) t1 = 0.f;
                    *(uint32_t*)(sSb + row * SPH + mg) = pack_bf16(t0, t1);
                }
            }
        }
        __syncthreads();
    }

    // ---- row sums -> 1/sum (fp32 accumulation from bf16 S) ----
    {
        int rrow = t >> 2;
        int lanei = t & 3;
        const uint32_t* rp = (const uint32_t*)(sSb + rrow * SPH);
        float sum = 0.f;
        for (int i = lanei; i < 128; i += 4) {
            __nv_bfloat162 h = *(const __nv_bfloat162*)&rp[i];
            float2 f = __bfloat1622float2(h);
            sum += f.x + f.y;
        }
        sum += __shfl_xor_sync(0xffffffffu, sum, 1);
        sum += __shfl_xor_sync(0xffffffffu, sum, 2);
        if (lanei == 0) sInv[rrow] = 1.f / sum;
    }

    // ---- stage V^T bf16 into overlay (score tiles dead) ----
    #pragma unroll
    for (int p = 0; p < 8; p++) {
        int idx = t + p * 256;               // 0..2047
        int dk = idx >> 5, m16 = (idx & 31) * 8;
        *(uint4*)(sVt + dk * SPH + m16) = *(const uint4*)(Vth + dk * NOBJ + m16);
    }
    __syncthreads();

    // ---- PV via mma bf16 (k16): O = P[64][256] @ V[256][64] ----
    float accO[2][2][4];
    #pragma unroll
    for (int i = 0; i < 2; i++)
        #pragma unroll
        for (int j = 0; j < 2; j++)
            #pragma unroll
            for (int q = 0; q < 4; q++) accO[i][j][q] = 0.f;

    #pragma unroll 4
    for (int ks = 0; ks < 16; ks++) {
        int ko = ks * 16 + tg * 2;
        uint32_t aP[2][4];
        #pragma unroll
        for (int ma = 0; ma < 2; ma++) {
            int rb = wm * 32 + ma * 16 + g;
            const uint16_t* p1 = sSb + rb * SPH + ko;
            aP[ma][0] = *(const uint32_t*)p1;
            aP[ma][1] = *(const uint32_t*)(p1 + 8 * SPH);
            aP[ma][2] = *(const uint32_t*)(p1 + 8);
            aP[ma][3] = *(const uint32_t*)(p1 + 8 * SPH + 8);
        }
        uint32_t bV[2][2];
        #pragma unroll
        for (int na = 0; na < 2; na++) {
            int cb = wn * 16 + na * 8 + g;
            const uint16_t* q1 = sVt + cb * SPH + ko;
            bV[na][0] = *(const uint32_t*)q1;
            bV[na][1] = *(const uint32_t*)(q1 + 8);
        }
        #pragma unroll
        for (int ma = 0; ma < 2; ma++)
            #pragma unroll
            for (int na = 0; na < 2; na++)
                mma_bf16(accO[ma][na][0], accO[ma][na][1],
                         accO[ma][na][2], accO[ma][na][3],
                         aP[ma][0], aP[ma][1], aP[ma][2], aP[ma][3],
                         bV[na][0], bV[na][1]);
    }

    // ---- normalize + residual + store ----
    #pragma unroll
    for (int ma = 0; ma < 2; ma++) {
        #pragma unroll
        for (int h = 0; h < 2; h++) {
            int row = wm * 32 + ma * 16 + g + h * 8;
            int ng  = nt * 64 + row;
            float inv = sInv[row];
            size_t base = ((size_t)bb * NOBJ + ng) * DIM + r * DK;
            #pragma unroll
            for (int na = 0; na < 2; na++) {
                int d = wn * 16 + na * 8 + tg * 2;
                float2 vres = *(const float2*)&vin[base + d];
                float2 o;
                o.x = accO[ma][na][h * 2]     * inv + vres.x;
                o.y = accO[ma][na][h * 2 + 1] * inv + vres.y;
                *(float2*)&out[base + d] = o;
            }
        }
    }
}

// ============================================================
extern "C" void kernel_launch(void* const* d_in, const int* in_sizes, int n_in,
                              void* d_out, int out_size)
{
    const float* v      = (const float*)d_in[0];
    const float* bmat   = (const float*)d_in[1];
    const float* vmask  = (const float*)d_in[2];
    const float* t      = (const float*)d_in[3];
    const float* tmask  = (const float*)d_in[4];
    const float* WG1_w  = (const float*)d_in[5];
    const float* WG1_b  = (const float*)d_in[6];
    const float* WG2_w  = (const float*)d_in[7];
    const float* WG2_b  = (const float*)d_in[8];
    const float* WK_w   = (const float*)d_in[9];
    const float* WK_b   = (const float*)d_in[10];
    const float* WQ_w   = (const float*)d_in[11];
    const float* WQ_b   = (const float*)d_in[12];
    const float* WV_w   = (const float*)d_in[13];
    const float* WV_b   = (const float*)d_in[14];
    const float* tc_w   = (const float*)d_in[15];
    const float* tc_b   = (const float*)d_in[16];
    const float* tmap_w = (const float*)d_in[17];
    const float* tmap_b = (const float*)d_in[18];
    float* out = (float*)d_out;

    cudaFuncSetAttribute(tmap_mma_kernel, cudaFuncAttributeMaxDynamicSharedMemorySize, TM_SMEM);
    cudaFuncSetAttribute(attn_kernel, cudaFuncAttributeMaxDynamicSharedMemorySize, ATTN_SMEM);
    cudaFuncSetAttribute(attn_kernel, cudaFuncAttributePreferredSharedMemoryCarveout, 100);
    cudaFuncSetAttribute(proj_mma_kernel, cudaFuncAttributeMaxDynamicSharedMemorySize, PJ_SMEM);

    tsum_kernel<<<BSZ, 256>>>(t, tmask, tc_w, tc_b);
    tmap_mma_kernel<<<256, 256, TM_SMEM>>>(tmap_w, tmap_b);
    proj_mma_kernel<<<dim3(2, 128, 5), 256, PJ_SMEM>>>(
        v, bmat, vmask,
        WG1_w, WG1_b, WG2_w, WG2_b, WK_w, WK_b, WQ_w, WQ_b, WV_w, WV_b);
    attn_kernel<<<dim3(4, RREL, BSZ), 256, ATTN_SMEM>>>(vmask, v, out);
}

// round 10
// speedup vs baseline: 4.4058x; 1.0211x over previous
#include <cuda_runtime.h>
#include <cuda_fp16.h>
#include <math.h>
#include <stdint.h>

#define BSZ   64
#define NOBJ  256
#define TTOK  32
#define DIM   512
#define RREL  8
#define DK    64

#define WSTRIDE (BSZ*RREL*NOBJ*DK)   // 8,388,608 elements per projection

// ---- static device scratch ----
__device__ float g_proj[4ull * WSTRIDE];     // G1,G2,K,Q fp32 [b,r,n,dk]
__device__ __half g_vth[1ull * WSTRIDE];     // V^T fp16 [b,r,dk,n]
__device__ float g_tmap[(size_t)BSZ * NOBJ * NOBJ];
__device__ float g_tsum[BSZ * DIM];

__device__ __forceinline__ uint32_t smem_to_u32(const void* smem_ptr) {
    uint32_t addr;
    asm("{ .reg .u64 tmp; cvta.to.shared.u64 tmp, %1; cvt.u32.u64 %0, tmp; }"
        : "=r"(addr) : "l"(smem_ptr));
    return addr;
}

__device__ __forceinline__ void cp_async16(uint32_t dst, const void* src) {
    asm volatile("cp.async.cg.shared.global [%0], [%1], 16;"
                 :: "r"(dst), "l"(src) : "memory");
}
#define CP_COMMIT() asm volatile("cp.async.commit_group;" ::: "memory")
#define CP_WAIT2()  asm volatile("cp.async.wait_group 2;" ::: "memory")

__device__ __forceinline__ void mma_tf32(
    float& d0, float& d1, float& d2, float& d3,
    uint32_t a0, uint32_t a1, uint32_t a2, uint32_t a3,
    uint32_t b0, uint32_t b1)
{
    asm volatile(
        "mma.sync.aligned.m16n8k8.row.col.f32.tf32.tf32.f32 "
        "{%0,%1,%2,%3}, {%4,%5,%6,%7}, {%8,%9}, {%0,%1,%2,%3};"
        : "+f"(d0), "+f"(d1), "+f"(d2), "+f"(d3)
        : "r"(a0), "r"(a1), "r"(a2), "r"(a3), "r"(b0), "r"(b1));
}

__device__ __forceinline__ void mma_f16(
    float& d0, float& d1, float& d2, float& d3,
    uint32_t a0, uint32_t a1, uint32_t a2, uint32_t a3,
    uint32_t b0, uint32_t b1)
{
    asm volatile(
        "mma.sync.aligned.m16n8k16.row.col.f32.f16.f16.f32 "
        "{%0,%1,%2,%3}, {%4,%5,%6,%7}, {%8,%9}, {%0,%1,%2,%3};"
        : "+f"(d0), "+f"(d1), "+f"(d2), "+f"(d3)
        : "r"(a0), "r"(a1), "r"(a2), "r"(a3), "r"(b0), "r"(b1));
}

__device__ __forceinline__ uint32_t pack_f16(float x, float y) {
    __half2 h = __floats2half2_rn(x, y);
    return *(uint32_t*)&h;
}

// ============================================================
// Kernel 1: text summary  (one block per batch)
// ============================================================
__global__ __launch_bounds__(256) void tsum_kernel(
    const float* __restrict__ t, const float* __restrict__ tmask,
    const float* __restrict__ tcw, const float* __restrict__ tcb)
{
    int bb = blockIdx.x;
    __shared__ float score[TTOK];
    const float* tb = t + (size_t)bb * TTOK * DIM;

    int warp = threadIdx.x >> 5, lane = threadIdx.x & 31;
    for (int tt = warp * 4; tt < warp * 4 + 4; tt++) {
        float s = 0.f;
        for (int d = lane; d < DIM; d += 32) s += tb[tt * DIM + d] * tcw[d];
        #pragma unroll
        for (int o = 16; o > 0; o >>= 1) s += __shfl_xor_sync(0xffffffffu, s, o);
        if (lane == 0) {
            float m = tmask[bb * TTOK + tt];
            if (m == 0.f) {
                score[tt] = 0.f;
            } else {
                float tc = s * m + tcb[0];
                float sg = 1.f / (1.f + expf(-tc));
                score[tt] = sg * m;
            }
        }
    }
    __syncthreads();

    for (int d = threadIdx.x; d < DIM; d += 256) {
        float acc = 0.f;
        #pragma unroll
        for (int tt = 0; tt < TTOK; tt++) acc += tb[tt * DIM + d] * score[tt];
        g_tsum[bb * DIM + d] = acc;
    }
}

// ============================================================
// tmap body: relu(t_summary @ tmap_w + tmap_b), tf32 mma, cp.async
// M=64, N=256 per call
// ============================================================
#define TM_ASTRIDE 36
#define TM_A_FLOATS (64 * TM_ASTRIDE)
#define TM_STAGE_FLOATS (TM_A_FLOATS + 32 * 264)
#define TM_STAGE_BYTES (TM_STAGE_FLOATS * 4)

__device__ __forceinline__ void tmap_body(
    const float* __restrict__ W, const float* __restrict__ bias,
    int tm_bid, float* smem)
{
    uint32_t sbase = smem_to_u32(smem);
    float* sBias = smem + 3 * TM_STAGE_FLOATS;

    int t = threadIdx.x;
    int wid = t >> 5, lane = t & 31;
    int mw = wid >> 2, nw = wid & 3;
    int g = lane >> 2, tg = lane & 3;
    int n0 = tm_bid * 256;

    sBias[t] = bias[n0 + t];

    const float* asrc[2]; uint32_t adst[2];
    #pragma unroll
    for (int i = 0; i < 2; i++) {
        int idx = t + i * 256;
        int row = idx >> 3, gc = idx & 7;
        asrc[i] = g_tsum + row * DIM + gc * 4;
        adst[i] = (uint32_t)(row * TM_ASTRIDE + gc * 4) * 4;
    }
    const float* bsrc[8]; uint32_t bdst[8];
    #pragma unroll
    for (int i = 0; i < 8; i++) {
        int idx = t + i * 256;
        int kr = idx >> 6, gc = idx & 63;
        bsrc[i] = W + (size_t)kr * 65536 + n0 + gc * 4;
        bdst[i] = (uint32_t)(TM_A_FLOATS + kr * 264 + gc * 4) * 4;
    }

    #pragma unroll
    for (int c = 0; c < 3; c++) {
        uint32_t sb = sbase + (uint32_t)c * TM_STAGE_BYTES;
        int k0 = c * 32;
        #pragma unroll
        for (int i = 0; i < 2; i++) cp_async16(sb + adst[i], asrc[i] + k0);
        #pragma unroll
        for (int i = 0; i < 8; i++) cp_async16(sb + bdst[i], bsrc[i] + (size_t)k0 * 65536);
        CP_COMMIT();
    }

    float acc[2][8][4];
    #pragma unroll
    for (int i = 0; i < 2; i++)
        #pragma unroll
        for (int j = 0; j < 8; j++)
            #pragma unroll
            for (int q = 0; q < 4; q++) acc[i][j][q] = 0.f;

    for (int c = 0; c < 16; c++) {
        CP_WAIT2();
        __syncthreads();
        const float* sA = smem + (c % 3) * TM_STAGE_FLOATS;
        const float* sB = sA + TM_A_FLOATS;

        #pragma unroll
        for (int ka = 0; ka < 4; ka++) {
            uint32_t af[2][4], bf[4][4];
            #pragma unroll
            for (int ml = 0; ml < 2; ml++) {
                const uint32_t* p0 = (const uint32_t*)(sA
                    + (mw * 32 + ml * 16 + g) * TM_ASTRIDE + ka * 8 + tg);
                af[ml][0] = p0[0];
                af[ml][1] = p0[8 * TM_ASTRIDE];
                af[ml][2] = p0[4];
                af[ml][3] = p0[8 * TM_ASTRIDE + 4];
            }
            #pragma unroll
            for (int pl = 0; pl < 4; pl++) {
                const uint32_t* q0 = (const uint32_t*)(sB
                    + (ka * 8 + tg) * 264 + nw * 64 + pl * 16 + g);
                bf[pl][0] = q0[0];
                bf[pl][1] = q0[4 * 264];
                bf[pl][2] = q0[8];
                bf[pl][3] = q0[4 * 264 + 8];
            }
            #pragma unroll
            for (int ml = 0; ml < 2; ml++) {
                #pragma unroll
                for (int pl = 0; pl < 4; pl++) {
                    mma_tf32(acc[ml][pl*2][0], acc[ml][pl*2][1],
                             acc[ml][pl*2][2], acc[ml][pl*2][3],
                             af[ml][0], af[ml][1], af[ml][2], af[ml][3],
                             bf[pl][0], bf[pl][1]);
                    mma_tf32(acc[ml][pl*2+1][0], acc[ml][pl*2+1][1],
                             acc[ml][pl*2+1][2], acc[ml][pl*2+1][3],
                             af[ml][0], af[ml][1], af[ml][2], af[ml][3],
                             bf[pl][2], bf[pl][3]);
                }
            }
        }
        __syncthreads();

        if (c + 3 < 16) {
            int cc = c + 3;
            uint32_t sb = sbase + (uint32_t)(cc % 3) * TM_STAGE_BYTES;
            int k0 = cc * 32;
            #pragma unroll
            for (int i = 0; i < 2; i++) cp_async16(sb + adst[i], asrc[i] + k0);
            #pragma unroll
            for (int i = 0; i < 8; i++) cp_async16(sb + bdst[i], bsrc[i] + (size_t)k0 * 65536);
            CP_COMMIT();
        }
    }

    #pragma unroll
    for (int ml = 0; ml < 2; ml++) {
        int gm0 = mw * 32 + ml * 16 + g;
        int gm1 = gm0 + 8;
        #pragma unroll
        for (int nl = 0; nl < 8; nl++) {
            int cl = (nw * 8 + nl) * 8 + tg * 2;
            float b0 = sBias[cl], b1 = sBias[cl + 1];
            float2 v0, v1;
            v0.x = fmaxf(acc[ml][nl][0] + b0, 0.f);
            v0.y = fmaxf(acc[ml][nl][1] + b1, 0.f);
            v1.x = fmaxf(acc[ml][nl][2] + b0, 0.f);
            v1.y = fmaxf(acc[ml][nl][3] + b1, 0.f);
            *(float2*)&g_tmap[(size_t)gm0 * 65536 + n0 + cl] = v0;
            *(float2*)&g_tmap[(size_t)gm1 * 65536 + n0 + cl] = v1;
        }
    }
}

// ============================================================
// proj body: one 128x256 tile of one of the 5 projections (tf32 mma)
// G1,G2,K,Q -> g_proj fp32; V -> g_vth fp16 [dk][n]
// ============================================================
#define PJ_ASTRIDE 36
#define PJ_BSTRIDE 264
#define PJ_A_FLOATS (128 * PJ_ASTRIDE)
#define PJ_STAGE_FLOATS (PJ_A_FLOATS + 32 * PJ_BSTRIDE)
#define PJ_STAGE_BYTES (PJ_STAGE_FLOATS * 4)
#define PJ_SMEM ((3 * PJ_STAGE_FLOATS + 256) * 4)

__device__ __forceinline__ void proj_body(
    const float* __restrict__ vin, const float* __restrict__ bmat,
    const float* __restrict__ vmask,
    const float* __restrict__ Wm, const float* __restrict__ Bv,
    int w, int nx, int my, float* smem)
{
    uint32_t sbase = smem_to_u32(smem);
    float* sBias = smem + 3 * PJ_STAGE_FLOATS;

    int t = threadIdx.x;
    int wid = t >> 5, lane = t & 31;
    int mw = wid >> 2, nw = wid & 3;
    int g = lane >> 2, tg = lane & 3;

    int m0 = my * 128;
    int n0 = nx * 256;

    const float* X = (w < 2) ? bmat : vin;

    sBias[t] = Bv[n0 + t];

    const float* asrc[4]; uint32_t adst[4];
    #pragma unroll
    for (int i = 0; i < 4; i++) {
        int idx = t + i * 256;
        int row = idx >> 3, gc = idx & 7;
        asrc[i] = X + (size_t)(m0 + row) * DIM + gc * 4;
        adst[i] = (uint32_t)(row * PJ_ASTRIDE + gc * 4) * 4;
    }
    const float* bsrc[8]; uint32_t bdst[8];
    #pragma unroll
    for (int i = 0; i < 8; i++) {
        int idx = t + i * 256;
        int kr = idx >> 6, gc = idx & 63;
        bsrc[i] = Wm + (size_t)kr * DIM + n0 + gc * 4;
        bdst[i] = (uint32_t)(PJ_A_FLOATS + kr * PJ_BSTRIDE + gc * 4) * 4;
    }

    #pragma unroll
    for (int c = 0; c < 3; c++) {
        uint32_t sb = sbase + (uint32_t)c * PJ_STAGE_BYTES;
        int k0 = c * 32;
        #pragma unroll
        for (int i = 0; i < 4; i++) cp_async16(sb + adst[i], asrc[i] + k0);
        #pragma unroll
        for (int i = 0; i < 8; i++) cp_async16(sb + bdst[i], bsrc[i] + (size_t)k0 * DIM);
        CP_COMMIT();
    }

    float acc[4][8][4];
    #pragma unroll
    for (int i = 0; i < 4; i++)
        #pragma unroll
        for (int j = 0; j < 8; j++)
            #pragma unroll
            for (int q = 0; q < 4; q++) acc[i][j][q] = 0.f;

    for (int c = 0; c < 16; c++) {
        CP_WAIT2();
        __syncthreads();
        const float* sA = smem + (c % 3) * PJ_STAGE_FLOATS;
        const float* sB = sA + PJ_A_FLOATS;

        #pragma unroll
        for (int ka = 0; ka < 4; ka++) {
            uint32_t af[4][4], bf[4][4];
            #pragma unroll
            for (int ml = 0; ml < 4; ml++) {
                const uint32_t* p0 = (const uint32_t*)(sA
                    + (mw * 64 + ml * 16 + g) * PJ_ASTRIDE + ka * 8 + tg);
                af[ml][0] = p0[0];
                af[ml][1] = p0[8 * PJ_ASTRIDE];
                af[ml][2] = p0[4];
                af[ml][3] = p0[8 * PJ_ASTRIDE + 4];
            }
            #pragma unroll
            for (int pl = 0; pl < 4; pl++) {
                const uint32_t* q0 = (const uint32_t*)(sB
                    + (ka * 8 + tg) * PJ_BSTRIDE + nw * 64 + pl * 16 + g);
                bf[pl][0] = q0[0];
                bf[pl][1] = q0[4 * PJ_BSTRIDE];
                bf[pl][2] = q0[8];
                bf[pl][3] = q0[4 * PJ_BSTRIDE + 8];
            }
            #pragma unroll
            for (int ml = 0; ml < 4; ml++) {
                #pragma unroll
                for (int pl = 0; pl < 4; pl++) {
                    mma_tf32(acc[ml][pl*2][0], acc[ml][pl*2][1],
                             acc[ml][pl*2][2], acc[ml][pl*2][3],
                             af[ml][0], af[ml][1], af[ml][2], af[ml][3],
                             bf[pl][0], bf[pl][1]);
                    mma_tf32(acc[ml][pl*2+1][0], acc[ml][pl*2+1][1],
                             acc[ml][pl*2+1][2], acc[ml][pl*2+1][3],
                             af[ml][0], af[ml][1], af[ml][2], af[ml][3],
                             bf[pl][2], bf[pl][3]);
                }
            }
        }
        __syncthreads();

        if (c + 3 < 16) {
            int cc = c + 3;
            uint32_t sb = sbase + (uint32_t)(cc % 3) * PJ_STAGE_BYTES;
            int k0 = cc * 32;
            #pragma unroll
            for (int i = 0; i < 4; i++) cp_async16(sb + adst[i], asrc[i] + k0);
            #pragma unroll
            for (int i = 0; i < 8; i++) cp_async16(sb + bdst[i], bsrc[i] + (size_t)k0 * DIM);
            CP_COMMIT();
        }
    }

    // ---- epilogue: bias + mask ----
    #pragma unroll
    for (int ml = 0; ml < 4; ml++) {
        int gm0 = m0 + mw * 64 + ml * 16 + g;
        int gm1 = gm0 + 8;
        float msk0 = (w < 2) ? vmask[gm0] : 1.0f;
        float msk1 = (w < 2) ? vmask[gm1] : 1.0f;
        int bbi = gm0 >> 8;
        int nn0 = gm0 & 255, nn1 = gm1 & 255;
        #pragma unroll
        for (int nl = 0; nl < 8; nl++) {
            int cl = (nw * 8 + nl) * 8 + tg * 2;
            int cg = n0 + cl;
            int rrel = cg >> 6, d = cg & 63;
            float b0 = sBias[cl], b1 = sBias[cl + 1];
            float x0 = (acc[ml][nl][0] + b0) * msk0;
            float y0 = (acc[ml][nl][1] + b1) * msk0;
            float x1 = (acc[ml][nl][2] + b0) * msk1;
            float y1 = (acc[ml][nl][3] + b1) * msk1;
            if (w < 4) {
                float* Pout = g_proj + (size_t)w * WSTRIDE;
                float2 v0 = {x0, y0}, v1 = {x1, y1};
                *(float2*)&Pout[((size_t)(bbi * RREL + rrel) * NOBJ + nn0) * DK + d] = v0;
                *(float2*)&Pout[((size_t)(bbi * RREL + rrel) * NOBJ + nn1) * DK + d] = v1;
            } else {
                size_t vb = (size_t)(bbi * RREL + rrel) * DK;
                g_vth[(vb + d)     * NOBJ + nn0] = __float2half(x0);
                g_vth[(vb + d + 1) * NOBJ + nn0] = __float2half(y0);
                g_vth[(vb + d)     * NOBJ + nn1] = __float2half(x1);
                g_vth[(vb + d + 1) * NOBJ + nn1] = __float2half(y1);
            }
        }
    }
}

// ============================================================
// Fused proj + tmap kernel: 1536 blocks, every 6th is a tmap block
// (interleaves HBM-bound tmap with tensor-bound proj per wave)
// ============================================================
__global__ __launch_bounds__(256, 1) void projtmap_kernel(
    const float* __restrict__ vin, const float* __restrict__ bmat,
    const float* __restrict__ vmask,
    const float* __restrict__ W0, const float* __restrict__ B0,
    const float* __restrict__ W1, const float* __restrict__ B1,
    const float* __restrict__ W2, const float* __restrict__ B2,
    const float* __restrict__ W3, const float* __restrict__ B3,
    const float* __restrict__ W4, const float* __restrict__ B4,
    const float* __restrict__ Wt, const float* __restrict__ Bt)
{
    extern __shared__ float smem[];
    int bid = blockIdx.x;
    if ((bid % 6) == 5) {
        tmap_body(Wt, Bt, bid / 6, smem);
    } else {
        int pid = bid - (bid + 1) / 6;      // 0..1279
        int w   = pid >> 8;
        int rem = pid & 255;
        int my  = rem >> 1;
        int nx  = rem & 1;
        const float* Wm; const float* Bv;
        switch (w) {
            case 0: Wm = W0; Bv = B0; break;
            case 1: Wm = W1; Bv = B1; break;
            case 2: Wm = W2; Bv = B2; break;
            case 3: Wm = W3; Bv = B3; break;
            default: Wm = W4; Bv = B4; break;
        }
        proj_body(vin, bmat, vmask, Wm, Bv, w, nx, my, smem);
    }
}

// ============================================================
// Kernel 4: fused attention — tf32 scores + fp16 (scaled) S + fp16 V
// smem: 4 fp32 tiles [64][68] (69.6 KB), S fp16 [64][264] (33.8 KB),
//       Vt fp16 overlays score tiles, inv fp32[64].  103.7 KB, 2/SM
// ============================================================
#define TPAD 68
#define TILE_F (64 * TPAD)
#define SPH   264
#define SS_B  (4 * TILE_F * 4)           // 69632
#define INV_B (SS_B + 64 * SPH * 2)      // 103424
#define ATTN_SMEM (INV_B + 256)          // 103680
#define S_SCALE 1024.0f

__device__ __forceinline__ void tile_ldg(float4* r, const float* __restrict__ src)
{
    int t = threadIdx.x;
    #pragma unroll
    for (int p = 0; p < 4; p++) {
        int idx = (t + p * 256) * 4;
        int row = idx >> 6, k = idx & 63;
        r[p] = *(const float4*)(src + row * 64 + k);
    }
}

__device__ __forceinline__ void tile_sts_rows(float* dst, const float4* r)
{
    int t = threadIdx.x;
    #pragma unroll
    for (int p = 0; p < 4; p++) {
        int idx = (t + p * 256) * 4;
        int row = idx >> 6, k = idx & 63;
        *(float4*)(dst + row * TPAD + k) = r[p];
    }
}

__global__ __launch_bounds__(256, 2) void attn_kernel(
    const float* __restrict__ vmask, const float* __restrict__ vin,
    float* __restrict__ out)
{
    extern __shared__ char smc[];
    float* sG1 = (float*)(smc);
    float* sK  = (float*)(smc + TILE_F * 4);
    float* sX  = (float*)(smc + 2 * TILE_F * 4);
    float* sY  = (float*)(smc + 3 * TILE_F * 4);
    uint16_t* sVt = (uint16_t*)(smc);            // overlay (PV phase)
    uint16_t* sSb = (uint16_t*)(smc + SS_B);
    float*    sInv = (float*)(smc + INV_B);

    int nt = blockIdx.x, r = blockIdx.y, bb = blockIdx.z;
    int t  = threadIdx.x;
    int wid = t >> 5, lane = t & 31;
    int g = lane >> 2, tg = lane & 3;
    int wm = wid >> 2, wn = wid & 3;

    size_t pbase = (size_t)(bb * RREL + r) * NOBJ * DK;
    const float* G1 = g_proj + 0ull * WSTRIDE + pbase;
    const float* G2 = g_proj + 1ull * WSTRIDE + pbase;
    const float* Kp = g_proj + 2ull * WSTRIDE + pbase;
    const float* Qp = g_proj + 3ull * WSTRIDE + pbase;
    const __half* Vth = g_vth + pbase;           // [dk][n]

    {
        float4 rg[4], rk[4];
        tile_ldg(rg, G1 + nt * 64 * DK);
        tile_ldg(rk, Kp + nt * 64 * DK);
        tile_sts_rows(sG1, rg);
        tile_sts_rows(sK, rk);
    }

    const float* tmrow = g_tmap + ((size_t)bb * NOBJ * NOBJ);

    float4 px[4], py[4];
    tile_ldg(px, G2);
    tile_ldg(py, Qp);

    // ---- score phase (tf32) ----
    for (int mt = 0; mt < 4; mt++) {
        tile_sts_rows(sX, px);
        tile_sts_rows(sY, py);
        __syncthreads();

        if (mt < 3) {
            tile_ldg(px, G2 + (mt + 1) * 64 * DK);
            tile_ldg(py, Qp + (mt + 1) * 64 * DK);
        }

        float accG[2][2][4], accS[2][2][4];
        #pragma unroll
        for (int i = 0; i < 2; i++)
            #pragma unroll
            for (int j = 0; j < 2; j++)
                #pragma unroll
                for (int q = 0; q < 4; q++) { accG[i][j][q] = 0.f; accS[i][j][q] = 0.f; }

        #pragma unroll
        for (int ks = 0; ks < 8; ks++) {
            int k0 = ks * 8;
            uint32_t aG[2][4], aK[2][4];
            #pragma unroll
            for (int ma = 0; ma < 2; ma++) {
                int rb = wm * 32 + ma * 16 + g;
                const uint32_t* p1 = (const uint32_t*)(sG1 + rb * TPAD + k0 + tg);
                aG[ma][0] = p1[0]; aG[ma][1] = p1[8 * TPAD];
                aG[ma][2] = p1[4]; aG[ma][3] = p1[8 * TPAD + 4];
                const uint32_t* p2 = (const uint32_t*)(sK + rb * TPAD + k0 + tg);
                aK[ma][0] = p2[0]; aK[ma][1] = p2[8 * TPAD];
                aK[ma][2] = p2[4]; aK[ma][3] = p2[8 * TPAD + 4];
            }
            uint32_t bX[2][2], bY[2][2];
            #pragma unroll
            for (int na = 0; na < 2; na++) {
                int cb = wn * 16 + na * 8 + g;
                const uint32_t* q1 = (const uint32_t*)(sX + cb * TPAD + k0 + tg);
                bX[na][0] = q1[0]; bX[na][1] = q1[4];
                const uint32_t* q2 = (const uint32_t*)(sY + cb * TPAD + k0 + tg);
                bY[na][0] = q2[0]; bY[na][1] = q2[4];
            }
            #pragma unroll
            for (int ma = 0; ma < 2; ma++)
                #pragma unroll
                for (int na = 0; na < 2; na++) {
                    mma_tf32(accG[ma][na][0], accG[ma][na][1],
                             accG[ma][na][2], accG[ma][na][3],
                             aG[ma][0], aG[ma][1], aG[ma][2], aG[ma][3],
                             bX[na][0], bX[na][1]);
                    mma_tf32(accS[ma][na][0], accS[ma][na][1],
                             accS[ma][na][2], accS[ma][na][3],
                             aK[ma][0], aK[ma][1], aK[ma][2], aK[ma][3],
                             bY[na][0], bY[na][1]);
                }
        }

        // epilogue: relu + tmap + exp + mask -> sSb (fp16 pairs, scaled)
        #pragma unroll
        for (int ma = 0; ma < 2; ma++) {
            #pragma unroll
            for (int na = 0; na < 2; na++) {
                int col = wn * 16 + na * 8 + tg * 2;
                int mg  = mt * 64 + col;
                float2 vm = *(const float2*)&vmask[bb * NOBJ + mg];
                #pragma unroll
                for (int h = 0; h < 2; h++) {
                    int row = wm * 32 + ma * 16 + g + h * 8;
                    int ng  = nt * 64 + row;
                    float2 tm = *(const float2*)&tmrow[(size_t)ng * NOBJ + mg];
                    float cG0 = accG[ma][na][h * 2], cG1 = accG[ma][na][h * 2 + 1];
                    float cS0 = accS[ma][na][h * 2], cS1 = accS[ma][na][h * 2 + 1];
                    float wg0 = fmaxf(fmaxf(cG0, 0.f) + tm.x, 1e-6f);
                    float wg1 = fmaxf(fmaxf(cG1, 0.f) + tm.y, 1e-6f);
                    float t0 = wg0 * __expf(fminf(cS0 * 0.125f, 8.f)) * S_SCALE;
                    float t1 = wg1 * __expf(fminf(cS1 * 0.125f, 8.f)) * S_SCALE;
                    t0 = fminf(t0, 60000.f);
                    t1 = fminf(t1, 60000.f);
                    if (vm.x == 0.f) t0 = 0.f;
                    if (vm.y == 0.f) t1 = 0.f;
                    *(uint32_t*)(sSb + row * SPH + mg) = pack_f16(t0, t1);
                }
            }
        }
        __syncthreads();
    }

    // ---- row sums -> 1/sum (fp32 accumulation; scale cancels) ----
    {
        int rrow = t >> 2;
        int lanei = t & 3;
        const uint32_t* rp = (const uint32_t*)(sSb + rrow * SPH);
        float sum = 0.f;
        for (int i = lanei; i < 128; i += 4) {
            __half2 h = *(const __half2*)&rp[i];
            float2 f = __half22float2(h);
            sum += f.x + f.y;
        }
        sum += __shfl_xor_sync(0xffffffffu, sum, 1);
        sum += __shfl_xor_sync(0xffffffffu, sum, 2);
        if (lanei == 0) sInv[rrow] = 1.f / fmaxf(sum, 1e-30f);
    }

    // ---- stage V^T fp16 into overlay (score tiles dead) ----
    #pragma unroll
    for (int p = 0; p < 8; p++) {
        int idx = t + p * 256;               // 0..2047
        int dk = idx >> 5, m16 = (idx & 31) * 8;
        *(uint4*)(sVt + dk * SPH + m16) = *(const uint4*)(Vth + dk * NOBJ + m16);
    }
    __syncthreads();

    // ---- PV via fp16 mma (k16): O = P[64][256] @ V[256][64] ----
    float accO[2][2][4];
    #pragma unroll
    for (int i = 0; i < 2; i++)
        #pragma unroll
        for (int j = 0; j < 2; j++)
            #pragma unroll
            for (int q = 0; q < 4; q++) accO[i][j][q] = 0.f;

    #pragma unroll 4
    for (int ks = 0; ks < 16; ks++) {
        int ko = ks * 16 + tg * 2;
        uint32_t aP[2][4];
        #pragma unroll
        for (int ma = 0; ma < 2; ma++) {
            int rb = wm * 32 + ma * 16 + g;
            const uint16_t* p1 = sSb + rb * SPH + ko;
            aP[ma][0] = *(const uint32_t*)p1;
            aP[ma][1] = *(const uint32_t*)(p1 + 8 * SPH);
            aP[ma][2] = *(const uint32_t*)(p1 + 8);
            aP[ma][3] = *(const uint32_t*)(p1 + 8 * SPH + 8);
        }
        uint32_t bV[2][2];
        #pragma unroll
        for (int na = 0; na < 2; na++) {
            int cb = wn * 16 + na * 8 + g;
            const uint16_t* q1 = sVt + cb * SPH + ko;
            bV[na][0] = *(const uint32_t*)q1;
            bV[na][1] = *(const uint32_t*)(q1 + 8);
        }
        #pragma unroll
        for (int ma = 0; ma < 2; ma++)
            #pragma unroll
            for (int na = 0; na < 2; na++)
                mma_f16(accO[ma][na][0], accO[ma][na][1],
                        accO[ma][na][2], accO[ma][na][3],
                        aP[ma][0], aP[ma][1], aP[ma][2], aP[ma][3],
                        bV[na][0], bV[na][1]);
    }

    // ---- normalize + residual + store ----
    #pragma unroll
    for (int ma = 0; ma < 2; ma++) {
        #pragma unroll
        for (int h = 0; h < 2; h++) {
            int row = wm * 32 + ma * 16 + g + h * 8;
            int ng  = nt * 64 + row;
            float inv = sInv[row];
            size_t base = ((size_t)bb * NOBJ + ng) * DIM + r * DK;
            #pragma unroll
            for (int na = 0; na < 2; na++) {
                int d = wn * 16 + na * 8 + tg * 2;
                float2 vres = *(const float2*)&vin[base + d];
                float2 o;
                o.x = accO[ma][na][h * 2]     * inv + vres.x;
                o.y = accO[ma][na][h * 2 + 1] * inv + vres.y;
                *(float2*)&out[base + d] = o;
            }
        }
    }
}

// ============================================================
extern "C" void kernel_launch(void* const* d_in, const int* in_sizes, int n_in,
                              void* d_out, int out_size)
{
    const float* v      = (const float*)d_in[0];
    const float* bmat   = (const float*)d_in[1];
    const float* vmask  = (const float*)d_in[2];
    const float* t      = (const float*)d_in[3];
    const float* tmask  = (const float*)d_in[4];
    const float* WG1_w  = (const float*)d_in[5];
    const float* WG1_b  = (const float*)d_in[6];
    const float* WG2_w  = (const float*)d_in[7];
    const float* WG2_b  = (const float*)d_in[8];
    const float* WK_w   = (const float*)d_in[9];
    const float* WK_b   = (const float*)d_in[10];
    const float* WQ_w   = (const float*)d_in[11];
    const float* WQ_b   = (const float*)d_in[12];
    const float* WV_w   = (const float*)d_in[13];
    const float* WV_b   = (const float*)d_in[14];
    const float* tc_w   = (const float*)d_in[15];
    const float* tc_b   = (const float*)d_in[16];
    const float* tmap_w = (const float*)d_in[17];
    const float* tmap_b = (const float*)d_in[18];
    float* out = (float*)d_out;

    cudaFuncSetAttribute(projtmap_kernel, cudaFuncAttributeMaxDynamicSharedMemorySize, PJ_SMEM);
    cudaFuncSetAttribute(attn_kernel, cudaFuncAttributeMaxDynamicSharedMemorySize, ATTN_SMEM);
    cudaFuncSetAttribute(attn_kernel, cudaFuncAttributePreferredSharedMemoryCarveout, 100);

    tsum_kernel<<<BSZ, 256>>>(t, tmask, tc_w, tc_b);
    projtmap_kernel<<<1536, 256, PJ_SMEM>>>(
        v, bmat, vmask,
        WG1_w, WG1_b, WG2_w, WG2_b, WK_w, WK_b, WQ_w, WQ_b, WV_w, WV_b,
        tmap_w, tmap_b);
    attn_kernel<<<dim3(4, RREL, BSZ), 256, ATTN_SMEM>>>(vmask, v, out);
}

// round 11
// speedup vs baseline: 4.9189x; 1.1164x over previous
#include <cuda_runtime.h>
#include <cuda_fp16.h>
#include <math.h>
#include <stdint.h>

#define BSZ   64
#define NOBJ  256
#define TTOK  32
#define DIM   512
#define RREL  8
#define DK    64

#define WSTRIDE (BSZ*RREL*NOBJ*DK)   // 8,388,608 elements per projection

// ---- static device scratch ----
__device__ __half g_projh[4ull * WSTRIDE];   // G1,G2,K,Q fp16 [b,r,n,dk]
__device__ __half g_vth[1ull * WSTRIDE];     // V^T fp16 [b,r,dk,n]
__device__ float g_tmap[(size_t)BSZ * NOBJ * NOBJ];
__device__ float g_tsum[BSZ * DIM];

__device__ __forceinline__ uint32_t smem_to_u32(const void* smem_ptr) {
    uint32_t addr;
    asm("{ .reg .u64 tmp; cvta.to.shared.u64 tmp, %1; cvt.u32.u64 %0, tmp; }"
        : "=r"(addr) : "l"(smem_ptr));
    return addr;
}

__device__ __forceinline__ void cp_async16(uint32_t dst, const void* src) {
    asm volatile("cp.async.cg.shared.global [%0], [%1], 16;"
                 :: "r"(dst), "l"(src) : "memory");
}
#define CP_COMMIT() asm volatile("cp.async.commit_group;" ::: "memory")
#define CP_WAIT2()  asm volatile("cp.async.wait_group 2;" ::: "memory")

__device__ __forceinline__ void mma_tf32(
    float& d0, float& d1, float& d2, float& d3,
    uint32_t a0, uint32_t a1, uint32_t a2, uint32_t a3,
    uint32_t b0, uint32_t b1)
{
    asm volatile(
        "mma.sync.aligned.m16n8k8.row.col.f32.tf32.tf32.f32 "
        "{%0,%1,%2,%3}, {%4,%5,%6,%7}, {%8,%9}, {%0,%1,%2,%3};"
        : "+f"(d0), "+f"(d1), "+f"(d2), "+f"(d3)
        : "r"(a0), "r"(a1), "r"(a2), "r"(a3), "r"(b0), "r"(b1));
}

__device__ __forceinline__ void mma_f16(
    float& d0, float& d1, float& d2, float& d3,
    uint32_t a0, uint32_t a1, uint32_t a2, uint32_t a3,
    uint32_t b0, uint32_t b1)
{
    asm volatile(
        "mma.sync.aligned.m16n8k16.row.col.f32.f16.f16.f32 "
        "{%0,%1,%2,%3}, {%4,%5,%6,%7}, {%8,%9}, {%0,%1,%2,%3};"
        : "+f"(d0), "+f"(d1), "+f"(d2), "+f"(d3)
        : "r"(a0), "r"(a1), "r"(a2), "r"(a3), "r"(b0), "r"(b1));
}

__device__ __forceinline__ uint32_t pack_f16(float x, float y) {
    __half2 h = __floats2half2_rn(x, y);
    return *(uint32_t*)&h;
}

// ============================================================
// Kernel 1: text summary  (one block per batch)
// ============================================================
__global__ __launch_bounds__(256) void tsum_kernel(
    const float* __restrict__ t, const float* __restrict__ tmask,
    const float* __restrict__ tcw, const float* __restrict__ tcb)
{
    int bb = blockIdx.x;
    __shared__ float score[TTOK];
    const float* tb = t + (size_t)bb * TTOK * DIM;

    int warp = threadIdx.x >> 5, lane = threadIdx.x & 31;
    for (int tt = warp * 4; tt < warp * 4 + 4; tt++) {
        float s = 0.f;
        for (int d = lane; d < DIM; d += 32) s += tb[tt * DIM + d] * tcw[d];
        #pragma unroll
        for (int o = 16; o > 0; o >>= 1) s += __shfl_xor_sync(0xffffffffu, s, o);
        if (lane == 0) {
            float m = tmask[bb * TTOK + tt];
            if (m == 0.f) {
                score[tt] = 0.f;
            } else {
                float tc = s * m + tcb[0];
                float sg = 1.f / (1.f + expf(-tc));
                score[tt] = sg * m;
            }
        }
    }
    __syncthreads();

    for (int d = threadIdx.x; d < DIM; d += 256) {
        float acc = 0.f;
        #pragma unroll
        for (int tt = 0; tt < TTOK; tt++) acc += tb[tt * DIM + d] * score[tt];
        g_tsum[bb * DIM + d] = acc;
    }
}

// ============================================================
// tmap body: relu(t_summary @ tmap_w + tmap_b), tf32 mma, cp.async
// ============================================================
#define TM_ASTRIDE 36
#define TM_A_FLOATS (64 * TM_ASTRIDE)
#define TM_STAGE_FLOATS (TM_A_FLOATS + 32 * 264)
#define TM_STAGE_BYTES (TM_STAGE_FLOATS * 4)

__device__ __forceinline__ void tmap_body(
    const float* __restrict__ W, const float* __restrict__ bias,
    int tm_bid, float* smem)
{
    uint32_t sbase = smem_to_u32(smem);
    float* sBias = smem + 3 * TM_STAGE_FLOATS;

    int t = threadIdx.x;
    int wid = t >> 5, lane = t & 31;
    int mw = wid >> 2, nw = wid & 3;
    int g = lane >> 2, tg = lane & 3;
    int n0 = tm_bid * 256;

    sBias[t] = bias[n0 + t];

    const float* asrc[2]; uint32_t adst[2];
    #pragma unroll
    for (int i = 0; i < 2; i++) {
        int idx = t + i * 256;
        int row = idx >> 3, gc = idx & 7;
        asrc[i] = g_tsum + row * DIM + gc * 4;
        adst[i] = (uint32_t)(row * TM_ASTRIDE + gc * 4) * 4;
    }
    const float* bsrc[8]; uint32_t bdst[8];
    #pragma unroll
    for (int i = 0; i < 8; i++) {
        int idx = t + i * 256;
        int kr = idx >> 6, gc = idx & 63;
        bsrc[i] = W + (size_t)kr * 65536 + n0 + gc * 4;
        bdst[i] = (uint32_t)(TM_A_FLOATS + kr * 264 + gc * 4) * 4;
    }

    #pragma unroll
    for (int c = 0; c < 3; c++) {
        uint32_t sb = sbase + (uint32_t)c * TM_STAGE_BYTES;
        int k0 = c * 32;
        #pragma unroll
        for (int i = 0; i < 2; i++) cp_async16(sb + adst[i], asrc[i] + k0);
        #pragma unroll
        for (int i = 0; i < 8; i++) cp_async16(sb + bdst[i], bsrc[i] + (size_t)k0 * 65536);
        CP_COMMIT();
    }

    float acc[2][8][4];
    #pragma unroll
    for (int i = 0; i < 2; i++)
        #pragma unroll
        for (int j = 0; j < 8; j++)
            #pragma unroll
            for (int q = 0; q < 4; q++) acc[i][j][q] = 0.f;

    for (int c = 0; c < 16; c++) {
        CP_WAIT2();
        __syncthreads();
        const float* sA = smem + (c % 3) * TM_STAGE_FLOATS;
        const float* sB = sA + TM_A_FLOATS;

        #pragma unroll
        for (int ka = 0; ka < 4; ka++) {
            uint32_t af[2][4], bf[4][4];
            #pragma unroll
            for (int ml = 0; ml < 2; ml++) {
                const uint32_t* p0 = (const uint32_t*)(sA
                    + (mw * 32 + ml * 16 + g) * TM_ASTRIDE + ka * 8 + tg);
                af[ml][0] = p0[0];
                af[ml][1] = p0[8 * TM_ASTRIDE];
                af[ml][2] = p0[4];
                af[ml][3] = p0[8 * TM_ASTRIDE + 4];
            }
            #pragma unroll
            for (int pl = 0; pl < 4; pl++) {
                const uint32_t* q0 = (const uint32_t*)(sB
                    + (ka * 8 + tg) * 264 + nw * 64 + pl * 16 + g);
                bf[pl][0] = q0[0];
                bf[pl][1] = q0[4 * 264];
                bf[pl][2] = q0[8];
                bf[pl][3] = q0[4 * 264 + 8];
            }
            #pragma unroll
            for (int ml = 0; ml < 2; ml++) {
                #pragma unroll
                for (int pl = 0; pl < 4; pl++) {
                    mma_tf32(acc[ml][pl*2][0], acc[ml][pl*2][1],
                             acc[ml][pl*2][2], acc[ml][pl*2][3],
                             af[ml][0], af[ml][1], af[ml][2], af[ml][3],
                             bf[pl][0], bf[pl][1]);
                    mma_tf32(acc[ml][pl*2+1][0], acc[ml][pl*2+1][1],
                             acc[ml][pl*2+1][2], acc[ml][pl*2+1][3],
                             af[ml][0], af[ml][1], af[ml][2], af[ml][3],
                             bf[pl][2], bf[pl][3]);
                }
            }
        }
        __syncthreads();

        if (c + 3 < 16) {
            int cc = c + 3;
            uint32_t sb = sbase + (uint32_t)(cc % 3) * TM_STAGE_BYTES;
            int k0 = cc * 32;
            #pragma unroll
            for (int i = 0; i < 2; i++) cp_async16(sb + adst[i], asrc[i] + k0);
            #pragma unroll
            for (int i = 0; i < 8; i++) cp_async16(sb + bdst[i], bsrc[i] + (size_t)k0 * 65536);
            CP_COMMIT();
        }
    }

    #pragma unroll
    for (int ml = 0; ml < 2; ml++) {
        int gm0 = mw * 32 + ml * 16 + g;
        int gm1 = gm0 + 8;
        #pragma unroll
        for (int nl = 0; nl < 8; nl++) {
            int cl = (nw * 8 + nl) * 8 + tg * 2;
            float b0 = sBias[cl], b1 = sBias[cl + 1];
            float2 v0, v1;
            v0.x = fmaxf(acc[ml][nl][0] + b0, 0.f);
            v0.y = fmaxf(acc[ml][nl][1] + b1, 0.f);
            v1.x = fmaxf(acc[ml][nl][2] + b0, 0.f);
            v1.y = fmaxf(acc[ml][nl][3] + b1, 0.f);
            *(float2*)&g_tmap[(size_t)gm0 * 65536 + n0 + cl] = v0;
            *(float2*)&g_tmap[(size_t)gm1 * 65536 + n0 + cl] = v1;
        }
    }
}

// ============================================================
// proj body: one 128x256 tile (tf32 mma), outputs fp16
// G1,G2,K,Q -> g_projh [n][dk]; V -> g_vth [dk][n]
// ============================================================
#define PJ_ASTRIDE 36
#define PJ_BSTRIDE 264
#define PJ_A_FLOATS (128 * PJ_ASTRIDE)
#define PJ_STAGE_FLOATS (PJ_A_FLOATS + 32 * PJ_BSTRIDE)
#define PJ_STAGE_BYTES (PJ_STAGE_FLOATS * 4)
#define PJ_SMEM ((3 * PJ_STAGE_FLOATS + 256) * 4)

__device__ __forceinline__ void proj_body(
    const float* __restrict__ vin, const float* __restrict__ bmat,
    const float* __restrict__ vmask,
    const float* __restrict__ Wm, const float* __restrict__ Bv,
    int w, int nx, int my, float* smem)
{
    uint32_t sbase = smem_to_u32(smem);
    float* sBias = smem + 3 * PJ_STAGE_FLOATS;

    int t = threadIdx.x;
    int wid = t >> 5, lane = t & 31;
    int mw = wid >> 2, nw = wid & 3;
    int g = lane >> 2, tg = lane & 3;

    int m0 = my * 128;
    int n0 = nx * 256;

    const float* X = (w < 2) ? bmat : vin;

    sBias[t] = Bv[n0 + t];

    const float* asrc[4]; uint32_t adst[4];
    #pragma unroll
    for (int i = 0; i < 4; i++) {
        int idx = t + i * 256;
        int row = idx >> 3, gc = idx & 7;
        asrc[i] = X + (size_t)(m0 + row) * DIM + gc * 4;
        adst[i] = (uint32_t)(row * PJ_ASTRIDE + gc * 4) * 4;
    }
    const float* bsrc[8]; uint32_t bdst[8];
    #pragma unroll
    for (int i = 0; i < 8; i++) {
        int idx = t + i * 256;
        int kr = idx >> 6, gc = idx & 63;
        bsrc[i] = Wm + (size_t)kr * DIM + n0 + gc * 4;
        bdst[i] = (uint32_t)(PJ_A_FLOATS + kr * PJ_BSTRIDE + gc * 4) * 4;
    }

    #pragma unroll
    for (int c = 0; c < 3; c++) {
        uint32_t sb = sbase + (uint32_t)c * PJ_STAGE_BYTES;
        int k0 = c * 32;
        #pragma unroll
        for (int i = 0; i < 4; i++) cp_async16(sb + adst[i], asrc[i] + k0);
        #pragma unroll
        for (int i = 0; i < 8; i++) cp_async16(sb + bdst[i], bsrc[i] + (size_t)k0 * DIM);
        CP_COMMIT();
    }

    float acc[4][8][4];
    #pragma unroll
    for (int i = 0; i < 4; i++)
        #pragma unroll
        for (int j = 0; j < 8; j++)
            #pragma unroll
            for (int q = 0; q < 4; q++) acc[i][j][q] = 0.f;

    for (int c = 0; c < 16; c++) {
        CP_WAIT2();
        __syncthreads();
        const float* sA = smem + (c % 3) * PJ_STAGE_FLOATS;
        const float* sB = sA + PJ_A_FLOATS;

        #pragma unroll
        for (int ka = 0; ka < 4; ka++) {
            uint32_t af[4][4], bf[4][4];
            #pragma unroll
            for (int ml = 0; ml < 4; ml++) {
                const uint32_t* p0 = (const uint32_t*)(sA
                    + (mw * 64 + ml * 16 + g) * PJ_ASTRIDE + ka * 8 + tg);
                af[ml][0] = p0[0];
                af[ml][1] = p0[8 * PJ_ASTRIDE];
                af[ml][2] = p0[4];
                af[ml][3] = p0[8 * PJ_ASTRIDE + 4];
            }
            #pragma unroll
            for (int pl = 0; pl < 4; pl++) {
                const uint32_t* q0 = (const uint32_t*)(sB
                    + (ka * 8 + tg) * PJ_BSTRIDE + nw * 64 + pl * 16 + g);
                bf[pl][0] = q0[0];
                bf[pl][1] = q0[4 * PJ_BSTRIDE];
                bf[pl][2] = q0[8];
                bf[pl][3] = q0[4 * PJ_BSTRIDE + 8];
            }
            #pragma unroll
            for (int ml = 0; ml < 4; ml++) {
                #pragma unroll
                for (int pl = 0; pl < 4; pl++) {
                    mma_tf32(acc[ml][pl*2][0], acc[ml][pl*2][1],
                             acc[ml][pl*2][2], acc[ml][pl*2][3],
                             af[ml][0], af[ml][1], af[ml][2], af[ml][3],
                             bf[pl][0], bf[pl][1]);
                    mma_tf32(acc[ml][pl*2+1][0], acc[ml][pl*2+1][1],
                             acc[ml][pl*2+1][2], acc[ml][pl*2+1][3],
                             af[ml][0], af[ml][1], af[ml][2], af[ml][3],
                             bf[pl][2], bf[pl][3]);
                }
            }
        }
        __syncthreads();

        if (c + 3 < 16) {
            int cc = c + 3;
            uint32_t sb = sbase + (uint32_t)(cc % 3) * PJ_STAGE_BYTES;
            int k0 = cc * 32;
            #pragma unroll
            for (int i = 0; i < 4; i++) cp_async16(sb + adst[i], asrc[i] + k0);
            #pragma unroll
            for (int i = 0; i < 8; i++) cp_async16(sb + bdst[i], bsrc[i] + (size_t)k0 * DIM);
            CP_COMMIT();
        }
    }

    // ---- epilogue: bias + mask -> fp16 ----
    #pragma unroll
    for (int ml = 0; ml < 4; ml++) {
        int gm0 = m0 + mw * 64 + ml * 16 + g;
        int gm1 = gm0 + 8;
        float msk0 = (w < 2) ? vmask[gm0] : 1.0f;
        float msk1 = (w < 2) ? vmask[gm1] : 1.0f;
        int bbi = gm0 >> 8;
        int nn0 = gm0 & 255, nn1 = gm1 & 255;
        #pragma unroll
        for (int nl = 0; nl < 8; nl++) {
            int cl = (nw * 8 + nl) * 8 + tg * 2;
            int cg = n0 + cl;
            int rrel = cg >> 6, d = cg & 63;
            float b0 = sBias[cl], b1 = sBias[cl + 1];
            float x0 = (acc[ml][nl][0] + b0) * msk0;
            float y0 = (acc[ml][nl][1] + b1) * msk0;
            float x1 = (acc[ml][nl][2] + b0) * msk1;
            float y1 = (acc[ml][nl][3] + b1) * msk1;
            if (w < 4) {
                __half* Ph = g_projh + (size_t)w * WSTRIDE;
                *(uint32_t*)&Ph[((size_t)(bbi * RREL + rrel) * NOBJ + nn0) * DK + d]
                    = pack_f16(x0, y0);
                *(uint32_t*)&Ph[((size_t)(bbi * RREL + rrel) * NOBJ + nn1) * DK + d]
                    = pack_f16(x1, y1);
            } else {
                size_t vb = (size_t)(bbi * RREL + rrel) * DK;
                g_vth[(vb + d)     * NOBJ + nn0] = __float2half(x0);
                g_vth[(vb + d + 1) * NOBJ + nn0] = __float2half(y0);
                g_vth[(vb + d)     * NOBJ + nn1] = __float2half(x1);
                g_vth[(vb + d + 1) * NOBJ + nn1] = __float2half(y1);
            }
        }
    }
}

// ============================================================
// Fused proj + tmap kernel: 1536 blocks, every 6th is tmap
// ============================================================
__global__ __launch_bounds__(256, 1) void projtmap_kernel(
    const float* __restrict__ vin, const float* __restrict__ bmat,
    const float* __restrict__ vmask,
    const float* __restrict__ W0, const float* __restrict__ B0,
    const float* __restrict__ W1, const float* __restrict__ B1,
    const float* __restrict__ W2, const float* __restrict__ B2,
    const float* __restrict__ W3, const float* __restrict__ B3,
    const float* __restrict__ W4, const float* __restrict__ B4,
    const float* __restrict__ Wt, const float* __restrict__ Bt)
{
    extern __shared__ float smem[];
    int bid = blockIdx.x;
    if ((bid % 6) == 5) {
        tmap_body(Wt, Bt, bid / 6, smem);
    } else {
        int pid = bid - (bid + 1) / 6;      // 0..1279
        int w   = pid >> 8;
        int rem = pid & 255;
        int my  = rem >> 1;
        int nx  = rem & 1;
        const float* Wm; const float* Bv;
        switch (w) {
            case 0: Wm = W0; Bv = B0; break;
            case 1: Wm = W1; Bv = B1; break;
            case 2: Wm = W2; Bv = B2; break;
            case 3: Wm = W3; Bv = B3; break;
            default: Wm = W4; Bv = B4; break;
        }
        proj_body(vin, bmat, vmask, Wm, Bv, w, nx, my, smem);
    }
}

// ============================================================
// Kernel 4: fused attention — full fp16 mma path + scaled fp16 S
// smem: 4 fp16 tiles [64][72] (36.9 KB), S fp16 [64][264] (33.8 KB),
//       Vt fp16 overlays tiles, inv fp32[64].  70.9 KB, 2 blocks/SM
// ============================================================
#define PBH   72
#define TILE_B (64 * PBH * 2)          // 9216 bytes
#define SPH   264
#define SS_B  (4 * TILE_B)             // 36864
#define INV_B (SS_B + 64 * SPH * 2)    // 70656
#define ATTN_SMEM (INV_B + 256)        // 70912
#define S_SCALE 1024.0f

__device__ __forceinline__ void tile_ldg_h(uint4* r, const __half* __restrict__ src)
{
    int t = threadIdx.x;
    #pragma unroll
    for (int p = 0; p < 2; p++) {
        int idx = t + p * 256;               // 0..511
        r[p] = *(const uint4*)(src + idx * 8);
    }
}

__device__ __forceinline__ void tile_sts_h(uint16_t* dst, const uint4* r)
{
    int t = threadIdx.x;
    #pragma unroll
    for (int p = 0; p < 2; p++) {
        int idx = t + p * 256;
        int row = idx >> 3, k8 = (idx & 7) * 8;
        *(uint4*)(dst + row * PBH + k8) = r[p];
    }
}

__global__ __launch_bounds__(256, 2) void attn_kernel(
    const float* __restrict__ vmask, const float* __restrict__ vin,
    float* __restrict__ out)
{
    extern __shared__ char smc[];
    uint16_t* sG1 = (uint16_t*)(smc);
    uint16_t* sK  = (uint16_t*)(smc + TILE_B);
    uint16_t* sX  = (uint16_t*)(smc + 2 * TILE_B);
    uint16_t* sY  = (uint16_t*)(smc + 3 * TILE_B);
    uint16_t* sVt = (uint16_t*)(smc);            // overlay (PV phase)
    uint16_t* sSb = (uint16_t*)(smc + SS_B);
    float*    sInv = (float*)(smc + INV_B);

    int nt = blockIdx.x, r = blockIdx.y, bb = blockIdx.z;
    int t  = threadIdx.x;
    int wid = t >> 5, lane = t & 31;
    int g = lane >> 2, tg = lane & 3;
    int wm = wid >> 2, wn = wid & 3;

    size_t pbase = (size_t)(bb * RREL + r) * NOBJ * DK;
    const __half* G1h = g_projh + 0ull * WSTRIDE + pbase;
    const __half* G2h = g_projh + 1ull * WSTRIDE + pbase;
    const __half* Kh  = g_projh + 2ull * WSTRIDE + pbase;
    const __half* Qh  = g_projh + 3ull * WSTRIDE + pbase;
    const __half* Vth = g_vth + pbase;           // [dk][n]

    {
        uint4 rg[2], rk[2];
        tile_ldg_h(rg, G1h + nt * 64 * DK);
        tile_ldg_h(rk, Kh  + nt * 64 * DK);
        tile_sts_h(sG1, rg);
        tile_sts_h(sK, rk);
    }

    const float* tmrow = g_tmap + ((size_t)bb * NOBJ * NOBJ);

    uint4 px[2], py[2];
    tile_ldg_h(px, G2h);
    tile_ldg_h(py, Qh);

    // ---- score phase (fp16 mma k16) ----
    for (int mt = 0; mt < 4; mt++) {
        tile_sts_h(sX, px);
        tile_sts_h(sY, py);
        __syncthreads();

        if (mt < 3) {
            tile_ldg_h(px, G2h + (mt + 1) * 64 * DK);
            tile_ldg_h(py, Qh  + (mt + 1) * 64 * DK);
        }

        float accG[2][2][4], accS[2][2][4];
        #pragma unroll
        for (int i = 0; i < 2; i++)
            #pragma unroll
            for (int j = 0; j < 2; j++)
                #pragma unroll
                for (int q = 0; q < 4; q++) { accG[i][j][q] = 0.f; accS[i][j][q] = 0.f; }

        #pragma unroll
        for (int ks = 0; ks < 4; ks++) {
            int ko = ks * 16 + tg * 2;
            uint32_t aG[2][4], aK[2][4];
            #pragma unroll
            for (int ma = 0; ma < 2; ma++) {
                int rb = wm * 32 + ma * 16 + g;
                const uint16_t* p1 = sG1 + rb * PBH + ko;
                aG[ma][0] = *(const uint32_t*)p1;
                aG[ma][1] = *(const uint32_t*)(p1 + 8 * PBH);
                aG[ma][2] = *(const uint32_t*)(p1 + 8);
                aG[ma][3] = *(const uint32_t*)(p1 + 8 * PBH + 8);
                const uint16_t* p2 = sK + rb * PBH + ko;
                aK[ma][0] = *(const uint32_t*)p2;
                aK[ma][1] = *(const uint32_t*)(p2 + 8 * PBH);
                aK[ma][2] = *(const uint32_t*)(p2 + 8);
                aK[ma][3] = *(const uint32_t*)(p2 + 8 * PBH + 8);
            }
            uint32_t bX[2][2], bY[2][2];
            #pragma unroll
            for (int na = 0; na < 2; na++) {
                int cb = wn * 16 + na * 8 + g;
                const uint16_t* q1 = sX + cb * PBH + ko;
                bX[na][0] = *(const uint32_t*)q1;
                bX[na][1] = *(const uint32_t*)(q1 + 8);
                const uint16_t* q2 = sY + cb * PBH + ko;
                bY[na][0] = *(const uint32_t*)q2;
                bY[na][1] = *(const uint32_t*)(q2 + 8);
            }
            #pragma unroll
            for (int ma = 0; ma < 2; ma++)
                #pragma unroll
                for (int na = 0; na < 2; na++) {
                    mma_f16(accG[ma][na][0], accG[ma][na][1],
                            accG[ma][na][2], accG[ma][na][3],
                            aG[ma][0], aG[ma][1], aG[ma][2], aG[ma][3],
                            bX[na][0], bX[na][1]);
                    mma_f16(accS[ma][na][0], accS[ma][na][1],
                            accS[ma][na][2], accS[ma][na][3],
                            aK[ma][0], aK[ma][1], aK[ma][2], aK[ma][3],
                            bY[na][0], bY[na][1]);
                }
        }

        // epilogue: relu + tmap + exp + mask -> sSb (fp16 pairs, scaled)
        #pragma unroll
        for (int ma = 0; ma < 2; ma++) {
            #pragma unroll
            for (int na = 0; na < 2; na++) {
                int col = wn * 16 + na * 8 + tg * 2;
                int mg  = mt * 64 + col;
                float2 vm = *(const float2*)&vmask[bb * NOBJ + mg];
                #pragma unroll
                for (int h = 0; h < 2; h++) {
                    int row = wm * 32 + ma * 16 + g + h * 8;
                    int ng  = nt * 64 + row;
                    float2 tm = *(const float2*)&tmrow[(size_t)ng * NOBJ + mg];
                    float cG0 = accG[ma][na][h * 2], cG1 = accG[ma][na][h * 2 + 1];
                    float cS0 = accS[ma][na][h * 2], cS1 = accS[ma][na][h * 2 + 1];
                    float wg0 = fmaxf(fmaxf(cG0, 0.f) + tm.x, 1e-6f);
                    float wg1 = fmaxf(fmaxf(cG1, 0.f) + tm.y, 1e-6f);
                    float t0 = wg0 * __expf(fminf(cS0 * 0.125f, 8.f)) * S_SCALE;
                    float t1 = wg1 * __expf(fminf(cS1 * 0.125f, 8.f)) * S_SCALE;
                    t0 = fminf(t0, 60000.f);
                    t1 = fminf(t1, 60000.f);
                    if (vm.x == 0.f) t0 = 0.f;
                    if (vm.y == 0.f) t1 = 0.f;
                    *(uint32_t*)(sSb + row * SPH + mg) = pack_f16(t0, t1);
                }
            }
        }
        __syncthreads();
    }

    // ---- row sums -> 1/sum (fp32 accumulation; scale cancels) ----
    {
        int rrow = t >> 2;
        int lanei = t & 3;
        const uint32_t* rp = (const uint32_t*)(sSb + rrow * SPH);
        float sum = 0.f;
        for (int i = lanei; i < 128; i += 4) {
            __half2 h = *(const __half2*)&rp[i];
            float2 f = __half22float2(h);
            sum += f.x + f.y;
        }
        sum += __shfl_xor_sync(0xffffffffu, sum, 1);
        sum += __shfl_xor_sync(0xffffffffu, sum, 2);
        if (lanei == 0) sInv[rrow] = 1.f / fmaxf(sum, 1e-30f);
    }

    // ---- stage V^T fp16 into overlay (score tiles dead) ----
    #pragma unroll
    for (int p = 0; p < 8; p++) {
        int idx = t + p * 256;               // 0..2047
        int dk = idx >> 5, m16 = (idx & 31) * 8;
        *(uint4*)(sVt + dk * SPH + m16) = *(const uint4*)(Vth + dk * NOBJ + m16);
    }
    __syncthreads();

    // ---- PV via fp16 mma (k16): O = P[64][256] @ V[256][64] ----
    float accO[2][2][4];
    #pragma unroll
    for (int i = 0; i < 2; i++)
        #pragma unroll
        for (int j = 0; j < 2; j++)
            #pragma unroll
            for (int q = 0; q < 4; q++) accO[i][j][q] = 0.f;

    #pragma unroll 4
    for (int ks = 0; ks < 16; ks++) {
        int ko = ks * 16 + tg * 2;
        uint32_t aP[2][4];
        #pragma unroll
        for (int ma = 0; ma < 2; ma++) {
            int rb = wm * 32 + ma * 16 + g;
            const uint16_t* p1 = sSb + rb * SPH + ko;
            aP[ma][0] = *(const uint32_t*)p1;
            aP[ma][1] = *(const uint32_t*)(p1 + 8 * SPH);
            aP[ma][2] = *(const uint32_t*)(p1 + 8);
            aP[ma][3] = *(const uint32_t*)(p1 + 8 * SPH + 8);
        }
        uint32_t bV[2][2];
        #pragma unroll
        for (int na = 0; na < 2; na++) {
            int cb = wn * 16 + na * 8 + g;
            const uint16_t* q1 = sVt + cb * SPH + ko;
            bV[na][0] = *(const uint32_t*)q1;
            bV[na][1] = *(const uint32_t*)(q1 + 8);
        }
        #pragma unroll
        for (int ma = 0; ma < 2; ma++)
            #pragma unroll
            for (int na = 0; na < 2; na++)
                mma_f16(accO[ma][na][0], accO[ma][na][1],
                        accO[ma][na][2], accO[ma][na][3],
                        aP[ma][0], aP[ma][1], aP[ma][2], aP[ma][3],
                        bV[na][0], bV[na][1]);
    }

    // ---- normalize + residual + store ----
    #pragma unroll
    for (int ma = 0; ma < 2; ma++) {
        #pragma unroll
        for (int h = 0; h < 2; h++) {
            int row = wm * 32 + ma * 16 + g + h * 8;
            int ng  = nt * 64 + row;
            float inv = sInv[row];
            size_t base = ((size_t)bb * NOBJ + ng) * DIM + r * DK;
            #pragma unroll
            for (int na = 0; na < 2; na++) {
                int d = wn * 16 + na * 8 + tg * 2;
                float2 vres = *(const float2*)&vin[base + d];
                float2 o;
                o.x = accO[ma][na][h * 2]     * inv + vres.x;
                o.y = accO[ma][na][h * 2 + 1] * inv + vres.y;
                *(float2*)&out[base + d] = o;
            }
        }
    }
}

// ============================================================
extern "C" void kernel_launch(void* const* d_in, const int* in_sizes, int n_in,
                              void* d_out, int out_size)
{
    const float* v      = (const float*)d_in[0];
    const float* bmat   = (const float*)d_in[1];
    const float* vmask  = (const float*)d_in[2];
    const float* t      = (const float*)d_in[3];
    const float* tmask  = (const float*)d_in[4];
    const float* WG1_w  = (const float*)d_in[5];
    const float* WG1_b  = (const float*)d_in[6];
    const float* WG2_w  = (const float*)d_in[7];
    const float* WG2_b  = (const float*)d_in[8];
    const float* WK_w   = (const float*)d_in[9];
    const float* WK_b   = (const float*)d_in[10];
    const float* WQ_w   = (const float*)d_in[11];
    const float* WQ_b   = (const float*)d_in[12];
    const float* WV_w   = (const float*)d_in[13];
    const float* WV_b   = (const float*)d_in[14];
    const float* tc_w   = (const float*)d_in[15];
    const float* tc_b   = (const float*)d_in[16];
    const float* tmap_w = (const float*)d_in[17];
    const float* tmap_b = (const float*)d_in[18];
    float* out = (float*)d_out;

    cudaFuncSetAttribute(projtmap_kernel, cudaFuncAttributeMaxDynamicSharedMemorySize, PJ_SMEM);
    cudaFuncSetAttribute(attn_kernel, cudaFuncAttributeMaxDynamicSharedMemorySize, ATTN_SMEM);
    cudaFuncSetAttribute(attn_kernel, cudaFuncAttributePreferredSharedMemoryCarveout, 100);

    tsum_kernel<<<BSZ, 256>>>(t, tmask, tc_w, tc_b);
    projtmap_kernel<<<1536, 256, PJ_SMEM>>>(
        v, bmat, vmask,
        WG1_w, WG1_b, WG2_w, WG2_b, WK_w, WK_b, WQ_w, WQ_b, WV_w, WV_b,
        tmap_w, tmap_b);
    attn_kernel<<<dim3(4, RREL, BSZ), 256, ATTN_SMEM>>>(vmask, v, out);
}

// round 13
// speedup vs baseline: 5.8795x; 1.1953x over previous
#include <cuda_runtime.h>
#include <cuda_fp16.h>
#include <math.h>
#include <stdint.h>

#define BSZ   64
#define NOBJ  256
#define TTOK  32
#define DIM   512
#define RREL  8
#define DK    64

#define WSTRIDE (BSZ*RREL*NOBJ*DK)   // 8,388,608
#define XSTRIDE (16384 * DIM)        // 8,388,608 (one input tensor)

// ---- static device scratch ----
__device__ __half g_projh[4ull * WSTRIDE];   // G1,G2,K,Q fp16 [b,r,n,dk]
__device__ __half g_vth[1ull * WSTRIDE];     // V^T fp16 [b,r,dk,n]
__device__ __half g_xh[2ull * XSTRIDE];      // fp16 inputs: [0]=b, [1]=v
__device__ __half g_wth[5ull * DIM * DIM];   // fp16 transposed weights [n][k]
__device__ float g_tmap[(size_t)BSZ * NOBJ * NOBJ];
__device__ float g_tsum[BSZ * DIM];

__device__ __forceinline__ uint32_t smem_to_u32(const void* smem_ptr) {
    uint32_t addr;
    asm("{ .reg .u64 tmp; cvta.to.shared.u64 tmp, %1; cvt.u32.u64 %0, tmp; }"
        : "=r"(addr) : "l"(smem_ptr));
    return addr;
}

__device__ __forceinline__ void cp_async16(uint32_t dst, const void* src) {
    asm volatile("cp.async.cg.shared.global [%0], [%1], 16;"
                 :: "r"(dst), "l"(src) : "memory");
}
#define CP_COMMIT() asm volatile("cp.async.commit_group;" ::: "memory")
#define CP_WAIT2()  asm volatile("cp.async.wait_group 2;" ::: "memory")

__device__ __forceinline__ void mma_tf32(
    float& d0, float& d1, float& d2, float& d3,
    uint32_t a0, uint32_t a1, uint32_t a2, uint32_t a3,
    uint32_t b0, uint32_t b1)
{
    asm volatile(
        "mma.sync.aligned.m16n8k8.row.col.f32.tf32.tf32.f32 "
        "{%0,%1,%2,%3}, {%4,%5,%6,%7}, {%8,%9}, {%0,%1,%2,%3};"
        : "+f"(d0), "+f"(d1), "+f"(d2), "+f"(d3)
        : "r"(a0), "r"(a1), "r"(a2), "r"(a3), "r"(b0), "r"(b1));
}

__device__ __forceinline__ void mma_f16(
    float& d0, float& d1, float& d2, float& d3,
    uint32_t a0, uint32_t a1, uint32_t a2, uint32_t a3,
    uint32_t b0, uint32_t b1)
{
    asm volatile(
        "mma.sync.aligned.m16n8k16.row.col.f32.f16.f16.f32 "
        "{%0,%1,%2,%3}, {%4,%5,%6,%7}, {%8,%9}, {%0,%1,%2,%3};"
        : "+f"(d0), "+f"(d1), "+f"(d2), "+f"(d3)
        : "r"(a0), "r"(a1), "r"(a2), "r"(a3), "r"(b0), "r"(b1));
}

__device__ __forceinline__ uint32_t pack_f16(float x, float y) {
    __half2 h = __floats2half2_rn(x, y);
    return *(uint32_t*)&h;
}

// ============================================================
// prep kernel: tsum (64) + W transpose/convert (1280)
//              + input fp32->fp16 convert (8192)   total 9536
// ============================================================
__global__ __launch_bounds__(256) void prep_kernel(
    const float* __restrict__ t, const float* __restrict__ tmask,
    const float* __restrict__ tcw, const float* __restrict__ tcb,
    const float* __restrict__ vin, const float* __restrict__ bmat,
    const float* __restrict__ W0, const float* __restrict__ W1,
    const float* __restrict__ W2, const float* __restrict__ W3,
    const float* __restrict__ W4)
{
    __shared__ float ptile[32 * 33];
    __shared__ float score[TTOK];
    int bid = blockIdx.x;
    int tid = threadIdx.x;

    if (bid < 64) {
        // ---- tsum body ----
        int bb = bid;
        const float* tb = t + (size_t)bb * TTOK * DIM;
        int warp = tid >> 5, lane = tid & 31;
        for (int tt = warp * 4; tt < warp * 4 + 4; tt++) {
            float s = 0.f;
            for (int d = lane; d < DIM; d += 32) s += tb[tt * DIM + d] * tcw[d];
            #pragma unroll
            for (int o = 16; o > 0; o >>= 1) s += __shfl_xor_sync(0xffffffffu, s, o);
            if (lane == 0) {
                float m = tmask[bb * TTOK + tt];
                if (m == 0.f) score[tt] = 0.f;
                else {
                    float tc = s * m + tcb[0];
                    score[tt] = (1.f / (1.f + expf(-tc))) * m;
                }
            }
        }
        __syncthreads();
        for (int d = tid; d < DIM; d += 256) {
            float acc = 0.f;
            #pragma unroll
            for (int tt = 0; tt < TTOK; tt++) acc += tb[tt * DIM + d] * score[tt];
            g_tsum[bb * DIM + d] = acc;
        }
    } else if (bid < 64 + 1280) {
        // ---- weight transpose + convert: Wth[n][k] = fp16(W[k][n]) ----
        int id = bid - 64;
        int w = id >> 8;          // 0..4
        int tile = id & 255;
        int K0 = (tile >> 4) * 32, N0 = (tile & 15) * 32;
        const float* W;
        switch (w) {
            case 0: W = W0; break; case 1: W = W1; break; case 2: W = W2; break;
            case 3: W = W3; break; default: W = W4; break;
        }
        __half* Wt = g_wth + (size_t)w * DIM * DIM;
        int tx = tid & 31, ty = tid >> 5;
        #pragma unroll
        for (int i = 0; i < 32; i += 8)
            ptile[(ty + i) * 33 + tx] = W[(size_t)(K0 + ty + i) * DIM + N0 + tx];
        __syncthreads();
        #pragma unroll
        for (int i = 0; i < 32; i += 8)
            Wt[(size_t)(N0 + ty + i) * DIM + K0 + tx] = __float2half(ptile[tx * 33 + ty + i]);
    } else {
        // ---- input convert: g_xh[0]=bmat, g_xh[1]=vin (4096 blocks each) ----
        int id = bid - 1344;                 // 0..8191
        int tensor = id >> 12;               // 0 or 1
        int blk = id & 4095;
        const float* src = tensor ? vin : bmat;
        size_t idx8 = ((size_t)blk * 256 + tid) * 8;
        float4 f0 = *(const float4*)(src + idx8);
        float4 f1 = *(const float4*)(src + idx8 + 4);
        uint4 o;
        o.x = pack_f16(f0.x, f0.y);
        o.y = pack_f16(f0.z, f0.w);
        o.z = pack_f16(f1.x, f1.y);
        o.w = pack_f16(f1.z, f1.w);
        *(uint4*)(g_xh + (size_t)tensor * XSTRIDE + idx8) = o;
    }
}

// ============================================================
// tmap body: relu(t_summary @ tmap_w + tmap_b), tf32 mma (unchanged)
// ============================================================
#define TM_ASTRIDE 36
#define TM_A_FLOATS (64 * TM_ASTRIDE)
#define TM_STAGE_FLOATS (TM_A_FLOATS + 32 * 264)
#define TM_STAGE_BYTES (TM_STAGE_FLOATS * 4)

__device__ __forceinline__ void tmap_body(
    const float* __restrict__ W, const float* __restrict__ bias,
    int tm_bid, float* smem)
{
    uint32_t sbase = smem_to_u32(smem);
    float* sBias = smem + 3 * TM_STAGE_FLOATS;

    int t = threadIdx.x;
    int wid = t >> 5, lane = t & 31;
    int mw = wid >> 2, nw = wid & 3;
    int g = lane >> 2, tg = lane & 3;
    int n0 = tm_bid * 256;

    sBias[t] = bias[n0 + t];

    const float* asrc[2]; uint32_t adst[2];
    #pragma unroll
    for (int i = 0; i < 2; i++) {
        int idx = t + i * 256;
        int row = idx >> 3, gc = idx & 7;
        asrc[i] = g_tsum + row * DIM + gc * 4;
        adst[i] = (uint32_t)(row * TM_ASTRIDE + gc * 4) * 4;
    }
    const float* bsrc[8]; uint32_t bdst[8];
    #pragma unroll
    for (int i = 0; i < 8; i++) {
        int idx = t + i * 256;
        int kr = idx >> 6, gc = idx & 63;
        bsrc[i] = W + (size_t)kr * 65536 + n0 + gc * 4;
        bdst[i] = (uint32_t)(TM_A_FLOATS + kr * 264 + gc * 4) * 4;
    }

    #pragma unroll
    for (int c = 0; c < 3; c++) {
        uint32_t sb = sbase + (uint32_t)c * TM_STAGE_BYTES;
        int k0 = c * 32;
        #pragma unroll
        for (int i = 0; i < 2; i++) cp_async16(sb + adst[i], asrc[i] + k0);
        #pragma unroll
        for (int i = 0; i < 8; i++) cp_async16(sb + bdst[i], bsrc[i] + (size_t)k0 * 65536);
        CP_COMMIT();
    }

    float acc[2][8][4];
    #pragma unroll
    for (int i = 0; i < 2; i++)
        #pragma unroll
        for (int j = 0; j < 8; j++)
            #pragma unroll
            for (int q = 0; q < 4; q++) acc[i][j][q] = 0.f;

    for (int c = 0; c < 16; c++) {
        CP_WAIT2();
        __syncthreads();
        const float* sA = smem + (c % 3) * TM_STAGE_FLOATS;
        const float* sB = sA + TM_A_FLOATS;

        #pragma unroll
        for (int ka = 0; ka < 4; ka++) {
            uint32_t af[2][4], bf[4][4];
            #pragma unroll
            for (int ml = 0; ml < 2; ml++) {
                const uint32_t* p0 = (const uint32_t*)(sA
                    + (mw * 32 + ml * 16 + g) * TM_ASTRIDE + ka * 8 + tg);
                af[ml][0] = p0[0];
                af[ml][1] = p0[8 * TM_ASTRIDE];
                af[ml][2] = p0[4];
                af[ml][3] = p0[8 * TM_ASTRIDE + 4];
            }
            #pragma unroll
            for (int pl = 0; pl < 4; pl++) {
                const uint32_t* q0 = (const uint32_t*)(sB
                    + (ka * 8 + tg) * 264 + nw * 64 + pl * 16 + g);
                bf[pl][0] = q0[0];
                bf[pl][1] = q0[4 * 264];
                bf[pl][2] = q0[8];
                bf[pl][3] = q0[4 * 264 + 8];
            }
            #pragma unroll
            for (int ml = 0; ml < 2; ml++) {
                #pragma unroll
                for (int pl = 0; pl < 4; pl++) {
                    mma_tf32(acc[ml][pl*2][0], acc[ml][pl*2][1],
                             acc[ml][pl*2][2], acc[ml][pl*2][3],
                             af[ml][0], af[ml][1], af[ml][2], af[ml][3],
                             bf[pl][0], bf[pl][1]);
                    mma_tf32(acc[ml][pl*2+1][0], acc[ml][pl*2+1][1],
                             acc[ml][pl*2+1][2], acc[ml][pl*2+1][3],
                             af[ml][0], af[ml][1], af[ml][2], af[ml][3],
                             bf[pl][2], bf[pl][3]);
                }
            }
        }
        __syncthreads();

        if (c + 3 < 16) {
            int cc = c + 3;
            uint32_t sb = sbase + (uint32_t)(cc % 3) * TM_STAGE_BYTES;
            int k0 = cc * 32;
            #pragma unroll
            for (int i = 0; i < 2; i++) cp_async16(sb + adst[i], asrc[i] + k0);
            #pragma unroll
            for (int i = 0; i < 8; i++) cp_async16(sb + bdst[i], bsrc[i] + (size_t)k0 * 65536);
            CP_COMMIT();
        }
    }

    #pragma unroll
    for (int ml = 0; ml < 2; ml++) {
        int gm0 = mw * 32 + ml * 16 + g;
        int gm1 = gm0 + 8;
        #pragma unroll
        for (int nl = 0; nl < 8; nl++) {
            int cl = (nw * 8 + nl) * 8 + tg * 2;
            float b0 = sBias[cl], b1 = sBias[cl + 1];
            float2 v0, v1;
            v0.x = fmaxf(acc[ml][nl][0] + b0, 0.f);
            v0.y = fmaxf(acc[ml][nl][1] + b1, 0.f);
            v1.x = fmaxf(acc[ml][nl][2] + b0, 0.f);
            v1.y = fmaxf(acc[ml][nl][3] + b1, 0.f);
            *(float2*)&g_tmap[(size_t)gm0 * 65536 + n0 + cl] = v0;
            *(float2*)&g_tmap[(size_t)gm1 * 65536 + n0 + cl] = v1;
        }
    }
}

// ============================================================
// proj body: fp16 mma k16, 128x256 tile, BK=32, cp.async 3-stage
// ============================================================
#define PH_STRIDE 40                     // halves per row
#define PH_A_HALVES (128 * PH_STRIDE)    // 5120
#define PH_A_BYTES  (PH_A_HALVES * 2)    // 10240
#define PH_STAGE_HALVES (PH_A_HALVES + 256 * PH_STRIDE)  // 15360
#define PH_STAGE_BYTES (PH_STAGE_HALVES * 2)             // 30720
#define PJ_SMEM 130304   // max(tmap 130048, proj 93184) + bias

__device__ __forceinline__ void proj_body(
    const float* __restrict__ vmask,
    const float* __restrict__ Bv,
    int w, int nx, int my, float* smemf)
{
    char* smem = (char*)smemf;
    uint32_t sbase = smem_to_u32(smem);
    float* sBias = (float*)(smem + 3 * PH_STAGE_BYTES);

    int t = threadIdx.x;
    int wid = t >> 5, lane = t & 31;
    int mw = wid >> 2, nw = wid & 3;
    int g = lane >> 2, tg = lane & 3;

    int m0 = my * 128;
    int n0 = nx * 256;

    const __half* Xh  = g_xh + (size_t)((w < 2) ? 0 : 1) * XSTRIDE;
    const __half* Wth = g_wth + (size_t)w * DIM * DIM;

    sBias[t] = Bv[n0 + t];

    const __half* asrc[2]; uint32_t adst[2];
    #pragma unroll
    for (int i = 0; i < 2; i++) {
        int idx = t + i * 256;          // 0..511
        int row = idx >> 2, cc = idx & 3;
        asrc[i] = Xh + (size_t)(m0 + row) * DIM + cc * 8;
        adst[i] = (uint32_t)(row * PH_STRIDE + cc * 8) * 2;
    }
    const __half* bsrc[4]; uint32_t bdst[4];
    #pragma unroll
    for (int i = 0; i < 4; i++) {
        int idx = t + i * 256;          // 0..1023
        int row = idx >> 2, cc = idx & 3;
        bsrc[i] = Wth + (size_t)(n0 + row) * DIM + cc * 8;
        bdst[i] = (uint32_t)(PH_A_BYTES + (row * PH_STRIDE + cc * 8) * 2);
    }

    #pragma unroll
    for (int c = 0; c < 3; c++) {
        uint32_t sb = sbase + (uint32_t)c * PH_STAGE_BYTES;
        int k0 = c * 32;
        #pragma unroll
        for (int i = 0; i < 2; i++) cp_async16(sb + adst[i], asrc[i] + k0);
        #pragma unroll
        for (int i = 0; i < 4; i++) cp_async16(sb + bdst[i], bsrc[i] + k0);
        CP_COMMIT();
    }

    float acc[4][8][4];
    #pragma unroll
    for (int i = 0; i < 4; i++)
        #pragma unroll
        for (int j = 0; j < 8; j++)
            #pragma unroll
            for (int q = 0; q < 4; q++) acc[i][j][q] = 0.f;

    for (int c = 0; c < 16; c++) {
        CP_WAIT2();
        __syncthreads();
        const uint16_t* sA = (const uint16_t*)(smem + (c % 3) * PH_STAGE_BYTES);
        const uint16_t* sB = sA + PH_A_HALVES;

        #pragma unroll
        for (int ka = 0; ka < 2; ka++) {
            int ko = ka * 16 + tg * 2;
            uint32_t af[4][4], bf[4][4];
            #pragma unroll
            for (int ml = 0; ml < 4; ml++) {
                const uint16_t* p = sA + (mw * 64 + ml * 16 + g) * PH_STRIDE + ko;
                af[ml][0] = *(const uint32_t*)p;
                af[ml][1] = *(const uint32_t*)(p + 8 * PH_STRIDE);
                af[ml][2] = *(const uint32_t*)(p + 8);
                af[ml][3] = *(const uint32_t*)(p + 8 * PH_STRIDE + 8);
            }
            #pragma unroll
            for (int pl = 0; pl < 4; pl++) {
                const uint16_t* q = sB + (nw * 64 + pl * 16 + g) * PH_STRIDE + ko;
                bf[pl][0] = *(const uint32_t*)q;
                bf[pl][1] = *(const uint32_t*)(q + 8);
                bf[pl][2] = *(const uint32_t*)(q + 8 * PH_STRIDE);
                bf[pl][3] = *(const uint32_t*)(q + 8 * PH_STRIDE + 8);
            }
            #pragma unroll
            for (int ml = 0; ml < 4; ml++) {
                #pragma unroll
                for (int pl = 0; pl < 4; pl++) {
                    mma_f16(acc[ml][pl*2][0], acc[ml][pl*2][1],
                            acc[ml][pl*2][2], acc[ml][pl*2][3],
                            af[ml][0], af[ml][1], af[ml][2], af[ml][3],
                            bf[pl][0], bf[pl][1]);
                    mma_f16(acc[ml][pl*2+1][0], acc[ml][pl*2+1][1],
                            acc[ml][pl*2+1][2], acc[ml][pl*2+1][3],
                            af[ml][0], af[ml][1], af[ml][2], af[ml][3],
                            bf[pl][2], bf[pl][3]);
                }
            }
        }
        __syncthreads();

        if (c + 3 < 16) {
            int cc = c + 3;
            uint32_t sb = sbase + (uint32_t)(cc % 3) * PH_STAGE_BYTES;
            int k0 = cc * 32;
            #pragma unroll
            for (int i = 0; i < 2; i++) cp_async16(sb + adst[i], asrc[i] + k0);
            #pragma unroll
            for (int i = 0; i < 4; i++) cp_async16(sb + bdst[i], bsrc[i] + k0);
            CP_COMMIT();
        }
    }

    // ---- epilogue: bias + mask -> fp16 ----
    #pragma unroll
    for (int ml = 0; ml < 4; ml++) {
        int gm0 = m0 + mw * 64 + ml * 16 + g;
        int gm1 = gm0 + 8;
        float msk0 = (w < 2) ? vmask[gm0] : 1.0f;
        float msk1 = (w < 2) ? vmask[gm1] : 1.0f;
        int bbi = gm0 >> 8;
        int nn0 = gm0 & 255, nn1 = gm1 & 255;
        #pragma unroll
        for (int nl = 0; nl < 8; nl++) {
            int cl = (nw * 8 + nl) * 8 + tg * 2;
            int cg = n0 + cl;
            int rrel = cg >> 6, d = cg & 63;
            float b0 = sBias[cl], b1 = sBias[cl + 1];
            float x0 = (acc[ml][nl][0] + b0) * msk0;
            float y0 = (acc[ml][nl][1] + b1) * msk0;
            float x1 = (acc[ml][nl][2] + b0) * msk1;
            float y1 = (acc[ml][nl][3] + b1) * msk1;
            if (w < 4) {
                __half* Ph = g_projh + (size_t)w * WSTRIDE;
                *(uint32_t*)&Ph[((size_t)(bbi * RREL + rrel) * NOBJ + nn0) * DK + d]
                    = pack_f16(x0, y0);
                *(uint32_t*)&Ph[((size_t)(bbi * RREL + rrel) * NOBJ + nn1) * DK + d]
                    = pack_f16(x1, y1);
            } else {
                size_t vb = (size_t)(bbi * RREL + rrel) * DK;
                g_vth[(vb + d)     * NOBJ + nn0] = __float2half(x0);
                g_vth[(vb + d + 1) * NOBJ + nn0] = __float2half(y0);
                g_vth[(vb + d)     * NOBJ + nn1] = __float2half(x1);
                g_vth[(vb + d + 1) * NOBJ + nn1] = __float2half(y1);
            }
        }
    }
}

// ============================================================
// Fused proj + tmap kernel: 1536 blocks, every 6th is tmap
// ============================================================
__global__ __launch_bounds__(256, 1) void projtmap_kernel(
    const float* __restrict__ vmask,
    const float* __restrict__ B0, const float* __restrict__ B1,
    const float* __restrict__ B2, const float* __restrict__ B3,
    const float* __restrict__ B4,
    const float* __restrict__ Wt, const float* __restrict__ Bt)
{
    extern __shared__ float smem[];
    int bid = blockIdx.x;
    if ((bid % 6) == 5) {
        tmap_body(Wt, Bt, bid / 6, smem);
    } else {
        int pid = bid - (bid + 1) / 6;      // 0..1279
        int w   = pid >> 8;
        int rem = pid & 255;
        int my  = rem >> 1;
        int nx  = rem & 1;
        const float* Bv;
        switch (w) {
            case 0: Bv = B0; break; case 1: Bv = B1; break;
            case 2: Bv = B2; break; case 3: Bv = B3; break;
            default: Bv = B4; break;
        }
        proj_body(vmask, Bv, w, nx, my, smem);
    }
}

// ============================================================
// Kernel 4: fused attention — full fp16 mma path + scaled fp16 S
// (unchanged from R11)
// ============================================================
#define PBH   72
#define TILE_B (64 * PBH * 2)
#define SPH   264
#define SS_B  (4 * TILE_B)
#define INV_B (SS_B + 64 * SPH * 2)
#define ATTN_SMEM (INV_B + 256)
#define S_SCALE 1024.0f

__device__ __forceinline__ void tile_ldg_h(uint4* r, const __half* __restrict__ src)
{
    int t = threadIdx.x;
    #pragma unroll
    for (int p = 0; p < 2; p++) {
        int idx = t + p * 256;
        r[p] = *(const uint4*)(src + idx * 8);
    }
}

__device__ __forceinline__ void tile_sts_h(uint16_t* dst, const uint4* r)
{
    int t = threadIdx.x;
    #pragma unroll
    for (int p = 0; p < 2; p++) {
        int idx = t + p * 256;
        int row = idx >> 3, k8 = (idx & 7) * 8;
        *(uint4*)(dst + row * PBH + k8) = r[p];
    }
}

__global__ __launch_bounds__(256, 2) void attn_kernel(
    const float* __restrict__ vmask, const float* __restrict__ vin,
    float* __restrict__ out)
{
    extern __shared__ char smc[];
    uint16_t* sG1 = (uint16_t*)(smc);
    uint16_t* sK  = (uint16_t*)(smc + TILE_B);
    uint16_t* sX  = (uint16_t*)(smc + 2 * TILE_B);
    uint16_t* sY  = (uint16_t*)(smc + 3 * TILE_B);
    uint16_t* sVt = (uint16_t*)(smc);
    uint16_t* sSb = (uint16_t*)(smc + SS_B);
    float*    sInv = (float*)(smc + INV_B);

    int nt = blockIdx.x, r = blockIdx.y, bb = blockIdx.z;
    int t  = threadIdx.x;
    int wid = t >> 5, lane = t & 31;
    int g = lane >> 2, tg = lane & 3;
    int wm = wid >> 2, wn = wid & 3;

    size_t pbase = (size_t)(bb * RREL + r) * NOBJ * DK;
    const __half* G1h = g_projh + 0ull * WSTRIDE + pbase;
    const __half* G2h = g_projh + 1ull * WSTRIDE + pbase;
    const __half* Kh  = g_projh + 2ull * WSTRIDE + pbase;
    const __half* Qh  = g_projh + 3ull * WSTRIDE + pbase;
    const __half* Vth = g_vth + pbase;

    {
        uint4 rg[2], rk[2];
        tile_ldg_h(rg, G1h + nt * 64 * DK);
        tile_ldg_h(rk, Kh  + nt * 64 * DK);
        tile_sts_h(sG1, rg);
        tile_sts_h(sK, rk);
    }

    const float* tmrow = g_tmap + ((size_t)bb * NOBJ * NOBJ);

    uint4 px[2], py[2];
    tile_ldg_h(px, G2h);
    tile_ldg_h(py, Qh);

    for (int mt = 0; mt < 4; mt++) {
        tile_sts_h(sX, px);
        tile_sts_h(sY, py);
        __syncthreads();

        if (mt < 3) {
            tile_ldg_h(px, G2h + (mt + 1) * 64 * DK);
            tile_ldg_h(py, Qh  + (mt + 1) * 64 * DK);
        }

        float accG[2][2][4], accS[2][2][4];
        #pragma unroll
        for (int i = 0; i < 2; i++)
            #pragma unroll
            for (int j = 0; j < 2; j++)
                #pragma unroll
                for (int q = 0; q < 4; q++) { accG[i][j][q] = 0.f; accS[i][j][q] = 0.f; }

        #pragma unroll
        for (int ks = 0; ks < 4; ks++) {
            int ko = ks * 16 + tg * 2;
            uint32_t aG[2][4], aK[2][4];
            #pragma unroll
            for (int ma = 0; ma < 2; ma++) {
                int rb = wm * 32 + ma * 16 + g;
                const uint16_t* p1 = sG1 + rb * PBH + ko;
                aG[ma][0] = *(const uint32_t*)p1;
                aG[ma][1] = *(const uint32_t*)(p1 + 8 * PBH);
                aG[ma][2] = *(const uint32_t*)(p1 + 8);
                aG[ma][3] = *(const uint32_t*)(p1 + 8 * PBH + 8);
                const uint16_t* p2 = sK + rb * PBH + ko;
                aK[ma][0] = *(const uint32_t*)p2;
                aK[ma][1] = *(const uint32_t*)(p2 + 8 * PBH);
                aK[ma][2] = *(const uint32_t*)(p2 + 8);
                aK[ma][3] = *(const uint32_t*)(p2 + 8 * PBH + 8);
            }
            uint32_t bX[2][2], bY[2][2];
            #pragma unroll
            for (int na = 0; na < 2; na++) {
                int cb = wn * 16 + na * 8 + g;
                const uint16_t* q1 = sX + cb * PBH + ko;
                bX[na][0] = *(const uint32_t*)q1;
                bX[na][1] = *(const uint32_t*)(q1 + 8);
                const uint16_t* q2 = sY + cb * PBH + ko;
                bY[na][0] = *(const uint32_t*)q2;
                bY[na][1] = *(const uint32_t*)(q2 + 8);
            }
            #pragma unroll
            for (int ma = 0; ma < 2; ma++)
                #pragma unroll
                for (int na = 0; na < 2; na++) {
                    mma_f16(accG[ma][na][0], accG[ma][na][1],
                            accG[ma][na][2], accG[ma][na][3],
                            aG[ma][0], aG[ma][1], aG[ma][2], aG[ma][3],
                            bX[na][0], bX[na][1]);
                    mma_f16(accS[ma][na][0], accS[ma][na][1],
                            accS[ma][na][2], accS[ma][na][3],
                            aK[ma][0], aK[ma][1], aK[ma][2], aK[ma][3],
                            bY[na][0], bY[na][1]);
                }
        }

        #pragma unroll
        for (int ma = 0; ma < 2; ma++) {
            #pragma unroll
            for (int na = 0; na < 2; na++) {
                int col = wn * 16 + na * 8 + tg * 2;
                int mg  = mt * 64 + col;
                float2 vm = *(const float2*)&vmask[bb * NOBJ + mg];
                #pragma unroll
                for (int h = 0; h < 2; h++) {
                    int row = wm * 32 + ma * 16 + g + h * 8;
                    int ng  = nt * 64 + row;
                    float2 tm = *(const float2*)&tmrow[(size_t)ng * NOBJ + mg];
                    float cG0 = accG[ma][na][h * 2], cG1 = accG[ma][na][h * 2 + 1];
                    float cS0 = accS[ma][na][h * 2], cS1 = accS[ma][na][h * 2 + 1];
                    float wg0 = fmaxf(fmaxf(cG0, 0.f) + tm.x, 1e-6f);
                    float wg1 = fmaxf(fmaxf(cG1, 0.f) + tm.y, 1e-6f);
                    float t0 = wg0 * __expf(fminf(cS0 * 0.125f, 8.f)) * S_SCALE;
                    float t1 = wg1 * __expf(fminf(cS1 * 0.125f, 8.f)) * S_SCALE;
                    t0 = fminf(t0, 60000.f);
                    t1 = fminf(t1, 60000.f);
                    if (vm.x == 0.f) t0 = 0.f;
                    if (vm.y == 0.f) t1 = 0.f;
                    *(uint32_t*)(sSb + row * SPH + mg) = pack_f16(t0, t1);
                }
            }
        }
        __syncthreads();
    }

    {
        int rrow = t >> 2;
        int lanei = t & 3;
        const uint32_t* rp = (const uint32_t*)(sSb + rrow * SPH);
        float sum = 0.f;
        for (int i = lanei; i < 128; i += 4) {
            __half2 h = *(const __half2*)&rp[i];
            float2 f = __half22float2(h);
            sum += f.x + f.y;
        }
        sum += __shfl_xor_sync(0xffffffffu, sum, 1);
        sum += __shfl_xor_sync(0xffffffffu, sum, 2);
        if (lanei == 0) sInv[rrow] = 1.f / fmaxf(sum, 1e-30f);
    }

    #pragma unroll
    for (int p = 0; p < 8; p++) {
        int idx = t + p * 256;
        int dk = idx >> 5, m16 = (idx & 31) * 8;
        *(uint4*)(sVt + dk * SPH + m16) = *(const uint4*)(Vth + dk * NOBJ + m16);
    }
    __syncthreads();

    float accO[2][2][4];
    #pragma unroll
    for (int i = 0; i < 2; i++)
        #pragma unroll
        for (int j = 0; j < 2; j++)
            #pragma unroll
            for (int q = 0; q < 4; q++) accO[i][j][q] = 0.f;

    #pragma unroll 4
    for (int ks = 0; ks < 16; ks++) {
        int ko = ks * 16 + tg * 2;
        uint32_t aP[2][4];
        #pragma unroll
        for (int ma = 0; ma < 2; ma++) {
            int rb = wm * 32 + ma * 16 + g;
            const uint16_t* p1 = sSb + rb * SPH + ko;
            aP[ma][0] = *(const uint32_t*)p1;
            aP[ma][1] = *(const uint32_t*)(p1 + 8 * SPH);
            aP[ma][2] = *(const uint32_t*)(p1 + 8);
            aP[ma][3] = *(const uint32_t*)(p1 + 8 * SPH + 8);
        }
        uint32_t bV[2][2];
        #pragma unroll
        for (int na = 0; na < 2; na++) {
            int cb = wn * 16 + na * 8 + g;
            const uint16_t* q1 = sVt + cb * SPH + ko;
            bV[na][0] = *(const uint32_t*)q1;
            bV[na][1] = *(const uint32_t*)(q1 + 8);
        }
        #pragma unroll
        for (int ma = 0; ma < 2; ma++)
            #pragma unroll
            for (int na = 0; na < 2; na++)
                mma_f16(accO[ma][na][0], accO[ma][na][1],
                        accO[ma][na][2], accO[ma][na][3],
                        aP[ma][0], aP[ma][1], aP[ma][2], aP[ma][3],
                        bV[na][0], bV[na][1]);
    }

    #pragma unroll
    for (int ma = 0; ma < 2; ma++) {
        #pragma unroll
        for (int h = 0; h < 2; h++) {
            int row = wm * 32 + ma * 16 + g + h * 8;
            int ng  = nt * 64 + row;
            float inv = sInv[row];
            size_t base = ((size_t)bb * NOBJ + ng) * DIM + r * DK;
            #pragma unroll
            for (int na = 0; na < 2; na++) {
                int d = wn * 16 + na * 8 + tg * 2;
                float2 vres = *(const float2*)&vin[base + d];
                float2 o;
                o.x = accO[ma][na][h * 2]     * inv + vres.x;
                o.y = accO[ma][na][h * 2 + 1] * inv + vres.y;
                *(float2*)&out[base + d] = o;
            }
        }
    }
}

// ============================================================
extern "C" void kernel_launch(void* const* d_in, const int* in_sizes, int n_in,
                              void* d_out, int out_size)
{
    const float* v      = (const float*)d_in[0];
    const float* bmat   = (const float*)d_in[1];
    const float* vmask  = (const float*)d_in[2];
    const float* t      = (const float*)d_in[3];
    const float* tmask  = (const float*)d_in[4];
    const float* WG1_w  = (const float*)d_in[5];
    const float* WG1_b  = (const float*)d_in[6];
    const float* WG2_w  = (const float*)d_in[7];
    const float* WG2_b  = (const float*)d_in[8];
    const float* WK_w   = (const float*)d_in[9];
    const float* WK_b   = (const float*)d_in[10];
    const float* WQ_w   = (const float*)d_in[11];
    const float* WQ_b   = (const float*)d_in[12];
    const float* WV_w   = (const float*)d_in[13];
    const float* WV_b   = (const float*)d_in[14];
    const float* tc_w   = (const float*)d_in[15];
    const float* tc_b   = (const float*)d_in[16];
    const float* tmap_w = (const float*)d_in[17];
    const float* tmap_b = (const float*)d_in[18];
    float* out = (float*)d_out;

    cudaFuncSetAttribute(projtmap_kernel, cudaFuncAttributeMaxDynamicSharedMemorySize, PJ_SMEM);
    cudaFuncSetAttribute(attn_kernel, cudaFuncAttributeMaxDynamicSharedMemorySize, ATTN_SMEM);
    cudaFuncSetAttribute(attn_kernel, cudaFuncAttributePreferredSharedMemoryCarveout, 100);

    prep_kernel<<<64 + 1280 + 8192, 256>>>(
        t, tmask, tc_w, tc_b, v, bmat,
        WG1_w, WG2_w, WK_w, WQ_w, WV_w);
    projtmap_kernel<<<1536, 256, PJ_SMEM>>>(
        vmask, WG1_b, WG2_b, WK_b, WQ_b, WV_b, tmap_w, tmap_b);
    attn_kernel<<<dim3(4, RREL, BSZ), 256, ATTN_SMEM>>>(vmask, v, out);
}

// round 14
// speedup vs baseline: 5.9304x; 1.0087x over previous
#include <cuda_runtime.h>
#include <cuda_fp16.h>
#include <math.h>
#include <stdint.h>

#define BSZ   64
#define NOBJ  256
#define TTOK  32
#define DIM   512
#define RREL  8
#define DK    64

#define WSTRIDE (BSZ*RREL*NOBJ*DK)   // 8,388,608
#define XSTRIDE (16384 * DIM)        // 8,388,608 (one input tensor)

// ---- static device scratch ----
__device__ __half g_projh[4ull * WSTRIDE];   // G1,G2,K,Q fp16 [b,r,n,dk]
__device__ __half g_vth[1ull * WSTRIDE];     // V^T fp16 [b,r,dk,n]
__device__ __half g_xh[2ull * XSTRIDE];      // fp16 inputs: [0]=b, [1]=v
__device__ __half g_wth[5ull * DIM * DIM];   // fp16 transposed weights [n][k]
__device__ float g_tmap[(size_t)BSZ * NOBJ * NOBJ];
__device__ float g_tsum[BSZ * DIM];

__device__ __forceinline__ uint32_t smem_to_u32(const void* smem_ptr) {
    uint32_t addr;
    asm("{ .reg .u64 tmp; cvta.to.shared.u64 tmp, %1; cvt.u32.u64 %0, tmp; }"
        : "=r"(addr) : "l"(smem_ptr));
    return addr;
}

__device__ __forceinline__ void cp_async16(uint32_t dst, const void* src) {
    asm volatile("cp.async.cg.shared.global [%0], [%1], 16;"
                 :: "r"(dst), "l"(src) : "memory");
}
#define CP_COMMIT() asm volatile("cp.async.commit_group;" ::: "memory")
#define CP_WAIT2()  asm volatile("cp.async.wait_group 2;" ::: "memory")

__device__ __forceinline__ void mma_tf32(
    float& d0, float& d1, float& d2, float& d3,
    uint32_t a0, uint32_t a1, uint32_t a2, uint32_t a3,
    uint32_t b0, uint32_t b1)
{
    asm volatile(
        "mma.sync.aligned.m16n8k8.row.col.f32.tf32.tf32.f32 "
        "{%0,%1,%2,%3}, {%4,%5,%6,%7}, {%8,%9}, {%0,%1,%2,%3};"
        : "+f"(d0), "+f"(d1), "+f"(d2), "+f"(d3)
        : "r"(a0), "r"(a1), "r"(a2), "r"(a3), "r"(b0), "r"(b1));
}

__device__ __forceinline__ void mma_f16(
    float& d0, float& d1, float& d2, float& d3,
    uint32_t a0, uint32_t a1, uint32_t a2, uint32_t a3,
    uint32_t b0, uint32_t b1)
{
    asm volatile(
        "mma.sync.aligned.m16n8k16.row.col.f32.f16.f16.f32 "
        "{%0,%1,%2,%3}, {%4,%5,%6,%7}, {%8,%9}, {%0,%1,%2,%3};"
        : "+f"(d0), "+f"(d1), "+f"(d2), "+f"(d3)
        : "r"(a0), "r"(a1), "r"(a2), "r"(a3), "r"(b0), "r"(b1));
}

__device__ __forceinline__ void ldsm_x4(uint32_t* r, uint32_t addr)
{
    asm volatile("ldmatrix.sync.aligned.m8n8.x4.shared.b16 {%0,%1,%2,%3}, [%4];"
        : "=r"(r[0]), "=r"(r[1]), "=r"(r[2]), "=r"(r[3]) : "r"(addr));
}

__device__ __forceinline__ uint32_t pack_f16(float x, float y) {
    __half2 h = __floats2half2_rn(x, y);
    return *(uint32_t*)&h;
}

// ============================================================
// prep kernel: tsum (64) + W transpose/convert (1280)
//              + input fp32->fp16 convert (8192)   total 9536
// ============================================================
__global__ __launch_bounds__(256) void prep_kernel(
    const float* __restrict__ t, const float* __restrict__ tmask,
    const float* __restrict__ tcw, const float* __restrict__ tcb,
    const float* __restrict__ vin, const float* __restrict__ bmat,
    const float* __restrict__ W0, const float* __restrict__ W1,
    const float* __restrict__ W2, const float* __restrict__ W3,
    const float* __restrict__ W4)
{
    __shared__ float ptile[32 * 33];
    __shared__ float score[TTOK];
    int bid = blockIdx.x;
    int tid = threadIdx.x;

    if (bid < 64) {
        int bb = bid;
        const float* tb = t + (size_t)bb * TTOK * DIM;
        int warp = tid >> 5, lane = tid & 31;
        for (int tt = warp * 4; tt < warp * 4 + 4; tt++) {
            float s = 0.f;
            for (int d = lane; d < DIM; d += 32) s += tb[tt * DIM + d] * tcw[d];
            #pragma unroll
            for (int o = 16; o > 0; o >>= 1) s += __shfl_xor_sync(0xffffffffu, s, o);
            if (lane == 0) {
                float m = tmask[bb * TTOK + tt];
                if (m == 0.f) score[tt] = 0.f;
                else {
                    float tc = s * m + tcb[0];
                    score[tt] = (1.f / (1.f + expf(-tc))) * m;
                }
            }
        }
        __syncthreads();
        for (int d = tid; d < DIM; d += 256) {
            float acc = 0.f;
            #pragma unroll
            for (int tt = 0; tt < TTOK; tt++) acc += tb[tt * DIM + d] * score[tt];
            g_tsum[bb * DIM + d] = acc;
        }
    } else if (bid < 64 + 1280) {
        int id = bid - 64;
        int w = id >> 8;
        int tile = id & 255;
        int K0 = (tile >> 4) * 32, N0 = (tile & 15) * 32;
        const float* W;
        switch (w) {
            case 0: W = W0; break; case 1: W = W1; break; case 2: W = W2; break;
            case 3: W = W3; break; default: W = W4; break;
        }
        __half* Wt = g_wth + (size_t)w * DIM * DIM;
        int tx = tid & 31, ty = tid >> 5;
        #pragma unroll
        for (int i = 0; i < 32; i += 8)
            ptile[(ty + i) * 33 + tx] = W[(size_t)(K0 + ty + i) * DIM + N0 + tx];
        __syncthreads();
        #pragma unroll
        for (int i = 0; i < 32; i += 8)
            Wt[(size_t)(N0 + ty + i) * DIM + K0 + tx] = __float2half(ptile[tx * 33 + ty + i]);
    } else {
        int id = bid - 1344;                 // 0..8191
        int tensor = id >> 12;
        int blk = id & 4095;
        const float* src = tensor ? vin : bmat;
        size_t idx8 = ((size_t)blk * 256 + tid) * 8;
        float4 f0 = *(const float4*)(src + idx8);
        float4 f1 = *(const float4*)(src + idx8 + 4);
        uint4 o;
        o.x = pack_f16(f0.x, f0.y);
        o.y = pack_f16(f0.z, f0.w);
        o.z = pack_f16(f1.x, f1.y);
        o.w = pack_f16(f1.z, f1.w);
        *(uint4*)(g_xh + (size_t)tensor * XSTRIDE + idx8) = o;
    }
}

// ============================================================
// tmap body: relu(t_summary @ tmap_w + tmap_b), tf32 mma (unchanged)
// ============================================================
#define TM_ASTRIDE 36
#define TM_A_FLOATS (64 * TM_ASTRIDE)
#define TM_STAGE_FLOATS (TM_A_FLOATS + 32 * 264)
#define TM_STAGE_BYTES (TM_STAGE_FLOATS * 4)

__device__ __forceinline__ void tmap_body(
    const float* __restrict__ W, const float* __restrict__ bias,
    int tm_bid, float* smem)
{
    uint32_t sbase = smem_to_u32(smem);
    float* sBias = smem + 3 * TM_STAGE_FLOATS;

    int t = threadIdx.x;
    int wid = t >> 5, lane = t & 31;
    int mw = wid >> 2, nw = wid & 3;
    int g = lane >> 2, tg = lane & 3;
    int n0 = tm_bid * 256;

    sBias[t] = bias[n0 + t];

    const float* asrc[2]; uint32_t adst[2];
    #pragma unroll
    for (int i = 0; i < 2; i++) {
        int idx = t + i * 256;
        int row = idx >> 3, gc = idx & 7;
        asrc[i] = g_tsum + row * DIM + gc * 4;
        adst[i] = (uint32_t)(row * TM_ASTRIDE + gc * 4) * 4;
    }
    const float* bsrc[8]; uint32_t bdst[8];
    #pragma unroll
    for (int i = 0; i < 8; i++) {
        int idx = t + i * 256;
        int kr = idx >> 6, gc = idx & 63;
        bsrc[i] = W + (size_t)kr * 65536 + n0 + gc * 4;
        bdst[i] = (uint32_t)(TM_A_FLOATS + kr * 264 + gc * 4) * 4;
    }

    #pragma unroll
    for (int c = 0; c < 3; c++) {
        uint32_t sb = sbase + (uint32_t)c * TM_STAGE_BYTES;
        int k0 = c * 32;
        #pragma unroll
        for (int i = 0; i < 2; i++) cp_async16(sb + adst[i], asrc[i] + k0);
        #pragma unroll
        for (int i = 0; i < 8; i++) cp_async16(sb + bdst[i], bsrc[i] + (size_t)k0 * 65536);
        CP_COMMIT();
    }

    float acc[2][8][4];
    #pragma unroll
    for (int i = 0; i < 2; i++)
        #pragma unroll
        for (int j = 0; j < 8; j++)
            #pragma unroll
            for (int q = 0; q < 4; q++) acc[i][j][q] = 0.f;

    for (int c = 0; c < 16; c++) {
        CP_WAIT2();
        __syncthreads();
        const float* sA = smem + (c % 3) * TM_STAGE_FLOATS;
        const float* sB = sA + TM_A_FLOATS;

        #pragma unroll
        for (int ka = 0; ka < 4; ka++) {
            uint32_t af[2][4], bf[4][4];
            #pragma unroll
            for (int ml = 0; ml < 2; ml++) {
                const uint32_t* p0 = (const uint32_t*)(sA
                    + (mw * 32 + ml * 16 + g) * TM_ASTRIDE + ka * 8 + tg);
                af[ml][0] = p0[0];
                af[ml][1] = p0[8 * TM_ASTRIDE];
                af[ml][2] = p0[4];
                af[ml][3] = p0[8 * TM_ASTRIDE + 4];
            }
            #pragma unroll
            for (int pl = 0; pl < 4; pl++) {
                const uint32_t* q0 = (const uint32_t*)(sB
                    + (ka * 8 + tg) * 264 + nw * 64 + pl * 16 + g);
                bf[pl][0] = q0[0];
                bf[pl][1] = q0[4 * 264];
                bf[pl][2] = q0[8];
                bf[pl][3] = q0[4 * 264 + 8];
            }
            #pragma unroll
            for (int ml = 0; ml < 2; ml++) {
                #pragma unroll
                for (int pl = 0; pl < 4; pl++) {
                    mma_tf32(acc[ml][pl*2][0], acc[ml][pl*2][1],
                             acc[ml][pl*2][2], acc[ml][pl*2][3],
                             af[ml][0], af[ml][1], af[ml][2], af[ml][3],
                             bf[pl][0], bf[pl][1]);
                    mma_tf32(acc[ml][pl*2+1][0], acc[ml][pl*2+1][1],
                             acc[ml][pl*2+1][2], acc[ml][pl*2+1][3],
                             af[ml][0], af[ml][1], af[ml][2], af[ml][3],
                             bf[pl][2], bf[pl][3]);
                }
            }
        }
        __syncthreads();

        if (c + 3 < 16) {
            int cc = c + 3;
            uint32_t sb = sbase + (uint32_t)(cc % 3) * TM_STAGE_BYTES;
            int k0 = cc * 32;
            #pragma unroll
            for (int i = 0; i < 2; i++) cp_async16(sb + adst[i], asrc[i] + k0);
            #pragma unroll
            for (int i = 0; i < 8; i++) cp_async16(sb + bdst[i], bsrc[i] + (size_t)k0 * 65536);
            CP_COMMIT();
        }
    }

    #pragma unroll
    for (int ml = 0; ml < 2; ml++) {
        int gm0 = mw * 32 + ml * 16 + g;
        int gm1 = gm0 + 8;
        #pragma unroll
        for (int nl = 0; nl < 8; nl++) {
            int cl = (nw * 8 + nl) * 8 + tg * 2;
            float b0 = sBias[cl], b1 = sBias[cl + 1];
            float2 v0, v1;
            v0.x = fmaxf(acc[ml][nl][0] + b0, 0.f);
            v0.y = fmaxf(acc[ml][nl][1] + b1, 0.f);
            v1.x = fmaxf(acc[ml][nl][2] + b0, 0.f);
            v1.y = fmaxf(acc[ml][nl][3] + b1, 0.f);
            *(float2*)&g_tmap[(size_t)gm0 * 65536 + n0 + cl] = v0;
            *(float2*)&g_tmap[(size_t)gm1 * 65536 + n0 + cl] = v1;
        }
    }
}

// ============================================================
// proj body: fp16 mma k16 with ldmatrix fragment loads
// ============================================================
#define PH_STRIDE 40                     // halves per row
#define PH_A_HALVES (128 * PH_STRIDE)    // 5120
#define PH_A_BYTES  (PH_A_HALVES * 2)    // 10240
#define PH_STAGE_HALVES (PH_A_HALVES + 256 * PH_STRIDE)  // 15360
#define PH_STAGE_BYTES (PH_STAGE_HALVES * 2)             // 30720
#define PJ_SMEM 130304

__device__ __forceinline__ void proj_body(
    const float* __restrict__ vmask,
    const float* __restrict__ Bv,
    int w, int nx, int my, float* smemf)
{
    char* smem = (char*)smemf;
    uint32_t sbase = smem_to_u32(smem);
    float* sBias = (float*)(smem + 3 * PH_STAGE_BYTES);

    int t = threadIdx.x;
    int wid = t >> 5, lane = t & 31;
    int mw = wid >> 2, nw = wid & 3;
    int g = lane >> 2, tg = lane & 3;

    int m0 = my * 128;
    int n0 = nx * 256;

    const __half* Xh  = g_xh + (size_t)((w < 2) ? 0 : 1) * XSTRIDE;
    const __half* Wth = g_wth + (size_t)w * DIM * DIM;

    sBias[t] = Bv[n0 + t];

    const __half* asrc[2]; uint32_t adst[2];
    #pragma unroll
    for (int i = 0; i < 2; i++) {
        int idx = t + i * 256;
        int row = idx >> 2, cc = idx & 3;
        asrc[i] = Xh + (size_t)(m0 + row) * DIM + cc * 8;
        adst[i] = (uint32_t)(row * PH_STRIDE + cc * 8) * 2;
    }
    const __half* bsrc[4]; uint32_t bdst[4];
    #pragma unroll
    for (int i = 0; i < 4; i++) {
        int idx = t + i * 256;
        int row = idx >> 2, cc = idx & 3;
        bsrc[i] = Wth + (size_t)(n0 + row) * DIM + cc * 8;
        bdst[i] = (uint32_t)(PH_A_BYTES + (row * PH_STRIDE + cc * 8) * 2);
    }

    // ldmatrix per-lane base offsets (bytes)
    uint32_t aoffL = (uint32_t)(((mw * 64 + (lane & 15)) * PH_STRIDE
                     + ((lane >> 4) * 8)) * 2);
    uint32_t boffL = (uint32_t)(PH_A_BYTES
                     + ((nw * 64 + (lane & 7) + ((lane >> 4) << 3)) * PH_STRIDE
                     + (((lane >> 3) & 1) * 8)) * 2);

    #pragma unroll
    for (int c = 0; c < 3; c++) {
        uint32_t sb = sbase + (uint32_t)c * PH_STAGE_BYTES;
        int k0 = c * 32;
        #pragma unroll
        for (int i = 0; i < 2; i++) cp_async16(sb + adst[i], asrc[i] + k0);
        #pragma unroll
        for (int i = 0; i < 4; i++) cp_async16(sb + bdst[i], bsrc[i] + k0);
        CP_COMMIT();
    }

    float acc[4][8][4];
    #pragma unroll
    for (int i = 0; i < 4; i++)
        #pragma unroll
        for (int j = 0; j < 8; j++)
            #pragma unroll
            for (int q = 0; q < 4; q++) acc[i][j][q] = 0.f;

    for (int c = 0; c < 16; c++) {
        CP_WAIT2();
        __syncthreads();
        uint32_t sb = sbase + (uint32_t)(c % 3) * PH_STAGE_BYTES;

        #pragma unroll
        for (int ka = 0; ka < 2; ka++) {
            uint32_t kb = (uint32_t)(ka * 16 * 2);
            uint32_t af[4][4], bf[4][4];
            #pragma unroll
            for (int ml = 0; ml < 4; ml++)
                ldsm_x4(af[ml], sb + aoffL + (uint32_t)(ml * 16 * PH_STRIDE * 2) + kb);
            #pragma unroll
            for (int p2 = 0; p2 < 4; p2++)
                ldsm_x4(bf[p2], sb + boffL + (uint32_t)(p2 * 16 * PH_STRIDE * 2) + kb);
            #pragma unroll
            for (int ml = 0; ml < 4; ml++) {
                #pragma unroll
                for (int p2 = 0; p2 < 4; p2++) {
                    mma_f16(acc[ml][p2*2][0], acc[ml][p2*2][1],
                            acc[ml][p2*2][2], acc[ml][p2*2][3],
                            af[ml][0], af[ml][1], af[ml][2], af[ml][3],
                            bf[p2][0], bf[p2][1]);
                    mma_f16(acc[ml][p2*2+1][0], acc[ml][p2*2+1][1],
                            acc[ml][p2*2+1][2], acc[ml][p2*2+1][3],
                            af[ml][0], af[ml][1], af[ml][2], af[ml][3],
                            bf[p2][2], bf[p2][3]);
                }
            }
        }
        __syncthreads();

        if (c + 3 < 16) {
            int cc = c + 3;
            uint32_t sb2 = sbase + (uint32_t)(cc % 3) * PH_STAGE_BYTES;
            int k0 = cc * 32;
            #pragma unroll
            for (int i = 0; i < 2; i++) cp_async16(sb2 + adst[i], asrc[i] + k0);
            #pragma unroll
            for (int i = 0; i < 4; i++) cp_async16(sb2 + bdst[i], bsrc[i] + k0);
            CP_COMMIT();
        }
    }

    // ---- epilogue: bias + mask -> fp16 ----
    #pragma unroll
    for (int ml = 0; ml < 4; ml++) {
        int gm0 = m0 + mw * 64 + ml * 16 + g;
        int gm1 = gm0 + 8;
        float msk0 = (w < 2) ? vmask[gm0] : 1.0f;
        float msk1 = (w < 2) ? vmask[gm1] : 1.0f;
        int bbi = gm0 >> 8;
        int nn0 = gm0 & 255, nn1 = gm1 & 255;
        #pragma unroll
        for (int nl = 0; nl < 8; nl++) {
            int cl = (nw * 8 + nl) * 8 + tg * 2;
            int cg = n0 + cl;
            int rrel = cg >> 6, d = cg & 63;
            float b0 = sBias[cl], b1 = sBias[cl + 1];
            float x0 = (acc[ml][nl][0] + b0) * msk0;
            float y0 = (acc[ml][nl][1] + b1) * msk0;
            float x1 = (acc[ml][nl][2] + b0) * msk1;
            float y1 = (acc[ml][nl][3] + b1) * msk1;
            if (w < 4) {
                __half* Ph = g_projh + (size_t)w * WSTRIDE;
                *(uint32_t*)&Ph[((size_t)(bbi * RREL + rrel) * NOBJ + nn0) * DK + d]
                    = pack_f16(x0, y0);
                *(uint32_t*)&Ph[((size_t)(bbi * RREL + rrel) * NOBJ + nn1) * DK + d]
                    = pack_f16(x1, y1);
            } else {
                size_t vb = (size_t)(bbi * RREL + rrel) * DK;
                g_vth[(vb + d)     * NOBJ + nn0] = __float2half(x0);
                g_vth[(vb + d + 1) * NOBJ + nn0] = __float2half(y0);
                g_vth[(vb + d)     * NOBJ + nn1] = __float2half(x1);
                g_vth[(vb + d + 1) * NOBJ + nn1] = __float2half(y1);
            }
        }
    }
}

// ============================================================
// Fused proj + tmap kernel: 1536 blocks, every 6th is tmap
// ============================================================
__global__ __launch_bounds__(256, 1) void projtmap_kernel(
    const float* __restrict__ vmask,
    const float* __restrict__ B0, const float* __restrict__ B1,
    const float* __restrict__ B2, const float* __restrict__ B3,
    const float* __restrict__ B4,
    const float* __restrict__ Wt, const float* __restrict__ Bt)
{
    extern __shared__ float smem[];
    int bid = blockIdx.x;
    if ((bid % 6) == 5) {
        tmap_body(Wt, Bt, bid / 6, smem);
    } else {
        int pid = bid - (bid + 1) / 6;
        int w   = pid >> 8;
        int rem = pid & 255;
        int my  = rem >> 1;
        int nx  = rem & 1;
        const float* Bv;
        switch (w) {
            case 0: Bv = B0; break; case 1: Bv = B1; break;
            case 2: Bv = B2; break; case 3: Bv = B3; break;
            default: Bv = B4; break;
        }
        proj_body(vmask, Bv, w, nx, my, smem);
    }
}

// ============================================================
// Kernel 4: fused attention — fp16 mma + ldmatrix + scaled fp16 S
// ============================================================
#define PBH   72
#define TILE_B (64 * PBH * 2)
#define SPH   264
#define SS_B  (4 * TILE_B)
#define INV_B (SS_B + 64 * SPH * 2)
#define ATTN_SMEM (INV_B + 256)
#define S_SCALE 1024.0f

__device__ __forceinline__ void tile_ldg_h(uint4* r, const __half* __restrict__ src)
{
    int t = threadIdx.x;
    #pragma unroll
    for (int p = 0; p < 2; p++) {
        int idx = t + p * 256;
        r[p] = *(const uint4*)(src + idx * 8);
    }
}

__device__ __forceinline__ void tile_sts_h(uint16_t* dst, const uint4* r)
{
    int t = threadIdx.x;
    #pragma unroll
    for (int p = 0; p < 2; p++) {
        int idx = t + p * 256;
        int row = idx >> 3, k8 = (idx & 7) * 8;
        *(uint4*)(dst + row * PBH + k8) = r[p];
    }
}

__global__ __launch_bounds__(256, 2) void attn_kernel(
    const float* __restrict__ vmask, const float* __restrict__ vin,
    float* __restrict__ out)
{
    extern __shared__ char smc[];
    uint16_t* sG1 = (uint16_t*)(smc);
    uint16_t* sK  = (uint16_t*)(smc + TILE_B);
    uint16_t* sX  = (uint16_t*)(smc + 2 * TILE_B);
    uint16_t* sY  = (uint16_t*)(smc + 3 * TILE_B);
    uint16_t* sVt = (uint16_t*)(smc);
    uint16_t* sSb = (uint16_t*)(smc + SS_B);
    float*    sInv = (float*)(smc + INV_B);
    uint32_t sb0 = smem_to_u32(smc);

    int nt = blockIdx.x, r = blockIdx.y, bb = blockIdx.z;
    int t  = threadIdx.x;
    int wid = t >> 5, lane = t & 31;
    int g = lane >> 2, tg = lane & 3;
    int wm = wid >> 2, wn = wid & 3;

    size_t pbase = (size_t)(bb * RREL + r) * NOBJ * DK;
    const __half* G1h = g_projh + 0ull * WSTRIDE + pbase;
    const __half* G2h = g_projh + 1ull * WSTRIDE + pbase;
    const __half* Kh  = g_projh + 2ull * WSTRIDE + pbase;
    const __half* Qh  = g_projh + 3ull * WSTRIDE + pbase;
    const __half* Vth = g_vth + pbase;

    // ldmatrix per-lane base offsets (bytes)
    uint32_t aoffT = (uint32_t)(((wm * 32 + (lane & 15)) * PBH
                     + ((lane >> 4) * 8)) * 2);
    uint32_t boffT = (uint32_t)(((wn * 16 + (lane & 7) + ((lane >> 4) << 3)) * PBH
                     + (((lane >> 3) & 1) * 8)) * 2);
    uint32_t aoffS = (uint32_t)(((wm * 32 + (lane & 15)) * SPH
                     + ((lane >> 4) * 8)) * 2);
    uint32_t boffV = (uint32_t)(((wn * 16 + (lane & 7) + ((lane >> 4) << 3)) * SPH
                     + (((lane >> 3) & 1) * 8)) * 2);

    {
        uint4 rg[2], rk[2];
        tile_ldg_h(rg, G1h + nt * 64 * DK);
        tile_ldg_h(rk, Kh  + nt * 64 * DK);
        tile_sts_h(sG1, rg);
        tile_sts_h(sK, rk);
    }

    const float* tmrow = g_tmap + ((size_t)bb * NOBJ * NOBJ);

    uint4 px[2], py[2];
    tile_ldg_h(px, G2h);
    tile_ldg_h(py, Qh);

    // ---- score phase (fp16 mma k16, ldmatrix) ----
    for (int mt = 0; mt < 4; mt++) {
        tile_sts_h(sX, px);
        tile_sts_h(sY, py);
        __syncthreads();

        if (mt < 3) {
            tile_ldg_h(px, G2h + (mt + 1) * 64 * DK);
            tile_ldg_h(py, Qh  + (mt + 1) * 64 * DK);
        }

        float accG[2][2][4], accS[2][2][4];
        #pragma unroll
        for (int i = 0; i < 2; i++)
            #pragma unroll
            for (int j = 0; j < 2; j++)
                #pragma unroll
                for (int q = 0; q < 4; q++) { accG[i][j][q] = 0.f; accS[i][j][q] = 0.f; }

        #pragma unroll
        for (int ks = 0; ks < 4; ks++) {
            uint32_t kb = (uint32_t)(ks * 16 * 2);
            uint32_t aG[2][4], aK[2][4], bX[4], bY[4];
            #pragma unroll
            for (int ma = 0; ma < 2; ma++) {
                uint32_t ao = aoffT + (uint32_t)(ma * 16 * PBH * 2) + kb;
                ldsm_x4(aG[ma], sb0 + ao);                      // sG1 at offset 0
                ldsm_x4(aK[ma], sb0 + TILE_B + ao);
            }
            ldsm_x4(bX, sb0 + 2 * TILE_B + boffT + kb);
            ldsm_x4(bY, sb0 + 3 * TILE_B + boffT + kb);
            #pragma unroll
            for (int ma = 0; ma < 2; ma++) {
                mma_f16(accG[ma][0][0], accG[ma][0][1], accG[ma][0][2], accG[ma][0][3],
                        aG[ma][0], aG[ma][1], aG[ma][2], aG[ma][3], bX[0], bX[1]);
                mma_f16(accG[ma][1][0], accG[ma][1][1], accG[ma][1][2], accG[ma][1][3],
                        aG[ma][0], aG[ma][1], aG[ma][2], aG[ma][3], bX[2], bX[3]);
                mma_f16(accS[ma][0][0], accS[ma][0][1], accS[ma][0][2], accS[ma][0][3],
                        aK[ma][0], aK[ma][1], aK[ma][2], aK[ma][3], bY[0], bY[1]);
                mma_f16(accS[ma][1][0], accS[ma][1][1], accS[ma][1][2], accS[ma][1][3],
                        aK[ma][0], aK[ma][1], aK[ma][2], aK[ma][3], bY[2], bY[3]);
            }
        }

        // epilogue: relu + tmap + exp + mask -> sSb (fp16 pairs, scaled)
        #pragma unroll
        for (int ma = 0; ma < 2; ma++) {
            #pragma unroll
            for (int na = 0; na < 2; na++) {
                int col = wn * 16 + na * 8 + tg * 2;
                int mg  = mt * 64 + col;
                float2 vm = *(const float2*)&vmask[bb * NOBJ + mg];
                #pragma unroll
                for (int h = 0; h < 2; h++) {
                    int row = wm * 32 + ma * 16 + g + h * 8;
                    int ng  = nt * 64 + row;
                    float2 tm = *(const float2*)&tmrow[(size_t)ng * NOBJ + mg];
                    float cG0 = accG[ma][na][h * 2], cG1 = accG[ma][na][h * 2 + 1];
                    float cS0 = accS[ma][na][h * 2], cS1 = accS[ma][na][h * 2 + 1];
                    float wg0 = fmaxf(fmaxf(cG0, 0.f) + tm.x, 1e-6f);
                    float wg1 = fmaxf(fmaxf(cG1, 0.f) + tm.y, 1e-6f);
                    float t0 = wg0 * __expf(fminf(cS0 * 0.125f, 8.f)) * S_SCALE;
                    float t1 = wg1 * __expf(fminf(cS1 * 0.125f, 8.f)) * S_SCALE;
                    t0 = fminf(t0, 60000.f);
                    t1 = fminf(t1, 60000.f);
                    if (vm.x == 0.f) t0 = 0.f;
                    if (vm.y == 0.f) t1 = 0.f;
                    *(uint32_t*)(sSb + row * SPH + mg) = pack_f16(t0, t1);
                }
            }
        }
        __syncthreads();
    }

    // ---- row sums -> 1/sum ----
    {
        int rrow = t >> 2;
        int lanei = t & 3;
        const uint32_t* rp = (const uint32_t*)(sSb + rrow * SPH);
        float sum = 0.f;
        for (int i = lanei; i < 128; i += 4) {
            __half2 h = *(const __half2*)&rp[i];
            float2 f = __half22float2(h);
            sum += f.x + f.y;
        }
        sum += __shfl_xor_sync(0xffffffffu, sum, 1);
        sum += __shfl_xor_sync(0xffffffffu, sum, 2);
        if (lanei == 0) sInv[rrow] = 1.f / fmaxf(sum, 1e-30f);
    }

    // ---- stage V^T fp16 into overlay ----
    #pragma unroll
    for (int p = 0; p < 8; p++) {
        int idx = t + p * 256;
        int dk = idx >> 5, m16 = (idx & 31) * 8;
        *(uint4*)(sVt + dk * SPH + m16) = *(const uint4*)(Vth + dk * NOBJ + m16);
    }
    __syncthreads();

    // ---- PV via fp16 mma (k16, ldmatrix) ----
    float accO[2][2][4];
    #pragma unroll
    for (int i = 0; i < 2; i++)
        #pragma unroll
        for (int j = 0; j < 2; j++)
            #pragma unroll
            for (int q = 0; q < 4; q++) accO[i][j][q] = 0.f;

    #pragma unroll 4
    for (int ks = 0; ks < 16; ks++) {
        uint32_t kb = (uint32_t)(ks * 16 * 2);
        uint32_t aP[2][4], bV[4];
        #pragma unroll
        for (int ma = 0; ma < 2; ma++)
            ldsm_x4(aP[ma], sb0 + SS_B + aoffS + (uint32_t)(ma * 16 * SPH * 2) + kb);
        ldsm_x4(bV, sb0 + boffV + kb);
        #pragma unroll
        for (int ma = 0; ma < 2; ma++) {
            mma_f16(accO[ma][0][0], accO[ma][0][1], accO[ma][0][2], accO[ma][0][3],
                    aP[ma][0], aP[ma][1], aP[ma][2], aP[ma][3], bV[0], bV[1]);
            mma_f16(accO[ma][1][0], accO[ma][1][1], accO[ma][1][2], accO[ma][1][3],
                    aP[ma][0], aP[ma][1], aP[ma][2], aP[ma][3], bV[2], bV[3]);
        }
    }

    // ---- normalize + residual + store ----
    #pragma unroll
    for (int ma = 0; ma < 2; ma++) {
        #pragma unroll
        for (int h = 0; h < 2; h++) {
            int row = wm * 32 + ma * 16 + g + h * 8;
            int ng  = nt * 64 + row;
            float inv = sInv[row];
            size_t base = ((size_t)bb * NOBJ + ng) * DIM + r * DK;
            #pragma unroll
            for (int na = 0; na < 2; na++) {
                int d = wn * 16 + na * 8 + tg * 2;
                float2 vres = *(const float2*)&vin[base + d];
                float2 o;
                o.x = accO[ma][na][h * 2]     * inv + vres.x;
                o.y = accO[ma][na][h * 2 + 1] * inv + vres.y;
                *(float2*)&out[base + d] = o;
            }
        }
    }
}

// ============================================================
extern "C" void kernel_launch(void* const* d_in, const int* in_sizes, int n_in,
                              void* d_out, int out_size)
{
    const float* v      = (const float*)d_in[0];
    const float* bmat   = (const float*)d_in[1];
    const float* vmask  = (const float*)d_in[2];
    const float* t      = (const float*)d_in[3];
    const float* tmask  = (const float*)d_in[4];
    const float* WG1_w  = (const float*)d_in[5];
    const float* WG1_b  = (const float*)d_in[6];
    const float* WG2_w  = (const float*)d_in[7];
    const float* WG2_b  = (const float*)d_in[8];
    const float* WK_w   = (const float*)d_in[9];
    const float* WK_b   = (const float*)d_in[10];
    const float* WQ_w   = (const float*)d_in[11];
    const float* WQ_b   = (const float*)d_in[12];
    const float* WV_w   = (const float*)d_in[13];
    const float* WV_b   = (const float*)d_in[14];
    const float* tc_w   = (const float*)d_in[15];
    const float* tc_b   = (const float*)d_in[16];
    const float* tmap_w = (const float*)d_in[17];
    const float* tmap_b = (const float*)d_in[18];
    float* out = (float*)d_out;

    cudaFuncSetAttribute(projtmap_kernel, cudaFuncAttributeMaxDynamicSharedMemorySize, PJ_SMEM);
    cudaFuncSetAttribute(attn_kernel, cudaFuncAttributeMaxDynamicSharedMemorySize, ATTN_SMEM);
    cudaFuncSetAttribute(attn_kernel, cudaFuncAttributePreferredSharedMemoryCarveout, 100);

    prep_kernel<<<64 + 1280 + 8192, 256>>>(
        t, tmask, tc_w, tc_b, v, bmat,
        WG1_w, WG2_w, WK_w, WQ_w, WV_w);
    projtmap_kernel<<<1536, 256, PJ_SMEM>>>(
        vmask, WG1_b, WG2_b, WK_b, WQ_b, WV_b, tmap_w, tmap_b);
    attn_kernel<<<dim3(4, RREL, BSZ), 256, ATTN_SMEM>>>(vmask, v, out);
}

// round 15
// speedup vs baseline: 6.3752x; 1.0750x over previous
#include <cuda_runtime.h>
#include <cuda_fp16.h>
#include <math.h>
#include <stdint.h>

#define BSZ   64
#define NOBJ  256
#define TTOK  32
#define DIM   512
#define RREL  8
#define DK    64

#define WSTRIDE (BSZ*RREL*NOBJ*DK)   // 8,388,608
#define XSTRIDE (16384 * DIM)        // 8,388,608

// ---- static device scratch ----
__device__ __half g_projh[4ull * WSTRIDE];   // G1,G2,K,Q fp16 [b,r,n,dk]
__device__ __half g_vth[1ull * WSTRIDE];     // V^T fp16 [b,r,dk,n]
__device__ __half g_xh[2ull * XSTRIDE];      // fp16 inputs: [0]=b, [1]=v
__device__ __half g_wth[5ull * DIM * DIM];   // fp16 transposed weights [n][k]
__device__ __half g_tmaph[(size_t)BSZ * NOBJ * NOBJ];  // fp16 tmap
__device__ float g_tsum[BSZ * DIM];

__device__ __forceinline__ uint32_t smem_to_u32(const void* smem_ptr) {
    uint32_t addr;
    asm("{ .reg .u64 tmp; cvta.to.shared.u64 tmp, %1; cvt.u32.u64 %0, tmp; }"
        : "=r"(addr) : "l"(smem_ptr));
    return addr;
}

__device__ __forceinline__ void cp_async16(uint32_t dst, const void* src) {
    asm volatile("cp.async.cg.shared.global [%0], [%1], 16;"
                 :: "r"(dst), "l"(src) : "memory");
}
#define CP_COMMIT() asm volatile("cp.async.commit_group;" ::: "memory")
#define CP_WAIT1()  asm volatile("cp.async.wait_group 1;" ::: "memory")
#define CP_WAIT2()  asm volatile("cp.async.wait_group 2;" ::: "memory")

__device__ __forceinline__ void mma_tf32(
    float& d0, float& d1, float& d2, float& d3,
    uint32_t a0, uint32_t a1, uint32_t a2, uint32_t a3,
    uint32_t b0, uint32_t b1)
{
    asm volatile(
        "mma.sync.aligned.m16n8k8.row.col.f32.tf32.tf32.f32 "
        "{%0,%1,%2,%3}, {%4,%5,%6,%7}, {%8,%9}, {%0,%1,%2,%3};"
        : "+f"(d0), "+f"(d1), "+f"(d2), "+f"(d3)
        : "r"(a0), "r"(a1), "r"(a2), "r"(a3), "r"(b0), "r"(b1));
}

__device__ __forceinline__ void mma_f16(
    float& d0, float& d1, float& d2, float& d3,
    uint32_t a0, uint32_t a1, uint32_t a2, uint32_t a3,
    uint32_t b0, uint32_t b1)
{
    asm volatile(
        "mma.sync.aligned.m16n8k16.row.col.f32.f16.f16.f32 "
        "{%0,%1,%2,%3}, {%4,%5,%6,%7}, {%8,%9}, {%0,%1,%2,%3};"
        : "+f"(d0), "+f"(d1), "+f"(d2), "+f"(d3)
        : "r"(a0), "r"(a1), "r"(a2), "r"(a3), "r"(b0), "r"(b1));
}

__device__ __forceinline__ void ldsm_x4(uint32_t* r, uint32_t addr)
{
    asm volatile("ldmatrix.sync.aligned.m8n8.x4.shared.b16 {%0,%1,%2,%3}, [%4];"
        : "=r"(r[0]), "=r"(r[1]), "=r"(r[2]), "=r"(r[3]) : "r"(addr));
}

__device__ __forceinline__ uint32_t pack_f16(float x, float y) {
    __half2 h = __floats2half2_rn(x, y);
    return *(uint32_t*)&h;
}

// ============================================================
// prep kernel: tsum (64) + W transpose/convert (1280)
//              + input fp32->fp16 convert (8192)   total 9536
// ============================================================
__global__ __launch_bounds__(256) void prep_kernel(
    const float* __restrict__ t, const float* __restrict__ tmask,
    const float* __restrict__ tcw, const float* __restrict__ tcb,
    const float* __restrict__ vin, const float* __restrict__ bmat,
    const float* __restrict__ W0, const float* __restrict__ W1,
    const float* __restrict__ W2, const float* __restrict__ W3,
    const float* __restrict__ W4)
{
    __shared__ float ptile[32 * 33];
    __shared__ float score[TTOK];
    int bid = blockIdx.x;
    int tid = threadIdx.x;

    if (bid < 64) {
        int bb = bid;
        const float* tb = t + (size_t)bb * TTOK * DIM;
        int warp = tid >> 5, lane = tid & 31;
        for (int tt = warp * 4; tt < warp * 4 + 4; tt++) {
            float s = 0.f;
            for (int d = lane; d < DIM; d += 32) s += tb[tt * DIM + d] * tcw[d];
            #pragma unroll
            for (int o = 16; o > 0; o >>= 1) s += __shfl_xor_sync(0xffffffffu, s, o);
            if (lane == 0) {
                float m = tmask[bb * TTOK + tt];
                if (m == 0.f) score[tt] = 0.f;
                else {
                    float tc = s * m + tcb[0];
                    score[tt] = (1.f / (1.f + expf(-tc))) * m;
                }
            }
        }
        __syncthreads();
        for (int d = tid; d < DIM; d += 256) {
            float acc = 0.f;
            #pragma unroll
            for (int tt = 0; tt < TTOK; tt++) acc += tb[tt * DIM + d] * score[tt];
            g_tsum[bb * DIM + d] = acc;
        }
    } else if (bid < 64 + 1280) {
        int id = bid - 64;
        int w = id >> 8;
        int tile = id & 255;
        int K0 = (tile >> 4) * 32, N0 = (tile & 15) * 32;
        const float* W;
        switch (w) {
            case 0: W = W0; break; case 1: W = W1; break; case 2: W = W2; break;
            case 3: W = W3; break; default: W = W4; break;
        }
        __half* Wt = g_wth + (size_t)w * DIM * DIM;
        int tx = tid & 31, ty = tid >> 5;
        #pragma unroll
        for (int i = 0; i < 32; i += 8)
            ptile[(ty + i) * 33 + tx] = W[(size_t)(K0 + ty + i) * DIM + N0 + tx];
        __syncthreads();
        #pragma unroll
        for (int i = 0; i < 32; i += 8)
            Wt[(size_t)(N0 + ty + i) * DIM + K0 + tx] = __float2half(ptile[tx * 33 + ty + i]);
    } else {
        int id = bid - 1344;                 // 0..8191
        int tensor = id >> 12;
        int blk = id & 4095;
        const float* src = tensor ? vin : bmat;
        size_t idx8 = ((size_t)blk * 256 + tid) * 8;
        float4 f0 = *(const float4*)(src + idx8);
        float4 f1 = *(const float4*)(src + idx8 + 4);
        uint4 o;
        o.x = pack_f16(f0.x, f0.y);
        o.y = pack_f16(f0.z, f0.w);
        o.z = pack_f16(f1.x, f1.y);
        o.w = pack_f16(f1.z, f1.w);
        *(uint4*)(g_xh + (size_t)tensor * XSTRIDE + idx8) = o;
    }
}

// ============================================================
// tmap body: relu(t_summary @ tmap_w + tmap_b), tf32 mma, 2-stage
// M=64, N=256 per call; output fp16
// ============================================================
#define TM_ASTRIDE 36
#define TM_A_FLOATS (64 * TM_ASTRIDE)
#define TM_STAGE_FLOATS (TM_A_FLOATS + 32 * 264)   // 10752
#define TM_STAGE_BYTES (TM_STAGE_FLOATS * 4)       // 43008

__device__ __forceinline__ void tmap_body(
    const float* __restrict__ W, const float* __restrict__ bias,
    int tm_bid, float* smem)
{
    uint32_t sbase = smem_to_u32(smem);
    float* sBias = smem + 2 * TM_STAGE_FLOATS;

    int t = threadIdx.x;
    int wid = t >> 5, lane = t & 31;
    int mw = wid >> 2, nw = wid & 3;
    int g = lane >> 2, tg = lane & 3;
    int n0 = tm_bid * 256;

    sBias[t] = bias[n0 + t];

    const float* asrc[2]; uint32_t adst[2];
    #pragma unroll
    for (int i = 0; i < 2; i++) {
        int idx = t + i * 256;
        int row = idx >> 3, gc = idx & 7;
        asrc[i] = g_tsum + row * DIM + gc * 4;
        adst[i] = (uint32_t)(row * TM_ASTRIDE + gc * 4) * 4;
    }
    const float* bsrc[8]; uint32_t bdst[8];
    #pragma unroll
    for (int i = 0; i < 8; i++) {
        int idx = t + i * 256;
        int kr = idx >> 6, gc = idx & 63;
        bsrc[i] = W + (size_t)kr * 65536 + n0 + gc * 4;
        bdst[i] = (uint32_t)(TM_A_FLOATS + kr * 264 + gc * 4) * 4;
    }

    #pragma unroll
    for (int c = 0; c < 2; c++) {
        uint32_t sb = sbase + (uint32_t)c * TM_STAGE_BYTES;
        int k0 = c * 32;
        #pragma unroll
        for (int i = 0; i < 2; i++) cp_async16(sb + adst[i], asrc[i] + k0);
        #pragma unroll
        for (int i = 0; i < 8; i++) cp_async16(sb + bdst[i], bsrc[i] + (size_t)k0 * 65536);
        CP_COMMIT();
    }

    float acc[2][8][4];
    #pragma unroll
    for (int i = 0; i < 2; i++)
        #pragma unroll
        for (int j = 0; j < 8; j++)
            #pragma unroll
            for (int q = 0; q < 4; q++) acc[i][j][q] = 0.f;

    for (int c = 0; c < 16; c++) {
        CP_WAIT1();
        __syncthreads();
        const float* sA = smem + (c & 1) * TM_STAGE_FLOATS;
        const float* sB = sA + TM_A_FLOATS;

        #pragma unroll
        for (int ka = 0; ka < 4; ka++) {
            uint32_t af[2][4], bf[4][4];
            #pragma unroll
            for (int ml = 0; ml < 2; ml++) {
                const uint32_t* p0 = (const uint32_t*)(sA
                    + (mw * 32 + ml * 16 + g) * TM_ASTRIDE + ka * 8 + tg);
                af[ml][0] = p0[0];
                af[ml][1] = p0[8 * TM_ASTRIDE];
                af[ml][2] = p0[4];
                af[ml][3] = p0[8 * TM_ASTRIDE + 4];
            }
            #pragma unroll
            for (int pl = 0; pl < 4; pl++) {
                const uint32_t* q0 = (const uint32_t*)(sB
                    + (ka * 8 + tg) * 264 + nw * 64 + pl * 16 + g);
                bf[pl][0] = q0[0];
                bf[pl][1] = q0[4 * 264];
                bf[pl][2] = q0[8];
                bf[pl][3] = q0[4 * 264 + 8];
            }
            #pragma unroll
            for (int ml = 0; ml < 2; ml++) {
                #pragma unroll
                for (int pl = 0; pl < 4; pl++) {
                    mma_tf32(acc[ml][pl*2][0], acc[ml][pl*2][1],
                             acc[ml][pl*2][2], acc[ml][pl*2][3],
                             af[ml][0], af[ml][1], af[ml][2], af[ml][3],
                             bf[pl][0], bf[pl][1]);
                    mma_tf32(acc[ml][pl*2+1][0], acc[ml][pl*2+1][1],
                             acc[ml][pl*2+1][2], acc[ml][pl*2+1][3],
                             af[ml][0], af[ml][1], af[ml][2], af[ml][3],
                             bf[pl][2], bf[pl][3]);
                }
            }
        }
        __syncthreads();

        if (c + 2 < 16) {
            int cc = c + 2;
            uint32_t sb = sbase + (uint32_t)(cc & 1) * TM_STAGE_BYTES;
            int k0 = cc * 32;
            #pragma unroll
            for (int i = 0; i < 2; i++) cp_async16(sb + adst[i], asrc[i] + k0);
            #pragma unroll
            for (int i = 0; i < 8; i++) cp_async16(sb + bdst[i], bsrc[i] + (size_t)k0 * 65536);
            CP_COMMIT();
        }
    }

    #pragma unroll
    for (int ml = 0; ml < 2; ml++) {
        int gm0 = mw * 32 + ml * 16 + g;
        int gm1 = gm0 + 8;
        #pragma unroll
        for (int nl = 0; nl < 8; nl++) {
            int cl = (nw * 8 + nl) * 8 + tg * 2;
            float b0 = sBias[cl], b1 = sBias[cl + 1];
            *(uint32_t*)&g_tmaph[(size_t)gm0 * 65536 + n0 + cl] =
                pack_f16(fmaxf(acc[ml][nl][0] + b0, 0.f),
                         fmaxf(acc[ml][nl][1] + b1, 0.f));
            *(uint32_t*)&g_tmaph[(size_t)gm1 * 65536 + n0 + cl] =
                pack_f16(fmaxf(acc[ml][nl][2] + b0, 0.f),
                         fmaxf(acc[ml][nl][3] + b1, 0.f));
        }
    }
}

// ============================================================
// proj body: fp16 mma k16, 128x128 tile, BK=32, 3-stage, ldmatrix
// 8 warps = 2(M) x 4(N); warp tile 64x32; acc[4][4][4] = 64 regs
// ============================================================
#define PH_STRIDE 40                     // halves per row
#define PH_A_HALVES (128 * PH_STRIDE)    // 5120
#define PH_A_BYTES  (PH_A_HALVES * 2)    // 10240
#define PH_STAGE_HALVES (2 * PH_A_HALVES)           // 10240 (A+B, both 128 rows)
#define PH_STAGE_BYTES (PH_STAGE_HALVES * 2)        // 20480
// fused smem: max(tmap 2*43008+1024 = 87040, proj 3*20480+512 = 61952)
#define PJ_SMEM 87296

__device__ __forceinline__ void proj_body(
    const float* __restrict__ vmask,
    const float* __restrict__ Bv,
    int w, int nx, int my, float* smemf)
{
    char* smem = (char*)smemf;
    uint32_t sbase = smem_to_u32(smem);
    float* sBias = (float*)(smem + 3 * PH_STAGE_BYTES);

    int t = threadIdx.x;
    int wid = t >> 5, lane = t & 31;
    int wm = wid >> 2, wn = wid & 3;
    int g = lane >> 2, tg = lane & 3;

    int m0 = my * 128;
    int n0 = nx * 128;

    const __half* Xh  = g_xh + (size_t)((w < 2) ? 0 : 1) * XSTRIDE;
    const __half* Wth = g_wth + (size_t)w * DIM * DIM;

    if (t < 128) sBias[t] = Bv[n0 + t];

    const __half* asrc[2]; uint32_t adst[2];
    #pragma unroll
    for (int i = 0; i < 2; i++) {
        int idx = t + i * 256;          // 0..511
        int row = idx >> 2, cc = idx & 3;
        asrc[i] = Xh + (size_t)(m0 + row) * DIM + cc * 8;
        adst[i] = (uint32_t)(row * PH_STRIDE + cc * 8) * 2;
    }
    const __half* bsrc[2]; uint32_t bdst[2];
    #pragma unroll
    for (int i = 0; i < 2; i++) {
        int idx = t + i * 256;          // 0..511
        int row = idx >> 2, cc = idx & 3;
        bsrc[i] = Wth + (size_t)(n0 + row) * DIM + cc * 8;
        bdst[i] = (uint32_t)(PH_A_BYTES + (row * PH_STRIDE + cc * 8) * 2);
    }

    uint32_t aoffL = (uint32_t)(((wm * 64 + (lane & 15)) * PH_STRIDE
                     + ((lane >> 4) * 8)) * 2);
    uint32_t boffL = (uint32_t)(PH_A_BYTES
                     + ((wn * 32 + (lane & 7) + ((lane >> 4) << 3)) * PH_STRIDE
                     + (((lane >> 3) & 1) * 8)) * 2);

    #pragma unroll
    for (int c = 0; c < 3; c++) {
        uint32_t sb = sbase + (uint32_t)c * PH_STAGE_BYTES;
        int k0 = c * 32;
        #pragma unroll
        for (int i = 0; i < 2; i++) cp_async16(sb + adst[i], asrc[i] + k0);
        #pragma unroll
        for (int i = 0; i < 2; i++) cp_async16(sb + bdst[i], bsrc[i] + k0);
        CP_COMMIT();
    }

    float acc[4][4][4];
    #pragma unroll
    for (int i = 0; i < 4; i++)
        #pragma unroll
        for (int j = 0; j < 4; j++)
            #pragma unroll
            for (int q = 0; q < 4; q++) acc[i][j][q] = 0.f;

    for (int c = 0; c < 16; c++) {
        CP_WAIT2();
        __syncthreads();
        uint32_t sb = sbase + (uint32_t)(c % 3) * PH_STAGE_BYTES;

        #pragma unroll
        for (int ka = 0; ka < 2; ka++) {
            uint32_t kb = (uint32_t)(ka * 16 * 2);
            uint32_t af[4][4], bf[2][4];
            #pragma unroll
            for (int ml = 0; ml < 4; ml++)
                ldsm_x4(af[ml], sb + aoffL + (uint32_t)(ml * 16 * PH_STRIDE * 2) + kb);
            #pragma unroll
            for (int p2 = 0; p2 < 2; p2++)
                ldsm_x4(bf[p2], sb + boffL + (uint32_t)(p2 * 16 * PH_STRIDE * 2) + kb);
            #pragma unroll
            for (int ml = 0; ml < 4; ml++) {
                #pragma unroll
                for (int p2 = 0; p2 < 2; p2++) {
                    mma_f16(acc[ml][p2*2][0], acc[ml][p2*2][1],
                            acc[ml][p2*2][2], acc[ml][p2*2][3],
                            af[ml][0], af[ml][1], af[ml][2], af[ml][3],
                            bf[p2][0], bf[p2][1]);
                    mma_f16(acc[ml][p2*2+1][0], acc[ml][p2*2+1][1],
                            acc[ml][p2*2+1][2], acc[ml][p2*2+1][3],
                            af[ml][0], af[ml][1], af[ml][2], af[ml][3],
                            bf[p2][2], bf[p2][3]);
                }
            }
        }
        __syncthreads();

        if (c + 3 < 16) {
            int cc = c + 3;
            uint32_t sb2 = sbase + (uint32_t)(cc % 3) * PH_STAGE_BYTES;
            int k0 = cc * 32;
            #pragma unroll
            for (int i = 0; i < 2; i++) cp_async16(sb2 + adst[i], asrc[i] + k0);
            #pragma unroll
            for (int i = 0; i < 2; i++) cp_async16(sb2 + bdst[i], bsrc[i] + k0);
            CP_COMMIT();
        }
    }

    // ---- epilogue: bias + mask -> fp16 ----
    #pragma unroll
    for (int ml = 0; ml < 4; ml++) {
        int gm0 = m0 + wm * 64 + ml * 16 + g;
        int gm1 = gm0 + 8;
        float msk0 = (w < 2) ? vmask[gm0] : 1.0f;
        float msk1 = (w < 2) ? vmask[gm1] : 1.0f;
        int bbi = gm0 >> 8;
        int nn0 = gm0 & 255, nn1 = gm1 & 255;
        #pragma unroll
        for (int nl = 0; nl < 4; nl++) {
            int cl = (wn * 4 + nl) * 8 + tg * 2;
            int cg = n0 + cl;
            int rrel = cg >> 6, d = cg & 63;
            float b0 = sBias[cl], b1 = sBias[cl + 1];
            float x0 = (acc[ml][nl][0] + b0) * msk0;
            float y0 = (acc[ml][nl][1] + b1) * msk0;
            float x1 = (acc[ml][nl][2] + b0) * msk1;
            float y1 = (acc[ml][nl][3] + b1) * msk1;
            if (w < 4) {
                __half* Ph = g_projh + (size_t)w * WSTRIDE;
                *(uint32_t*)&Ph[((size_t)(bbi * RREL + rrel) * NOBJ + nn0) * DK + d]
                    = pack_f16(x0, y0);
                *(uint32_t*)&Ph[((size_t)(bbi * RREL + rrel) * NOBJ + nn1) * DK + d]
                    = pack_f16(x1, y1);
            } else {
                size_t vb = (size_t)(bbi * RREL + rrel) * DK;
                g_vth[(vb + d)     * NOBJ + nn0] = __float2half(x0);
                g_vth[(vb + d + 1) * NOBJ + nn0] = __float2half(y0);
                g_vth[(vb + d)     * NOBJ + nn1] = __float2half(x1);
                g_vth[(vb + d + 1) * NOBJ + nn1] = __float2half(y1);
            }
        }
    }
}

// ============================================================
// Fused proj + tmap kernel: 2816 blocks, every 11th is tmap
// ============================================================
__global__ __launch_bounds__(256, 2) void projtmap_kernel(
    const float* __restrict__ vmask,
    const float* __restrict__ B0, const float* __restrict__ B1,
    const float* __restrict__ B2, const float* __restrict__ B3,
    const float* __restrict__ B4,
    const float* __restrict__ Wt, const float* __restrict__ Bt)
{
    extern __shared__ float smem[];
    int bid = blockIdx.x;
    if ((bid % 11) == 10) {
        tmap_body(Wt, Bt, bid / 11, smem);
    } else {
        int pid = bid - bid / 11;           // 0..2559
        int w   = pid >> 9;
        int rem = pid & 511;
        int my  = rem >> 2;
        int nx  = rem & 3;
        const float* Bv;
        switch (w) {
            case 0: Bv = B0; break; case 1: Bv = B1; break;
            case 2: Bv = B2; break; case 3: Bv = B3; break;
            default: Bv = B4; break;
        }
        proj_body(vmask, Bv, w, nx, my, smem);
    }
}

// ============================================================
// Kernel 4: fused attention — fp16 mma + ldmatrix + scaled fp16 S
// (tmap now read as fp16)
// ============================================================
#define PBH   72
#define TILE_B (64 * PBH * 2)
#define SPH   264
#define SS_B  (4 * TILE_B)
#define INV_B (SS_B + 64 * SPH * 2)
#define ATTN_SMEM (INV_B + 256)
#define S_SCALE 1024.0f

__device__ __forceinline__ void tile_ldg_h(uint4* r, const __half* __restrict__ src)
{
    int t = threadIdx.x;
    #pragma unroll
    for (int p = 0; p < 2; p++) {
        int idx = t + p * 256;
        r[p] = *(const uint4*)(src + idx * 8);
    }
}

__device__ __forceinline__ void tile_sts_h(uint16_t* dst, const uint4* r)
{
    int t = threadIdx.x;
    #pragma unroll
    for (int p = 0; p < 2; p++) {
        int idx = t + p * 256;
        int row = idx >> 3, k8 = (idx & 7) * 8;
        *(uint4*)(dst + row * PBH + k8) = r[p];
    }
}

__global__ __launch_bounds__(256, 2) void attn_kernel(
    const float* __restrict__ vmask, const float* __restrict__ vin,
    float* __restrict__ out)
{
    extern __shared__ char smc[];
    uint16_t* sG1 = (uint16_t*)(smc);
    uint16_t* sK  = (uint16_t*)(smc + TILE_B);
    uint16_t* sX  = (uint16_t*)(smc + 2 * TILE_B);
    uint16_t* sY  = (uint16_t*)(smc + 3 * TILE_B);
    uint16_t* sVt = (uint16_t*)(smc);
    uint16_t* sSb = (uint16_t*)(smc + SS_B);
    float*    sInv = (float*)(smc + INV_B);
    uint32_t sb0 = smem_to_u32(smc);

    int nt = blockIdx.x, r = blockIdx.y, bb = blockIdx.z;
    int t  = threadIdx.x;
    int wid = t >> 5, lane = t & 31;
    int g = lane >> 2, tg = lane & 3;
    int wm = wid >> 2, wn = wid & 3;

    size_t pbase = (size_t)(bb * RREL + r) * NOBJ * DK;
    const __half* G1h = g_projh + 0ull * WSTRIDE + pbase;
    const __half* G2h = g_projh + 1ull * WSTRIDE + pbase;
    const __half* Kh  = g_projh + 2ull * WSTRIDE + pbase;
    const __half* Qh  = g_projh + 3ull * WSTRIDE + pbase;
    const __half* Vth = g_vth + pbase;

    uint32_t aoffT = (uint32_t)(((wm * 32 + (lane & 15)) * PBH
                     + ((lane >> 4) * 8)) * 2);
    uint32_t boffT = (uint32_t)(((wn * 16 + (lane & 7) + ((lane >> 4) << 3)) * PBH
                     + (((lane >> 3) & 1) * 8)) * 2);
    uint32_t aoffS = (uint32_t)(((wm * 32 + (lane & 15)) * SPH
                     + ((lane >> 4) * 8)) * 2);
    uint32_t boffV = (uint32_t)(((wn * 16 + (lane & 7) + ((lane >> 4) << 3)) * SPH
                     + (((lane >> 3) & 1) * 8)) * 2);

    {
        uint4 rg[2], rk[2];
        tile_ldg_h(rg, G1h + nt * 64 * DK);
        tile_ldg_h(rk, Kh  + nt * 64 * DK);
        tile_sts_h(sG1, rg);
        tile_sts_h(sK, rk);
    }

    const __half* tmrow = g_tmaph + ((size_t)bb * NOBJ * NOBJ);

    uint4 px[2], py[2];
    tile_ldg_h(px, G2h);
    tile_ldg_h(py, Qh);

    // ---- score phase ----
    for (int mt = 0; mt < 4; mt++) {
        tile_sts_h(sX, px);
        tile_sts_h(sY, py);
        __syncthreads();

        if (mt < 3) {
            tile_ldg_h(px, G2h + (mt + 1) * 64 * DK);
            tile_ldg_h(py, Qh  + (mt + 1) * 64 * DK);
        }

        float accG[2][2][4], accS[2][2][4];
        #pragma unroll
        for (int i = 0; i < 2; i++)
            #pragma unroll
            for (int j = 0; j < 2; j++)
                #pragma unroll
                for (int q = 0; q < 4; q++) { accG[i][j][q] = 0.f; accS[i][j][q] = 0.f; }

        #pragma unroll
        for (int ks = 0; ks < 4; ks++) {
            uint32_t kb = (uint32_t)(ks * 16 * 2);
            uint32_t aG[2][4], aK[2][4], bX[4], bY[4];
            #pragma unroll
            for (int ma = 0; ma < 2; ma++) {
                uint32_t ao = aoffT + (uint32_t)(ma * 16 * PBH * 2) + kb;
                ldsm_x4(aG[ma], sb0 + ao);
                ldsm_x4(aK[ma], sb0 + TILE_B + ao);
            }
            ldsm_x4(bX, sb0 + 2 * TILE_B + boffT + kb);
            ldsm_x4(bY, sb0 + 3 * TILE_B + boffT + kb);
            #pragma unroll
            for (int ma = 0; ma < 2; ma++) {
                mma_f16(accG[ma][0][0], accG[ma][0][1], accG[ma][0][2], accG[ma][0][3],
                        aG[ma][0], aG[ma][1], aG[ma][2], aG[ma][3], bX[0], bX[1]);
                mma_f16(accG[ma][1][0], accG[ma][1][1], accG[ma][1][2], accG[ma][1][3],
                        aG[ma][0], aG[ma][1], aG[ma][2], aG[ma][3], bX[2], bX[3]);
                mma_f16(accS[ma][0][0], accS[ma][0][1], accS[ma][0][2], accS[ma][0][3],
                        aK[ma][0], aK[ma][1], aK[ma][2], aK[ma][3], bY[0], bY[1]);
                mma_f16(accS[ma][1][0], accS[ma][1][1], accS[ma][1][2], accS[ma][1][3],
                        aK[ma][0], aK[ma][1], aK[ma][2], aK[ma][3], bY[2], bY[3]);
            }
        }

        // epilogue -> sSb (fp16 pairs, scaled)
        #pragma unroll
        for (int ma = 0; ma < 2; ma++) {
            #pragma unroll
            for (int na = 0; na < 2; na++) {
                int col = wn * 16 + na * 8 + tg * 2;
                int mg  = mt * 64 + col;
                float2 vm = *(const float2*)&vmask[bb * NOBJ + mg];
                #pragma unroll
                for (int h = 0; h < 2; h++) {
                    int row = wm * 32 + ma * 16 + g + h * 8;
                    int ng  = nt * 64 + row;
                    __half2 tmh = *(const __half2*)&tmrow[(size_t)ng * NOBJ + mg];
                    float2 tm = __half22float2(tmh);
                    float cG0 = accG[ma][na][h * 2], cG1 = accG[ma][na][h * 2 + 1];
                    float cS0 = accS[ma][na][h * 2], cS1 = accS[ma][na][h * 2 + 1];
                    float wg0 = fmaxf(fmaxf(cG0, 0.f) + tm.x, 1e-6f);
                    float wg1 = fmaxf(fmaxf(cG1, 0.f) + tm.y, 1e-6f);
                    float t0 = wg0 * __expf(fminf(cS0 * 0.125f, 8.f)) * S_SCALE;
                    float t1 = wg1 * __expf(fminf(cS1 * 0.125f, 8.f)) * S_SCALE;
                    t0 = fminf(t0, 60000.f);
                    t1 = fminf(t1, 60000.f);
                    if (vm.x == 0.f) t0 = 0.f;
                    if (vm.y == 0.f) t1 = 0.f;
                    *(uint32_t*)(sSb + row * SPH + mg) = pack_f16(t0, t1);
                }
            }
        }
        __syncthreads();
    }

    // ---- row sums -> 1/sum ----
    {
        int rrow = t >> 2;
        int lanei = t & 3;
        const uint32_t* rp = (const uint32_t*)(sSb + rrow * SPH);
        float sum = 0.f;
        for (int i = lanei; i < 128; i += 4) {
            __half2 h = *(const __half2*)&rp[i];
            float2 f = __half22float2(h);
            sum += f.x + f.y;
        }
        sum += __shfl_xor_sync(0xffffffffu, sum, 1);
        sum += __shfl_xor_sync(0xffffffffu, sum, 2);
        if (lanei == 0) sInv[rrow] = 1.f / fmaxf(sum, 1e-30f);
    }

    // ---- stage V^T ----
    #pragma unroll
    for (int p = 0; p < 8; p++) {
        int idx = t + p * 256;
        int dk = idx >> 5, m16 = (idx & 31) * 8;
        *(uint4*)(sVt + dk * SPH + m16) = *(const uint4*)(Vth + dk * NOBJ + m16);
    }
    __syncthreads();

    // ---- PV ----
    float accO[2][2][4];
    #pragma unroll
    for (int i = 0; i < 2; i++)
        #pragma unroll
        for (int j = 0; j < 2; j++)
            #pragma unroll
            for (int q = 0; q < 4; q++) accO[i][j][q] = 0.f;

    #pragma unroll 4
    for (int ks = 0; ks < 16; ks++) {
        uint32_t kb = (uint32_t)(ks * 16 * 2);
        uint32_t aP[2][4], bV[4];
        #pragma unroll
        for (int ma = 0; ma < 2; ma++)
            ldsm_x4(aP[ma], sb0 + SS_B + aoffS + (uint32_t)(ma * 16 * SPH * 2) + kb);
        ldsm_x4(bV, sb0 + boffV + kb);
        #pragma unroll
        for (int ma = 0; ma < 2; ma++) {
            mma_f16(accO[ma][0][0], accO[ma][0][1], accO[ma][0][2], accO[ma][0][3],
                    aP[ma][0], aP[ma][1], aP[ma][2], aP[ma][3], bV[0], bV[1]);
            mma_f16(accO[ma][1][0], accO[ma][1][1], accO[ma][1][2], accO[ma][1][3],
                    aP[ma][0], aP[ma][1], aP[ma][2], aP[ma][3], bV[2], bV[3]);
        }
    }

    // ---- normalize + residual + store ----
    #pragma unroll
    for (int ma = 0; ma < 2; ma++) {
        #pragma unroll
        for (int h = 0; h < 2; h++) {
            int row = wm * 32 + ma * 16 + g + h * 8;
            int ng  = nt * 64 + row;
            float inv = sInv[row];
            size_t base = ((size_t)bb * NOBJ + ng) * DIM + r * DK;
            #pragma unroll
            for (int na = 0; na < 2; na++) {
                int d = wn * 16 + na * 8 + tg * 2;
                float2 vres = *(const float2*)&vin[base + d];
                float2 o;
                o.x = accO[ma][na][h * 2]     * inv + vres.x;
                o.y = accO[ma][na][h * 2 + 1] * inv + vres.y;
                *(float2*)&out[base + d] = o;
            }
        }
    }
}

// ============================================================
extern "C" void kernel_launch(void* const* d_in, const int* in_sizes, int n_in,
                              void* d_out, int out_size)
{
    const float* v      = (const float*)d_in[0];
    const float* bmat   = (const float*)d_in[1];
    const float* vmask  = (const float*)d_in[2];
    const float* t      = (const float*)d_in[3];
    const float* tmask  = (const float*)d_in[4];
    const float* WG1_w  = (const float*)d_in[5];
    const float* WG1_b  = (const float*)d_in[6];
    const float* WG2_w  = (const float*)d_in[7];
    const float* WG2_b  = (const float*)d_in[8];
    const float* WK_w   = (const float*)d_in[9];
    const float* WK_b   = (const float*)d_in[10];
    const float* WQ_w   = (const float*)d_in[11];
    const float* WQ_b   = (const float*)d_in[12];
    const float* WV_w   = (const float*)d_in[13];
    const float* WV_b   = (const float*)d_in[14];
    const float* tc_w   = (const float*)d_in[15];
    const float* tc_b   = (const float*)d_in[16];
    const float* tmap_w = (const float*)d_in[17];
    const float* tmap_b = (const float*)d_in[18];
    float* out = (float*)d_out;

    cudaFuncSetAttribute(projtmap_kernel, cudaFuncAttributeMaxDynamicSharedMemorySize, PJ_SMEM);
    cudaFuncSetAttribute(projtmap_kernel, cudaFuncAttributePreferredSharedMemoryCarveout, 100);
    cudaFuncSetAttribute(attn_kernel, cudaFuncAttributeMaxDynamicSharedMemorySize, ATTN_SMEM);
    cudaFuncSetAttribute(attn_kernel, cudaFuncAttributePreferredSharedMemoryCarveout, 100);

    prep_kernel<<<64 + 1280 + 8192, 256>>>(
        t, tmask, tc_w, tc_b, v, bmat,
        WG1_w, WG2_w, WK_w, WQ_w, WV_w);
    projtmap_kernel<<<2816, 256, PJ_SMEM>>>(
        vmask, WG1_b, WG2_b, WK_b, WQ_b, WV_b, tmap_w, tmap_b);
    attn_kernel<<<dim3(4, RREL, BSZ), 256, ATTN_SMEM>>>(vmask, v, out);
}

// round 16
// speedup vs baseline: 6.8324x; 1.0717x over previous
#include <cuda_runtime.h>
#include <cuda_fp16.h>
#include <math.h>
#include <stdint.h>

#define BSZ   64
#define NOBJ  256
#define TTOK  32
#define DIM   512
#define RREL  8
#define DK    64

#define WSTRIDE (BSZ*RREL*NOBJ*DK)   // 8,388,608
#define XSTRIDE (16384 * DIM)        // 8,388,608

// ---- static device scratch ----
__device__ __half g_projh[4ull * WSTRIDE];   // G1,G2,K,Q fp16 [b,r,n,dk]
__device__ __half g_vth[1ull * WSTRIDE];     // V^T fp16 [b,r,dk,n]
__device__ __half g_xh[2ull * XSTRIDE];      // fp16 inputs: [0]=b, [1]=v
__device__ __half g_wth[5ull * DIM * DIM];   // fp16 transposed weights [n][k]
__device__ __half g_tmaph[(size_t)BSZ * NOBJ * NOBJ];  // fp16 tmap
__device__ float g_tsum[BSZ * DIM];

__device__ __forceinline__ uint32_t smem_to_u32(const void* smem_ptr) {
    uint32_t addr;
    asm("{ .reg .u64 tmp; cvta.to.shared.u64 tmp, %1; cvt.u32.u64 %0, tmp; }"
        : "=r"(addr) : "l"(smem_ptr));
    return addr;
}

__device__ __forceinline__ void cp_async16(uint32_t dst, const void* src) {
    asm volatile("cp.async.cg.shared.global [%0], [%1], 16;"
                 :: "r"(dst), "l"(src) : "memory");
}
#define CP_COMMIT() asm volatile("cp.async.commit_group;" ::: "memory")
#define CP_WAIT1()  asm volatile("cp.async.wait_group 1;" ::: "memory")

__device__ __forceinline__ void mma_tf32(
    float& d0, float& d1, float& d2, float& d3,
    uint32_t a0, uint32_t a1, uint32_t a2, uint32_t a3,
    uint32_t b0, uint32_t b1)
{
    asm volatile(
        "mma.sync.aligned.m16n8k8.row.col.f32.tf32.tf32.f32 "
        "{%0,%1,%2,%3}, {%4,%5,%6,%7}, {%8,%9}, {%0,%1,%2,%3};"
        : "+f"(d0), "+f"(d1), "+f"(d2), "+f"(d3)
        : "r"(a0), "r"(a1), "r"(a2), "r"(a3), "r"(b0), "r"(b1));
}

__device__ __forceinline__ void mma_f16(
    float& d0, float& d1, float& d2, float& d3,
    uint32_t a0, uint32_t a1, uint32_t a2, uint32_t a3,
    uint32_t b0, uint32_t b1)
{
    asm volatile(
        "mma.sync.aligned.m16n8k16.row.col.f32.f16.f16.f32 "
        "{%0,%1,%2,%3}, {%4,%5,%6,%7}, {%8,%9}, {%0,%1,%2,%3};"
        : "+f"(d0), "+f"(d1), "+f"(d2), "+f"(d3)
        : "r"(a0), "r"(a1), "r"(a2), "r"(a3), "r"(b0), "r"(b1));
}

__device__ __forceinline__ void ldsm_x4(uint32_t* r, uint32_t addr)
{
    asm volatile("ldmatrix.sync.aligned.m8n8.x4.shared.b16 {%0,%1,%2,%3}, [%4];"
        : "=r"(r[0]), "=r"(r[1]), "=r"(r[2]), "=r"(r[3]) : "r"(addr));
}

__device__ __forceinline__ uint32_t pack_f16(float x, float y) {
    __half2 h = __floats2half2_rn(x, y);
    return *(uint32_t*)&h;
}

// ============================================================
// prep kernel: tsum (64) + W transpose/convert (1280)
//              + input fp32->fp16 convert (8192)   total 9536
// ============================================================
__global__ __launch_bounds__(256) void prep_kernel(
    const float* __restrict__ t, const float* __restrict__ tmask,
    const float* __restrict__ tcw, const float* __restrict__ tcb,
    const float* __restrict__ vin, const float* __restrict__ bmat,
    const float* __restrict__ W0, const float* __restrict__ W1,
    const float* __restrict__ W2, const float* __restrict__ W3,
    const float* __restrict__ W4)
{
    __shared__ float ptile[32 * 33];
    __shared__ float score[TTOK];
    int bid = blockIdx.x;
    int tid = threadIdx.x;

    if (bid < 64) {
        int bb = bid;
        const float* tb = t + (size_t)bb * TTOK * DIM;
        int warp = tid >> 5, lane = tid & 31;
        for (int tt = warp * 4; tt < warp * 4 + 4; tt++) {
            float s = 0.f;
            for (int d = lane; d < DIM; d += 32) s += tb[tt * DIM + d] * tcw[d];
            #pragma unroll
            for (int o = 16; o > 0; o >>= 1) s += __shfl_xor_sync(0xffffffffu, s, o);
            if (lane == 0) {
                float m = tmask[bb * TTOK + tt];
                if (m == 0.f) score[tt] = 0.f;
                else {
                    float tc = s * m + tcb[0];
                    score[tt] = (1.f / (1.f + expf(-tc))) * m;
                }
            }
        }
        __syncthreads();
        for (int d = tid; d < DIM; d += 256) {
            float acc = 0.f;
            #pragma unroll
            for (int tt = 0; tt < TTOK; tt++) acc += tb[tt * DIM + d] * score[tt];
            g_tsum[bb * DIM + d] = acc;
        }
    } else if (bid < 64 + 1280) {
        int id = bid - 64;
        int w = id >> 8;
        int tile = id & 255;
        int K0 = (tile >> 4) * 32, N0 = (tile & 15) * 32;
        const float* W;
        switch (w) {
            case 0: W = W0; break; case 1: W = W1; break; case 2: W = W2; break;
            case 3: W = W3; break; default: W = W4; break;
        }
        __half* Wt = g_wth + (size_t)w * DIM * DIM;
        int tx = tid & 31, ty = tid >> 5;
        #pragma unroll
        for (int i = 0; i < 32; i += 8)
            ptile[(ty + i) * 33 + tx] = W[(size_t)(K0 + ty + i) * DIM + N0 + tx];
        __syncthreads();
        #pragma unroll
        for (int i = 0; i < 32; i += 8)
            Wt[(size_t)(N0 + ty + i) * DIM + K0 + tx] = __float2half(ptile[tx * 33 + ty + i]);
    } else {
        int id = bid - 1344;                 // 0..8191
        int tensor = id >> 12;
        int blk = id & 4095;
        const float* src = tensor ? vin : bmat;
        size_t idx8 = ((size_t)blk * 256 + tid) * 8;
        float4 f0 = *(const float4*)(src + idx8);
        float4 f1 = *(const float4*)(src + idx8 + 4);
        uint4 o;
        o.x = pack_f16(f0.x, f0.y);
        o.y = pack_f16(f0.z, f0.w);
        o.z = pack_f16(f1.x, f1.y);
        o.w = pack_f16(f1.z, f1.w);
        *(uint4*)(g_xh + (size_t)tensor * XSTRIDE + idx8) = o;
    }
}

// ============================================================
// tmap body: relu(t_summary @ tmap_w + tmap_b), tf32 mma, 2-stage
// (unchanged from R15)
// ============================================================
#define TM_ASTRIDE 36
#define TM_A_FLOATS (64 * TM_ASTRIDE)
#define TM_STAGE_FLOATS (TM_A_FLOATS + 32 * 264)   // 10752
#define TM_STAGE_BYTES (TM_STAGE_FLOATS * 4)       // 43008

__device__ __forceinline__ void tmap_body(
    const float* __restrict__ W, const float* __restrict__ bias,
    int tm_bid, float* smem)
{
    uint32_t sbase = smem_to_u32(smem);
    float* sBias = smem + 2 * TM_STAGE_FLOATS;

    int t = threadIdx.x;
    int wid = t >> 5, lane = t & 31;
    int mw = wid >> 2, nw = wid & 3;
    int g = lane >> 2, tg = lane & 3;
    int n0 = tm_bid * 256;

    sBias[t] = bias[n0 + t];

    const float* asrc[2]; uint32_t adst[2];
    #pragma unroll
    for (int i = 0; i < 2; i++) {
        int idx = t + i * 256;
        int row = idx >> 3, gc = idx & 7;
        asrc[i] = g_tsum + row * DIM + gc * 4;
        adst[i] = (uint32_t)(row * TM_ASTRIDE + gc * 4) * 4;
    }
    const float* bsrc[8]; uint32_t bdst[8];
    #pragma unroll
    for (int i = 0; i < 8; i++) {
        int idx = t + i * 256;
        int kr = idx >> 6, gc = idx & 63;
        bsrc[i] = W + (size_t)kr * 65536 + n0 + gc * 4;
        bdst[i] = (uint32_t)(TM_A_FLOATS + kr * 264 + gc * 4) * 4;
    }

    #pragma unroll
    for (int c = 0; c < 2; c++) {
        uint32_t sb = sbase + (uint32_t)c * TM_STAGE_BYTES;
        int k0 = c * 32;
        #pragma unroll
        for (int i = 0; i < 2; i++) cp_async16(sb + adst[i], asrc[i] + k0);
        #pragma unroll
        for (int i = 0; i < 8; i++) cp_async16(sb + bdst[i], bsrc[i] + (size_t)k0 * 65536);
        CP_COMMIT();
    }

    float acc[2][8][4];
    #pragma unroll
    for (int i = 0; i < 2; i++)
        #pragma unroll
        for (int j = 0; j < 8; j++)
            #pragma unroll
            for (int q = 0; q < 4; q++) acc[i][j][q] = 0.f;

    for (int c = 0; c < 16; c++) {
        CP_WAIT1();
        __syncthreads();
        const float* sA = smem + (c & 1) * TM_STAGE_FLOATS;
        const float* sB = sA + TM_A_FLOATS;

        #pragma unroll
        for (int ka = 0; ka < 4; ka++) {
            uint32_t af[2][4], bf[4][4];
            #pragma unroll
            for (int ml = 0; ml < 2; ml++) {
                const uint32_t* p0 = (const uint32_t*)(sA
                    + (mw * 32 + ml * 16 + g) * TM_ASTRIDE + ka * 8 + tg);
                af[ml][0] = p0[0];
                af[ml][1] = p0[8 * TM_ASTRIDE];
                af[ml][2] = p0[4];
                af[ml][3] = p0[8 * TM_ASTRIDE + 4];
            }
            #pragma unroll
            for (int pl = 0; pl < 4; pl++) {
                const uint32_t* q0 = (const uint32_t*)(sB
                    + (ka * 8 + tg) * 264 + nw * 64 + pl * 16 + g);
                bf[pl][0] = q0[0];
                bf[pl][1] = q0[4 * 264];
                bf[pl][2] = q0[8];
                bf[pl][3] = q0[4 * 264 + 8];
            }
            #pragma unroll
            for (int ml = 0; ml < 2; ml++) {
                #pragma unroll
                for (int pl = 0; pl < 4; pl++) {
                    mma_tf32(acc[ml][pl*2][0], acc[ml][pl*2][1],
                             acc[ml][pl*2][2], acc[ml][pl*2][3],
                             af[ml][0], af[ml][1], af[ml][2], af[ml][3],
                             bf[pl][0], bf[pl][1]);
                    mma_tf32(acc[ml][pl*2+1][0], acc[ml][pl*2+1][1],
                             acc[ml][pl*2+1][2], acc[ml][pl*2+1][3],
                             af[ml][0], af[ml][1], af[ml][2], af[ml][3],
                             bf[pl][2], bf[pl][3]);
                }
            }
        }
        __syncthreads();

        if (c + 2 < 16) {
            int cc = c + 2;
            uint32_t sb = sbase + (uint32_t)(cc & 1) * TM_STAGE_BYTES;
            int k0 = cc * 32;
            #pragma unroll
            for (int i = 0; i < 2; i++) cp_async16(sb + adst[i], asrc[i] + k0);
            #pragma unroll
            for (int i = 0; i < 8; i++) cp_async16(sb + bdst[i], bsrc[i] + (size_t)k0 * 65536);
            CP_COMMIT();
        }
    }

    #pragma unroll
    for (int ml = 0; ml < 2; ml++) {
        int gm0 = mw * 32 + ml * 16 + g;
        int gm1 = gm0 + 8;
        #pragma unroll
        for (int nl = 0; nl < 8; nl++) {
            int cl = (nw * 8 + nl) * 8 + tg * 2;
            float b0 = sBias[cl], b1 = sBias[cl + 1];
            *(uint32_t*)&g_tmaph[(size_t)gm0 * 65536 + n0 + cl] =
                pack_f16(fmaxf(acc[ml][nl][0] + b0, 0.f),
                         fmaxf(acc[ml][nl][1] + b1, 0.f));
            *(uint32_t*)&g_tmaph[(size_t)gm1 * 65536 + n0 + cl] =
                pack_f16(fmaxf(acc[ml][nl][2] + b0, 0.f),
                         fmaxf(acc[ml][nl][3] + b1, 0.f));
        }
    }
}

// ============================================================
// proj body: fp16 mma k16, 128x128 tile, BK=64, 2-stage, ldmatrix
// 8 warps = 2(M) x 4(N); warp tile 64x32; acc[4][4][4] = 64 regs
// ============================================================
#define PH_STRIDE 72                     // halves per row (64 k + 8 pad)
#define PH_A_HALVES (128 * PH_STRIDE)    // 9216
#define PH_A_BYTES  (PH_A_HALVES * 2)    // 18432
#define PH_STAGE_HALVES (2 * PH_A_HALVES)           // 18432
#define PH_STAGE_BYTES (PH_STAGE_HALVES * 2)        // 36864
// fused smem: max(tmap 2*43008+1024 = 87040, proj 2*36864+512 = 74240)
#define PJ_SMEM 87296

__device__ __forceinline__ void proj_body(
    const float* __restrict__ vmask,
    const float* __restrict__ Bv,
    int w, int nx, int my, float* smemf)
{
    char* smem = (char*)smemf;
    uint32_t sbase = smem_to_u32(smem);
    float* sBias = (float*)(smem + 2 * PH_STAGE_BYTES);

    int t = threadIdx.x;
    int wid = t >> 5, lane = t & 31;
    int wm = wid >> 2, wn = wid & 3;
    int g = lane >> 2, tg = lane & 3;

    int m0 = my * 128;
    int n0 = nx * 128;

    const __half* Xh  = g_xh + (size_t)((w < 2) ? 0 : 1) * XSTRIDE;
    const __half* Wth = g_wth + (size_t)w * DIM * DIM;

    if (t < 128) sBias[t] = Bv[n0 + t];

    // A: 128 rows x 64 halves per chunk -> 4 cp.async/thread
    const __half* asrc[4]; uint32_t adst[4];
    #pragma unroll
    for (int i = 0; i < 4; i++) {
        int idx = t + i * 256;          // 0..1023
        int row = idx >> 3, cc = idx & 7;
        asrc[i] = Xh + (size_t)(m0 + row) * DIM + cc * 8;
        adst[i] = (uint32_t)(row * PH_STRIDE + cc * 8) * 2;
    }
    const __half* bsrc[4]; uint32_t bdst[4];
    #pragma unroll
    for (int i = 0; i < 4; i++) {
        int idx = t + i * 256;
        int row = idx >> 3, cc = idx & 7;
        bsrc[i] = Wth + (size_t)(n0 + row) * DIM + cc * 8;
        bdst[i] = (uint32_t)(PH_A_BYTES + (row * PH_STRIDE + cc * 8) * 2);
    }

    uint32_t aoffL = (uint32_t)(((wm * 64 + (lane & 15)) * PH_STRIDE
                     + ((lane >> 4) * 8)) * 2);
    uint32_t boffL = (uint32_t)(PH_A_BYTES
                     + ((wn * 32 + (lane & 7) + ((lane >> 4) << 3)) * PH_STRIDE
                     + (((lane >> 3) & 1) * 8)) * 2);

    // prologue: stages 0,1 (chunks of 64 k)
    #pragma unroll
    for (int c = 0; c < 2; c++) {
        uint32_t sb = sbase + (uint32_t)c * PH_STAGE_BYTES;
        int k0 = c * 64;
        #pragma unroll
        for (int i = 0; i < 4; i++) cp_async16(sb + adst[i], asrc[i] + k0);
        #pragma unroll
        for (int i = 0; i < 4; i++) cp_async16(sb + bdst[i], bsrc[i] + k0);
        CP_COMMIT();
    }

    float acc[4][4][4];
    #pragma unroll
    for (int i = 0; i < 4; i++)
        #pragma unroll
        for (int j = 0; j < 4; j++)
            #pragma unroll
            for (int q = 0; q < 4; q++) acc[i][j][q] = 0.f;

    for (int c = 0; c < 8; c++) {
        CP_WAIT1();
        __syncthreads();
        uint32_t sb = sbase + (uint32_t)(c & 1) * PH_STAGE_BYTES;

        #pragma unroll
        for (int ka = 0; ka < 4; ka++) {
            uint32_t kb = (uint32_t)(ka * 16 * 2);
            uint32_t af[4][4], bf[2][4];
            #pragma unroll
            for (int ml = 0; ml < 4; ml++)
                ldsm_x4(af[ml], sb + aoffL + (uint32_t)(ml * 16 * PH_STRIDE * 2) + kb);
            #pragma unroll
            for (int p2 = 0; p2 < 2; p2++)
                ldsm_x4(bf[p2], sb + boffL + (uint32_t)(p2 * 16 * PH_STRIDE * 2) + kb);
            #pragma unroll
            for (int ml = 0; ml < 4; ml++) {
                #pragma unroll
                for (int p2 = 0; p2 < 2; p2++) {
                    mma_f16(acc[ml][p2*2][0], acc[ml][p2*2][1],
                            acc[ml][p2*2][2], acc[ml][p2*2][3],
                            af[ml][0], af[ml][1], af[ml][2], af[ml][3],
                            bf[p2][0], bf[p2][1]);
                    mma_f16(acc[ml][p2*2+1][0], acc[ml][p2*2+1][1],
                            acc[ml][p2*2+1][2], acc[ml][p2*2+1][3],
                            af[ml][0], af[ml][1], af[ml][2], af[ml][3],
                            bf[p2][2], bf[p2][3]);
                }
            }
        }
        __syncthreads();

        if (c + 2 < 8) {
            int cc = c + 2;
            uint32_t sb2 = sbase + (uint32_t)(cc & 1) * PH_STAGE_BYTES;
            int k0 = cc * 64;
            #pragma unroll
            for (int i = 0; i < 4; i++) cp_async16(sb2 + adst[i], asrc[i] + k0);
            #pragma unroll
            for (int i = 0; i < 4; i++) cp_async16(sb2 + bdst[i], bsrc[i] + k0);
            CP_COMMIT();
        }
    }

    // ---- epilogue: bias + mask -> fp16 ----
    #pragma unroll
    for (int ml = 0; ml < 4; ml++) {
        int gm0 = m0 + wm * 64 + ml * 16 + g;
        int gm1 = gm0 + 8;
        float msk0 = (w < 2) ? vmask[gm0] : 1.0f;
        float msk1 = (w < 2) ? vmask[gm1] : 1.0f;
        int bbi = gm0 >> 8;
        int nn0 = gm0 & 255, nn1 = gm1 & 255;
        #pragma unroll
        for (int nl = 0; nl < 4; nl++) {
            int cl = (wn * 4 + nl) * 8 + tg * 2;
            int cg = n0 + cl;
            int rrel = cg >> 6, d = cg & 63;
            float b0 = sBias[cl], b1 = sBias[cl + 1];
            float x0 = (acc[ml][nl][0] + b0) * msk0;
            float y0 = (acc[ml][nl][1] + b1) * msk0;
            float x1 = (acc[ml][nl][2] + b0) * msk1;
            float y1 = (acc[ml][nl][3] + b1) * msk1;
            if (w < 4) {
                __half* Ph = g_projh + (size_t)w * WSTRIDE;
                *(uint32_t*)&Ph[((size_t)(bbi * RREL + rrel) * NOBJ + nn0) * DK + d]
                    = pack_f16(x0, y0);
                *(uint32_t*)&Ph[((size_t)(bbi * RREL + rrel) * NOBJ + nn1) * DK + d]
                    = pack_f16(x1, y1);
            } else {
                size_t vb = (size_t)(bbi * RREL + rrel) * DK;
                g_vth[(vb + d)     * NOBJ + nn0] = __float2half(x0);
                g_vth[(vb + d + 1) * NOBJ + nn0] = __float2half(y0);
                g_vth[(vb + d)     * NOBJ + nn1] = __float2half(x1);
                g_vth[(vb + d + 1) * NOBJ + nn1] = __float2half(y1);
            }
        }
    }
}

// ============================================================
// Fused proj + tmap kernel: 2816 blocks, every 11th is tmap
// ============================================================
__global__ __launch_bounds__(256, 2) void projtmap_kernel(
    const float* __restrict__ vmask,
    const float* __restrict__ B0, const float* __restrict__ B1,
    const float* __restrict__ B2, const float* __restrict__ B3,
    const float* __restrict__ B4,
    const float* __restrict__ Wt, const float* __restrict__ Bt)
{
    extern __shared__ float smem[];
    int bid = blockIdx.x;
    if ((bid % 11) == 10) {
        tmap_body(Wt, Bt, bid / 11, smem);
    } else {
        int pid = bid - bid / 11;           // 0..2559
        int w   = pid >> 9;
        int rem = pid & 511;
        int my  = rem >> 2;
        int nx  = rem & 3;
        const float* Bv;
        switch (w) {
            case 0: Bv = B0; break; case 1: Bv = B1; break;
            case 2: Bv = B2; break; case 3: Bv = B3; break;
            default: Bv = B4; break;
        }
        proj_body(vmask, Bv, w, nx, my, smem);
    }
}

// ============================================================
// Kernel 4: fused attention (unchanged from R15)
// ============================================================
#define PBH   72
#define TILE_B (64 * PBH * 2)
#define SPH   264
#define SS_B  (4 * TILE_B)
#define INV_B (SS_B + 64 * SPH * 2)
#define ATTN_SMEM (INV_B + 256)
#define S_SCALE 1024.0f

__device__ __forceinline__ void tile_ldg_h(uint4* r, const __half* __restrict__ src)
{
    int t = threadIdx.x;
    #pragma unroll
    for (int p = 0; p < 2; p++) {
        int idx = t + p * 256;
        r[p] = *(const uint4*)(src + idx * 8);
    }
}

__device__ __forceinline__ void tile_sts_h(uint16_t* dst, const uint4* r)
{
    int t = threadIdx.x;
    #pragma unroll
    for (int p = 0; p < 2; p++) {
        int idx = t + p * 256;
        int row = idx >> 3, k8 = (idx & 7) * 8;
        *(uint4*)(dst + row * PBH + k8) = r[p];
    }
}

__global__ __launch_bounds__(256, 2) void attn_kernel(
    const float* __restrict__ vmask, const float* __restrict__ vin,
    float* __restrict__ out)
{
    extern __shared__ char smc[];
    uint16_t* sG1 = (uint16_t*)(smc);
    uint16_t* sK  = (uint16_t*)(smc + TILE_B);
    uint16_t* sX  = (uint16_t*)(smc + 2 * TILE_B);
    uint16_t* sY  = (uint16_t*)(smc + 3 * TILE_B);
    uint16_t* sVt = (uint16_t*)(smc);
    uint16_t* sSb = (uint16_t*)(smc + SS_B);
    float*    sInv = (float*)(smc + INV_B);
    uint32_t sb0 = smem_to_u32(smc);

    int nt = blockIdx.x, r = blockIdx.y, bb = blockIdx.z;
    int t  = threadIdx.x;
    int wid = t >> 5, lane = t & 31;
    int g = lane >> 2, tg = lane & 3;
    int wm = wid >> 2, wn = wid & 3;

    size_t pbase = (size_t)(bb * RREL + r) * NOBJ * DK;
    const __half* G1h = g_projh + 0ull * WSTRIDE + pbase;
    const __half* G2h = g_projh + 1ull * WSTRIDE + pbase;
    const __half* Kh  = g_projh + 2ull * WSTRIDE + pbase;
    const __half* Qh  = g_projh + 3ull * WSTRIDE + pbase;
    const __half* Vth = g_vth + pbase;

    uint32_t aoffT = (uint32_t)(((wm * 32 + (lane & 15)) * PBH
                     + ((lane >> 4) * 8)) * 2);
    uint32_t boffT = (uint32_t)(((wn * 16 + (lane & 7) + ((lane >> 4) << 3)) * PBH
                     + (((lane >> 3) & 1) * 8)) * 2);
    uint32_t aoffS = (uint32_t)(((wm * 32 + (lane & 15)) * SPH
                     + ((lane >> 4) * 8)) * 2);
    uint32_t boffV = (uint32_t)(((wn * 16 + (lane & 7) + ((lane >> 4) << 3)) * SPH
                     + (((lane >> 3) & 1) * 8)) * 2);

    {
        uint4 rg[2], rk[2];
        tile_ldg_h(rg, G1h + nt * 64 * DK);
        tile_ldg_h(rk, Kh  + nt * 64 * DK);
        tile_sts_h(sG1, rg);
        tile_sts_h(sK, rk);
    }

    const __half* tmrow = g_tmaph + ((size_t)bb * NOBJ * NOBJ);

    uint4 px[2], py[2];
    tile_ldg_h(px, G2h);
    tile_ldg_h(py, Qh);

    // ---- score phase ----
    for (int mt = 0; mt < 4; mt++) {
        tile_sts_h(sX, px);
        tile_sts_h(sY, py);
        __syncthreads();

        if (mt < 3) {
            tile_ldg_h(px, G2h + (mt + 1) * 64 * DK);
            tile_ldg_h(py, Qh  + (mt + 1) * 64 * DK);
        }

        float accG[2][2][4], accS[2][2][4];
        #pragma unroll
        for (int i = 0; i < 2; i++)
            #pragma unroll
            for (int j = 0; j < 2; j++)
                #pragma unroll
                for (int q = 0; q < 4; q++) { accG[i][j][q] = 0.f; accS[i][j][q] = 0.f; }

        #pragma unroll
        for (int ks = 0; ks < 4; ks++) {
            uint32_t kb = (uint32_t)(ks * 16 * 2);
            uint32_t aG[2][4], aK[2][4], bX[4], bY[4];
            #pragma unroll
            for (int ma = 0; ma < 2; ma++) {
                uint32_t ao = aoffT + (uint32_t)(ma * 16 * PBH * 2) + kb;
                ldsm_x4(aG[ma], sb0 + ao);
                ldsm_x4(aK[ma], sb0 + TILE_B + ao);
            }
            ldsm_x4(bX, sb0 + 2 * TILE_B + boffT + kb);
            ldsm_x4(bY, sb0 + 3 * TILE_B + boffT + kb);
            #pragma unroll
            for (int ma = 0; ma < 2; ma++) {
                mma_f16(accG[ma][0][0], accG[ma][0][1], accG[ma][0][2], accG[ma][0][3],
                        aG[ma][0], aG[ma][1], aG[ma][2], aG[ma][3], bX[0], bX[1]);
                mma_f16(accG[ma][1][0], accG[ma][1][1], accG[ma][1][2], accG[ma][1][3],
                        aG[ma][0], aG[ma][1], aG[ma][2], aG[ma][3], bX[2], bX[3]);
                mma_f16(accS[ma][0][0], accS[ma][0][1], accS[ma][0][2], accS[ma][0][3],
                        aK[ma][0], aK[ma][1], aK[ma][2], aK[ma][3], bY[0], bY[1]);
                mma_f16(accS[ma][1][0], accS[ma][1][1], accS[ma][1][2], accS[ma][1][3],
                        aK[ma][0], aK[ma][1], aK[ma][2], aK[ma][3], bY[2], bY[3]);
            }
        }

        #pragma unroll
        for (int ma = 0; ma < 2; ma++) {
            #pragma unroll
            for (int na = 0; na < 2; na++) {
                int col = wn * 16 + na * 8 + tg * 2;
                int mg  = mt * 64 + col;
                float2 vm = *(const float2*)&vmask[bb * NOBJ + mg];
                #pragma unroll
                for (int h = 0; h < 2; h++) {
                    int row = wm * 32 + ma * 16 + g + h * 8;
                    int ng  = nt * 64 + row;
                    __half2 tmh = *(const __half2*)&tmrow[(size_t)ng * NOBJ + mg];
                    float2 tm = __half22float2(tmh);
                    float cG0 = accG[ma][na][h * 2], cG1 = accG[ma][na][h * 2 + 1];
                    float cS0 = accS[ma][na][h * 2], cS1 = accS[ma][na][h * 2 + 1];
                    float wg0 = fmaxf(fmaxf(cG0, 0.f) + tm.x, 1e-6f);
                    float wg1 = fmaxf(fmaxf(cG1, 0.f) + tm.y, 1e-6f);
                    float t0 = wg0 * __expf(fminf(cS0 * 0.125f, 8.f)) * S_SCALE;
                    float t1 = wg1 * __expf(fminf(cS1 * 0.125f, 8.f)) * S_SCALE;
                    t0 = fminf(t0, 60000.f);
                    t1 = fminf(t1, 60000.f);
                    if (vm.x == 0.f) t0 = 0.f;
                    if (vm.y == 0.f) t1 = 0.f;
                    *(uint32_t*)(sSb + row * SPH + mg) = pack_f16(t0, t1);
                }
            }
        }
        __syncthreads();
    }

    // ---- row sums -> 1/sum ----
    {
        int rrow = t >> 2;
        int lanei = t & 3;
        const uint32_t* rp = (const uint32_t*)(sSb + rrow * SPH);
        float sum = 0.f;
        for (int i = lanei; i < 128; i += 4) {
            __half2 h = *(const __half2*)&rp[i];
            float2 f = __half22float2(h);
            sum += f.x + f.y;
        }
        sum += __shfl_xor_sync(0xffffffffu, sum, 1);
        sum += __shfl_xor_sync(0xffffffffu, sum, 2);
        if (lanei == 0) sInv[rrow] = 1.f / fmaxf(sum, 1e-30f);
    }

    // ---- stage V^T ----
    #pragma unroll
    for (int p = 0; p < 8; p++) {
        int idx = t + p * 256;
        int dk = idx >> 5, m16 = (idx & 31) * 8;
        *(uint4*)(sVt + dk * SPH + m16) = *(const uint4*)(Vth + dk * NOBJ + m16);
    }
    __syncthreads();

    // ---- PV ----
    float accO[2][2][4];
    #pragma unroll
    for (int i = 0; i < 2; i++)
        #pragma unroll
        for (int j = 0; j < 2; j++)
            #pragma unroll
            for (int q = 0; q < 4; q++) accO[i][j][q] = 0.f;

    #pragma unroll 4
    for (int ks = 0; ks < 16; ks++) {
        uint32_t kb = (uint32_t)(ks * 16 * 2);
        uint32_t aP[2][4], bV[4];
        #pragma unroll
        for (int ma = 0; ma < 2; ma++)
            ldsm_x4(aP[ma], sb0 + SS_B + aoffS + (uint32_t)(ma * 16 * SPH * 2) + kb);
        ldsm_x4(bV, sb0 + boffV + kb);
        #pragma unroll
        for (int ma = 0; ma < 2; ma++) {
            mma_f16(accO[ma][0][0], accO[ma][0][1], accO[ma][0][2], accO[ma][0][3],
                    aP[ma][0], aP[ma][1], aP[ma][2], aP[ma][3], bV[0], bV[1]);
            mma_f16(accO[ma][1][0], accO[ma][1][1], accO[ma][1][2], accO[ma][1][3],
                    aP[ma][0], aP[ma][1], aP[ma][2], aP[ma][3], bV[2], bV[3]);
        }
    }

    // ---- normalize + residual + store ----
    #pragma unroll
    for (int ma = 0; ma < 2; ma++) {
        #pragma unroll
        for (int h = 0; h < 2; h++) {
            int row = wm * 32 + ma * 16 + g + h * 8;
            int ng  = nt * 64 + row;
            float inv = sInv[row];
            size_t base = ((size_t)bb * NOBJ + ng) * DIM + r * DK;
            #pragma unroll
            for (int na = 0; na < 2; na++) {
                int d = wn * 16 + na * 8 + tg * 2;
                float2 vres = *(const float2*)&vin[base + d];
                float2 o;
                o.x = accO[ma][na][h * 2]     * inv + vres.x;
                o.y = accO[ma][na][h * 2 + 1] * inv + vres.y;
                *(float2*)&out[base + d] = o;
            }
        }
    }
}

// ============================================================
extern "C" void kernel_launch(void* const* d_in, const int* in_sizes, int n_in,
                              void* d_out, int out_size)
{
    const float* v      = (const float*)d_in[0];
    const float* bmat   = (const float*)d_in[1];
    const float* vmask  = (const float*)d_in[2];
    const float* t      = (const float*)d_in[3];
    const float* tmask  = (const float*)d_in[4];
    const float* WG1_w  = (const float*)d_in[5];
    const float* WG1_b  = (const float*)d_in[6];
    const float* WG2_w  = (const float*)d_in[7];
    const float* WG2_b  = (const float*)d_in[8];
    const float* WK_w   = (const float*)d_in[9];
    const float* WK_b   = (const float*)d_in[10];
    const float* WQ_w   = (const float*)d_in[11];
    const float* WQ_b   = (const float*)d_in[12];
    const float* WV_w   = (const float*)d_in[13];
    const float* WV_b   = (const float*)d_in[14];
    const float* tc_w   = (const float*)d_in[15];
    const float* tc_b   = (const float*)d_in[16];
    const float* tmap_w = (const float*)d_in[17];
    const float* tmap_b = (const float*)d_in[18];
    float* out = (float*)d_out;

    cudaFuncSetAttribute(projtmap_kernel, cudaFuncAttributeMaxDynamicSharedMemorySize, PJ_SMEM);
    cudaFuncSetAttribute(projtmap_kernel, cudaFuncAttributePreferredSharedMemoryCarveout, 100);
    cudaFuncSetAttribute(attn_kernel, cudaFuncAttributeMaxDynamicSharedMemorySize, ATTN_SMEM);
    cudaFuncSetAttribute(attn_kernel, cudaFuncAttributePreferredSharedMemoryCarveout, 100);

    prep_kernel<<<64 + 1280 + 8192, 256>>>(
        t, tmask, tc_w, tc_b, v, bmat,
        WG1_w, WG2_w, WK_w, WQ_w, WV_w);
    projtmap_kernel<<<2816, 256, PJ_SMEM>>>(
        vmask, WG1_b, WG2_b, WK_b, WQ_b, WV_b, tmap_w, tmap_b);
    attn_kernel<<<dim3(4, RREL, BSZ), 256, ATTN_SMEM>>>(vmask, v, out);
}

// round 17
// speedup vs baseline: 7.0733x; 1.0353x over previous
#include <cuda_runtime.h>
#include <cuda_fp16.h>
#include <math.h>
#include <stdint.h>

#define BSZ   64
#define NOBJ  256
#define TTOK  32
#define DIM   512
#define RREL  8
#define DK    64

#define WSTRIDE (BSZ*RREL*NOBJ*DK)   // 8,388,608
#define XSTRIDE (16384 * DIM)        // 8,388,608

// ---- static device scratch ----
__device__ __half g_projh[4ull * WSTRIDE];   // G1,G2,K,Q fp16 [b,r,n,dk]
__device__ __half g_vth[1ull * WSTRIDE];     // V^T fp16 [b,r,dk,n]
__device__ __half g_xh[2ull * XSTRIDE];      // fp16 inputs: [0]=b, [1]=v
__device__ __half g_wth[5ull * DIM * DIM];   // fp16 transposed weights [n][k]
__device__ __half g_tmaph[(size_t)BSZ * NOBJ * NOBJ];  // fp16 tmap
__device__ float g_tsum[BSZ * DIM];

__device__ __forceinline__ uint32_t smem_to_u32(const void* smem_ptr) {
    uint32_t addr;
    asm("{ .reg .u64 tmp; cvta.to.shared.u64 tmp, %1; cvt.u32.u64 %0, tmp; }"
        : "=r"(addr) : "l"(smem_ptr));
    return addr;
}

__device__ __forceinline__ void cp_async16(uint32_t dst, const void* src) {
    asm volatile("cp.async.cg.shared.global [%0], [%1], 16;"
                 :: "r"(dst), "l"(src) : "memory");
}
#define CP_COMMIT() asm volatile("cp.async.commit_group;" ::: "memory")
#define CP_WAIT0()  asm volatile("cp.async.wait_group 0;" ::: "memory")
#define CP_WAIT1()  asm volatile("cp.async.wait_group 1;" ::: "memory")
#define CP_WAIT2()  asm volatile("cp.async.wait_group 2;" ::: "memory")

__device__ __forceinline__ void mma_tf32(
    float& d0, float& d1, float& d2, float& d3,
    uint32_t a0, uint32_t a1, uint32_t a2, uint32_t a3,
    uint32_t b0, uint32_t b1)
{
    asm volatile(
        "mma.sync.aligned.m16n8k8.row.col.f32.tf32.tf32.f32 "
        "{%0,%1,%2,%3}, {%4,%5,%6,%7}, {%8,%9}, {%0,%1,%2,%3};"
        : "+f"(d0), "+f"(d1), "+f"(d2), "+f"(d3)
        : "r"(a0), "r"(a1), "r"(a2), "r"(a3), "r"(b0), "r"(b1));
}

__device__ __forceinline__ void mma_f16(
    float& d0, float& d1, float& d2, float& d3,
    uint32_t a0, uint32_t a1, uint32_t a2, uint32_t a3,
    uint32_t b0, uint32_t b1)
{
    asm volatile(
        "mma.sync.aligned.m16n8k16.row.col.f32.f16.f16.f32 "
        "{%0,%1,%2,%3}, {%4,%5,%6,%7}, {%8,%9}, {%0,%1,%2,%3};"
        : "+f"(d0), "+f"(d1), "+f"(d2), "+f"(d3)
        : "r"(a0), "r"(a1), "r"(a2), "r"(a3), "r"(b0), "r"(b1));
}

__device__ __forceinline__ void ldsm_x4(uint32_t* r, uint32_t addr)
{
    asm volatile("ldmatrix.sync.aligned.m8n8.x4.shared.b16 {%0,%1,%2,%3}, [%4];"
        : "=r"(r[0]), "=r"(r[1]), "=r"(r[2]), "=r"(r[3]) : "r"(addr));
}

__device__ __forceinline__ uint32_t pack_f16(float x, float y) {
    __half2 h = __floats2half2_rn(x, y);
    return *(uint32_t*)&h;
}

// ============================================================
// prep kernel: tsum (64) + W transpose/convert (1280)
//              + input fp32->fp16 convert (8192)   total 9536
// ============================================================
__global__ __launch_bounds__(256) void prep_kernel(
    const float* __restrict__ t, const float* __restrict__ tmask,
    const float* __restrict__ tcw, const float* __restrict__ tcb,
    const float* __restrict__ vin, const float* __restrict__ bmat,
    const float* __restrict__ W0, const float* __restrict__ W1,
    const float* __restrict__ W2, const float* __restrict__ W3,
    const float* __restrict__ W4)
{
    __shared__ float ptile[32 * 33];
    __shared__ float score[TTOK];
    int bid = blockIdx.x;
    int tid = threadIdx.x;

    if (bid < 64) {
        int bb = bid;
        const float* tb = t + (size_t)bb * TTOK * DIM;
        int warp = tid >> 5, lane = tid & 31;
        for (int tt = warp * 4; tt < warp * 4 + 4; tt++) {
            float s = 0.f;
            for (int d = lane; d < DIM; d += 32) s += tb[tt * DIM + d] * tcw[d];
            #pragma unroll
            for (int o = 16; o > 0; o >>= 1) s += __shfl_xor_sync(0xffffffffu, s, o);
            if (lane == 0) {
                float m = tmask[bb * TTOK + tt];
                if (m == 0.f) score[tt] = 0.f;
                else {
                    float tc = s * m + tcb[0];
                    score[tt] = (1.f / (1.f + expf(-tc))) * m;
                }
            }
        }
        __syncthreads();
        for (int d = tid; d < DIM; d += 256) {
            float acc = 0.f;
            #pragma unroll
            for (int tt = 0; tt < TTOK; tt++) acc += tb[tt * DIM + d] * score[tt];
            g_tsum[bb * DIM + d] = acc;
        }
    } else if (bid < 64 + 1280) {
        int id = bid - 64;
        int w = id >> 8;
        int tile = id & 255;
        int K0 = (tile >> 4) * 32, N0 = (tile & 15) * 32;
        const float* W;
        switch (w) {
            case 0: W = W0; break; case 1: W = W1; break; case 2: W = W2; break;
            case 3: W = W3; break; default: W = W4; break;
        }
        __half* Wt = g_wth + (size_t)w * DIM * DIM;
        int tx = tid & 31, ty = tid >> 5;
        #pragma unroll
        for (int i = 0; i < 32; i += 8)
            ptile[(ty + i) * 33 + tx] = W[(size_t)(K0 + ty + i) * DIM + N0 + tx];
        __syncthreads();
        #pragma unroll
        for (int i = 0; i < 32; i += 8)
            Wt[(size_t)(N0 + ty + i) * DIM + K0 + tx] = __float2half(ptile[tx * 33 + ty + i]);
    } else {
        int id = bid - 1344;                 // 0..8191
        int tensor = id >> 12;
        int blk = id & 4095;
        const float* src = tensor ? vin : bmat;
        size_t idx8 = ((size_t)blk * 256 + tid) * 8;
        float4 f0 = *(const float4*)(src + idx8);
        float4 f1 = *(const float4*)(src + idx8 + 4);
        uint4 o;
        o.x = pack_f16(f0.x, f0.y);
        o.y = pack_f16(f0.z, f0.w);
        o.z = pack_f16(f1.x, f1.y);
        o.w = pack_f16(f1.z, f1.w);
        *(uint4*)(g_xh + (size_t)tensor * XSTRIDE + idx8) = o;
    }
}

// ============================================================
// tmap body: relu(t_summary @ tmap_w + tmap_b), tf32 mma, 2-stage
// N=128 per block (512 blocks)
// ============================================================
#define TM_ASTRIDE 36
#define TM_BSTRIDE 132
#define TM_A_FLOATS (64 * TM_ASTRIDE)                // 2304
#define TM_STAGE_FLOATS (TM_A_FLOATS + 32 * TM_BSTRIDE)  // 6528
#define TM_STAGE_BYTES (TM_STAGE_FLOATS * 4)             // 26112

__device__ __forceinline__ void tmap_body(
    const float* __restrict__ W, const float* __restrict__ bias,
    int tm_bid, float* smem)
{
    uint32_t sbase = smem_to_u32(smem);
    float* sBias = smem + 2 * TM_STAGE_FLOATS;

    int t = threadIdx.x;
    int wid = t >> 5, lane = t & 31;
    int mw = wid >> 2, nw = wid & 3;
    int g = lane >> 2, tg = lane & 3;
    int n0 = tm_bid * 128;

    if (t < 128) sBias[t] = bias[n0 + t];

    const float* asrc[2]; uint32_t adst[2];
    #pragma unroll
    for (int i = 0; i < 2; i++) {
        int idx = t + i * 256;
        int row = idx >> 3, gc = idx & 7;
        asrc[i] = g_tsum + row * DIM + gc * 4;
        adst[i] = (uint32_t)(row * TM_ASTRIDE + gc * 4) * 4;
    }
    const float* bsrc[4]; uint32_t bdst[4];
    #pragma unroll
    for (int i = 0; i < 4; i++) {
        int idx = t + i * 256;          // 0..1023
        int kr = idx >> 5, gc = idx & 31;
        bsrc[i] = W + (size_t)kr * 65536 + n0 + gc * 4;
        bdst[i] = (uint32_t)(TM_A_FLOATS + kr * TM_BSTRIDE + gc * 4) * 4;
    }

    #pragma unroll
    for (int c = 0; c < 2; c++) {
        uint32_t sb = sbase + (uint32_t)c * TM_STAGE_BYTES;
        int k0 = c * 32;
        #pragma unroll
        for (int i = 0; i < 2; i++) cp_async16(sb + adst[i], asrc[i] + k0);
        #pragma unroll
        for (int i = 0; i < 4; i++) cp_async16(sb + bdst[i], bsrc[i] + (size_t)k0 * 65536);
        CP_COMMIT();
    }

    float acc[2][4][4];
    #pragma unroll
    for (int i = 0; i < 2; i++)
        #pragma unroll
        for (int j = 0; j < 4; j++)
            #pragma unroll
            for (int q = 0; q < 4; q++) acc[i][j][q] = 0.f;

    for (int c = 0; c < 16; c++) {
        CP_WAIT1();
        __syncthreads();
        const float* sA = smem + (c & 1) * TM_STAGE_FLOATS;
        const float* sB = sA + TM_A_FLOATS;

        #pragma unroll
        for (int ka = 0; ka < 4; ka++) {
            uint32_t af[2][4], bf[2][4];
            #pragma unroll
            for (int ml = 0; ml < 2; ml++) {
                const uint32_t* p0 = (const uint32_t*)(sA
                    + (mw * 32 + ml * 16 + g) * TM_ASTRIDE + ka * 8 + tg);
                af[ml][0] = p0[0];
                af[ml][1] = p0[8 * TM_ASTRIDE];
                af[ml][2] = p0[4];
                af[ml][3] = p0[8 * TM_ASTRIDE + 4];
            }
            #pragma unroll
            for (int pl = 0; pl < 2; pl++) {
                const uint32_t* q0 = (const uint32_t*)(sB
                    + (ka * 8 + tg) * TM_BSTRIDE + nw * 32 + pl * 16 + g);
                bf[pl][0] = q0[0];
                bf[pl][1] = q0[4 * TM_BSTRIDE];
                bf[pl][2] = q0[8];
                bf[pl][3] = q0[4 * TM_BSTRIDE + 8];
            }
            #pragma unroll
            for (int ml = 0; ml < 2; ml++) {
                #pragma unroll
                for (int pl = 0; pl < 2; pl++) {
                    mma_tf32(acc[ml][pl*2][0], acc[ml][pl*2][1],
                             acc[ml][pl*2][2], acc[ml][pl*2][3],
                             af[ml][0], af[ml][1], af[ml][2], af[ml][3],
                             bf[pl][0], bf[pl][1]);
                    mma_tf32(acc[ml][pl*2+1][0], acc[ml][pl*2+1][1],
                             acc[ml][pl*2+1][2], acc[ml][pl*2+1][3],
                             af[ml][0], af[ml][1], af[ml][2], af[ml][3],
                             bf[pl][2], bf[pl][3]);
                }
            }
        }
        __syncthreads();

        if (c + 2 < 16) {
            int cc = c + 2;
            uint32_t sb = sbase + (uint32_t)(cc & 1) * TM_STAGE_BYTES;
            int k0 = cc * 32;
            #pragma unroll
            for (int i = 0; i < 2; i++) cp_async16(sb + adst[i], asrc[i] + k0);
            #pragma unroll
            for (int i = 0; i < 4; i++) cp_async16(sb + bdst[i], bsrc[i] + (size_t)k0 * 65536);
            CP_COMMIT();
        }
    }

    #pragma unroll
    for (int ml = 0; ml < 2; ml++) {
        int gm0 = mw * 32 + ml * 16 + g;
        int gm1 = gm0 + 8;
        #pragma unroll
        for (int nl = 0; nl < 4; nl++) {
            int cl = (nw * 4 + nl) * 8 + tg * 2;
            float b0 = sBias[cl], b1 = sBias[cl + 1];
            *(uint32_t*)&g_tmaph[(size_t)gm0 * 65536 + n0 + cl] =
                pack_f16(fmaxf(acc[ml][nl][0] + b0, 0.f),
                         fmaxf(acc[ml][nl][1] + b1, 0.f));
            *(uint32_t*)&g_tmaph[(size_t)gm1 * 65536 + n0 + cl] =
                pack_f16(fmaxf(acc[ml][nl][2] + b0, 0.f),
                         fmaxf(acc[ml][nl][3] + b1, 0.f));
        }
    }
}

// ============================================================
// proj body: fp16 mma k16, 128x128 tile, BK=64, 3-stage, ldmatrix
// ============================================================
#define PH_STRIDE 72
#define PH_A_HALVES (128 * PH_STRIDE)    // 9216
#define PH_A_BYTES  (PH_A_HALVES * 2)    // 18432
#define PH_STAGE_BYTES (2 * PH_A_BYTES)  // 36864
// fused smem: max(tmap 2*26112+512=52736, proj 3*36864+512=111104)
#define PJ_SMEM 111104

__device__ __forceinline__ void proj_body(
    const float* __restrict__ vmask,
    const float* __restrict__ Bv,
    int w, int nx, int my, float* smemf)
{
    char* smem = (char*)smemf;
    uint32_t sbase = smem_to_u32(smem);
    float* sBias = (float*)(smem + 3 * PH_STAGE_BYTES);

    int t = threadIdx.x;
    int wid = t >> 5, lane = t & 31;
    int wm = wid >> 2, wn = wid & 3;
    int g = lane >> 2, tg = lane & 3;

    int m0 = my * 128;
    int n0 = nx * 128;

    const __half* Xh  = g_xh + (size_t)((w < 2) ? 0 : 1) * XSTRIDE;
    const __half* Wth = g_wth + (size_t)w * DIM * DIM;

    if (t < 128) sBias[t] = Bv[n0 + t];

    const __half* asrc[4]; uint32_t adst[4];
    #pragma unroll
    for (int i = 0; i < 4; i++) {
        int idx = t + i * 256;
        int row = idx >> 3, cc = idx & 7;
        asrc[i] = Xh + (size_t)(m0 + row) * DIM + cc * 8;
        adst[i] = (uint32_t)(row * PH_STRIDE + cc * 8) * 2;
    }
    const __half* bsrc[4]; uint32_t bdst[4];
    #pragma unroll
    for (int i = 0; i < 4; i++) {
        int idx = t + i * 256;
        int row = idx >> 3, cc = idx & 7;
        bsrc[i] = Wth + (size_t)(n0 + row) * DIM + cc * 8;
        bdst[i] = (uint32_t)(PH_A_BYTES + (row * PH_STRIDE + cc * 8) * 2);
    }

    uint32_t aoffL = (uint32_t)(((wm * 64 + (lane & 15)) * PH_STRIDE
                     + ((lane >> 4) * 8)) * 2);
    uint32_t boffL = (uint32_t)(PH_A_BYTES
                     + ((wn * 32 + (lane & 7) + ((lane >> 4) << 3)) * PH_STRIDE
                     + (((lane >> 3) & 1) * 8)) * 2);

    #pragma unroll
    for (int c = 0; c < 3; c++) {
        uint32_t sb = sbase + (uint32_t)c * PH_STAGE_BYTES;
        int k0 = c * 64;
        #pragma unroll
        for (int i = 0; i < 4; i++) cp_async16(sb + adst[i], asrc[i] + k0);
        #pragma unroll
        for (int i = 0; i < 4; i++) cp_async16(sb + bdst[i], bsrc[i] + k0);
        CP_COMMIT();
    }

    float acc[4][4][4];
    #pragma unroll
    for (int i = 0; i < 4; i++)
        #pragma unroll
        for (int j = 0; j < 4; j++)
            #pragma unroll
            for (int q = 0; q < 4; q++) acc[i][j][q] = 0.f;

    for (int c = 0; c < 8; c++) {
        CP_WAIT2();
        __syncthreads();
        uint32_t sb = sbase + (uint32_t)(c % 3) * PH_STAGE_BYTES;

        #pragma unroll
        for (int ka = 0; ka < 4; ka++) {
            uint32_t kb = (uint32_t)(ka * 16 * 2);
            uint32_t af[4][4], bf[2][4];
            #pragma unroll
            for (int ml = 0; ml < 4; ml++)
                ldsm_x4(af[ml], sb + aoffL + (uint32_t)(ml * 16 * PH_STRIDE * 2) + kb);
            #pragma unroll
            for (int p2 = 0; p2 < 2; p2++)
                ldsm_x4(bf[p2], sb + boffL + (uint32_t)(p2 * 16 * PH_STRIDE * 2) + kb);
            #pragma unroll
            for (int ml = 0; ml < 4; ml++) {
                #pragma unroll
                for (int p2 = 0; p2 < 2; p2++) {
                    mma_f16(acc[ml][p2*2][0], acc[ml][p2*2][1],
                            acc[ml][p2*2][2], acc[ml][p2*2][3],
                            af[ml][0], af[ml][1], af[ml][2], af[ml][3],
                            bf[p2][0], bf[p2][1]);
                    mma_f16(acc[ml][p2*2+1][0], acc[ml][p2*2+1][1],
                            acc[ml][p2*2+1][2], acc[ml][p2*2+1][3],
                            af[ml][0], af[ml][1], af[ml][2], af[ml][3],
                            bf[p2][2], bf[p2][3]);
                }
            }
        }
        __syncthreads();

        if (c + 3 < 8) {
            int cc = c + 3;
            uint32_t sb2 = sbase + (uint32_t)(cc % 3) * PH_STAGE_BYTES;
            int k0 = cc * 64;
            #pragma unroll
            for (int i = 0; i < 4; i++) cp_async16(sb2 + adst[i], asrc[i] + k0);
            #pragma unroll
            for (int i = 0; i < 4; i++) cp_async16(sb2 + bdst[i], bsrc[i] + k0);
            CP_COMMIT();
        }
    }

    // ---- epilogue: bias + mask -> fp16 ----
    #pragma unroll
    for (int ml = 0; ml < 4; ml++) {
        int gm0 = m0 + wm * 64 + ml * 16 + g;
        int gm1 = gm0 + 8;
        float msk0 = (w < 2) ? vmask[gm0] : 1.0f;
        float msk1 = (w < 2) ? vmask[gm1] : 1.0f;
        int bbi = gm0 >> 8;
        int nn0 = gm0 & 255, nn1 = gm1 & 255;
        #pragma unroll
        for (int nl = 0; nl < 4; nl++) {
            int cl = (wn * 4 + nl) * 8 + tg * 2;
            int cg = n0 + cl;
            int rrel = cg >> 6, d = cg & 63;
            float b0 = sBias[cl], b1 = sBias[cl + 1];
            float x0 = (acc[ml][nl][0] + b0) * msk0;
            float y0 = (acc[ml][nl][1] + b1) * msk0;
            float x1 = (acc[ml][nl][2] + b0) * msk1;
            float y1 = (acc[ml][nl][3] + b1) * msk1;
            if (w < 4) {
                __half* Ph = g_projh + (size_t)w * WSTRIDE;
                *(uint32_t*)&Ph[((size_t)(bbi * RREL + rrel) * NOBJ + nn0) * DK + d]
                    = pack_f16(x0, y0);
                *(uint32_t*)&Ph[((size_t)(bbi * RREL + rrel) * NOBJ + nn1) * DK + d]
                    = pack_f16(x1, y1);
            } else {
                size_t vb = (size_t)(bbi * RREL + rrel) * DK;
                g_vth[(vb + d)     * NOBJ + nn0] = __float2half(x0);
                g_vth[(vb + d + 1) * NOBJ + nn0] = __float2half(y0);
                g_vth[(vb + d)     * NOBJ + nn1] = __float2half(x1);
                g_vth[(vb + d + 1) * NOBJ + nn1] = __float2half(y1);
            }
        }
    }
}

// ============================================================
// Fused proj + tmap kernel: 3072 blocks, every 6th is tmap (512)
// ============================================================
__global__ __launch_bounds__(256, 2) void projtmap_kernel(
    const float* __restrict__ vmask,
    const float* __restrict__ B0, const float* __restrict__ B1,
    const float* __restrict__ B2, const float* __restrict__ B3,
    const float* __restrict__ B4,
    const float* __restrict__ Wt, const float* __restrict__ Bt)
{
    extern __shared__ float smem[];
    int bid = blockIdx.x;
    if ((bid % 6) == 5) {
        tmap_body(Wt, Bt, bid / 6, smem);
    } else {
        int pid = bid - (bid + 1) / 6;      // 0..2559
        int w   = pid >> 9;
        int rem = pid & 511;
        int my  = rem >> 2;
        int nx  = rem & 3;
        const float* Bv;
        switch (w) {
            case 0: Bv = B0; break; case 1: Bv = B1; break;
            case 2: Bv = B2; break; case 3: Bv = B3; break;
            default: Bv = B4; break;
        }
        proj_body(vmask, Bv, w, nx, my, smem);
    }
}

// ============================================================
// Kernel 4: fused attention — cp.async pipeline, fp16 mma, ldmatrix
// smem: G1,K + 3x(X,Y) fp16 tiles (8*9216=73728), S fp16 (33792),
//       Vt overlay, inv fp32.  107.8 KB, 2 blocks/SM
// ============================================================
#define PBH   72
#define TILE_B (64 * PBH * 2)            // 9216
#define SPH   264
#define SS_B  (8 * TILE_B)               // 73728
#define INV_B (SS_B + 64 * SPH * 2)      // 107520
#define ATTN_SMEM (INV_B + 256)          // 107776
#define S_SCALE 1024.0f

// cp.async a 64x64 fp16 tile (contiguous src) into dst (stride PBH)
__device__ __forceinline__ void tile_cp(uint32_t dst, const __half* __restrict__ src)
{
    int t = threadIdx.x;
    #pragma unroll
    for (int p = 0; p < 2; p++) {
        int idx = t + p * 256;
        int row = idx >> 3, k8 = (idx & 7) * 8;
        cp_async16(dst + (uint32_t)(row * PBH + k8) * 2, src + idx * 8);
    }
}

__global__ __launch_bounds__(256, 2) void attn_kernel(
    const float* __restrict__ vmask, const float* __restrict__ vin,
    float* __restrict__ out)
{
    extern __shared__ char smc[];
    uint16_t* sVt = (uint16_t*)(smc);            // overlay (PV phase)
    uint16_t* sSb = (uint16_t*)(smc + SS_B);
    float*    sInv = (float*)(smc + INV_B);
    uint32_t sb0 = smem_to_u32(smc);

    int nt = blockIdx.x, r = blockIdx.y, bb = blockIdx.z;
    int t  = threadIdx.x;
    int wid = t >> 5, lane = t & 31;
    int g = lane >> 2, tg = lane & 3;
    int wm = wid >> 2, wn = wid & 3;

    size_t pbase = (size_t)(bb * RREL + r) * NOBJ * DK;
    const __half* G1h = g_projh + 0ull * WSTRIDE + pbase;
    const __half* G2h = g_projh + 1ull * WSTRIDE + pbase;
    const __half* Kh  = g_projh + 2ull * WSTRIDE + pbase;
    const __half* Qh  = g_projh + 3ull * WSTRIDE + pbase;
    const __half* Vth = g_vth + pbase;

    uint32_t aoffT = (uint32_t)(((wm * 32 + (lane & 15)) * PBH
                     + ((lane >> 4) * 8)) * 2);
    uint32_t boffT = (uint32_t)(((wn * 16 + (lane & 7) + ((lane >> 4) << 3)) * PBH
                     + (((lane >> 3) & 1) * 8)) * 2);
    uint32_t aoffS = (uint32_t)(((wm * 32 + (lane & 15)) * SPH
                     + ((lane >> 4) * 8)) * 2);
    uint32_t boffV = (uint32_t)(((wn * 16 + (lane & 7) + ((lane >> 4) << 3)) * SPH
                     + (((lane >> 3) & 1) * 8)) * 2);

    // prologue: group0 = {G1, K, X0, Y0}; group1 = {X1,Y1}; group2 = {X2,Y2}
    tile_cp(sb0,              G1h + nt * 64 * DK);
    tile_cp(sb0 + TILE_B,     Kh  + nt * 64 * DK);
    tile_cp(sb0 + 2 * TILE_B, G2h);
    tile_cp(sb0 + 5 * TILE_B, Qh);
    CP_COMMIT();
    tile_cp(sb0 + 3 * TILE_B, G2h + 64 * DK);
    tile_cp(sb0 + 6 * TILE_B, Qh  + 64 * DK);
    CP_COMMIT();
    tile_cp(sb0 + 4 * TILE_B, G2h + 128 * DK);
    tile_cp(sb0 + 7 * TILE_B, Qh  + 128 * DK);
    CP_COMMIT();

    const __half* tmrow = g_tmaph + ((size_t)bb * NOBJ * NOBJ);

    // ---- score phase (1 sync per mt) ----
    #pragma unroll
    for (int mt = 0; mt < 4; mt++) {
        if (mt == 0)      CP_WAIT2();
        else if (mt == 3) CP_WAIT0();
        else              CP_WAIT1();
        __syncthreads();

        if (mt == 1) {   // issue XY3 into buffer 0 (read finished at mt0)
            tile_cp(sb0 + 2 * TILE_B, G2h + 192 * DK);
            tile_cp(sb0 + 5 * TILE_B, Qh  + 192 * DK);
            CP_COMMIT();
        }

        uint32_t xb = sb0 + (uint32_t)(2 + (mt % 3)) * TILE_B;
        uint32_t yb = sb0 + (uint32_t)(5 + (mt % 3)) * TILE_B;

        float accG[2][2][4], accS[2][2][4];
        #pragma unroll
        for (int i = 0; i < 2; i++)
            #pragma unroll
            for (int j = 0; j < 2; j++)
                #pragma unroll
                for (int q = 0; q < 4; q++) { accG[i][j][q] = 0.f; accS[i][j][q] = 0.f; }

        #pragma unroll
        for (int ks = 0; ks < 4; ks++) {
            uint32_t kb = (uint32_t)(ks * 16 * 2);
            uint32_t aG[2][4], aK[2][4], bX[4], bY[4];
            #pragma unroll
            for (int ma = 0; ma < 2; ma++) {
                uint32_t ao = aoffT + (uint32_t)(ma * 16 * PBH * 2) + kb;
                ldsm_x4(aG[ma], sb0 + ao);
                ldsm_x4(aK[ma], sb0 + TILE_B + ao);
            }
            ldsm_x4(bX, xb + boffT + kb);
            ldsm_x4(bY, yb + boffT + kb);
            #pragma unroll
            for (int ma = 0; ma < 2; ma++) {
                mma_f16(accG[ma][0][0], accG[ma][0][1], accG[ma][0][2], accG[ma][0][3],
                        aG[ma][0], aG[ma][1], aG[ma][2], aG[ma][3], bX[0], bX[1]);
                mma_f16(accG[ma][1][0], accG[ma][1][1], accG[ma][1][2], accG[ma][1][3],
                        aG[ma][0], aG[ma][1], aG[ma][2], aG[ma][3], bX[2], bX[3]);
                mma_f16(accS[ma][0][0], accS[ma][0][1], accS[ma][0][2], accS[ma][0][3],
                        aK[ma][0], aK[ma][1], aK[ma][2], aK[ma][3], bY[0], bY[1]);
                mma_f16(accS[ma][1][0], accS[ma][1][1], accS[ma][1][2], accS[ma][1][3],
                        aK[ma][0], aK[ma][1], aK[ma][2], aK[ma][3], bY[2], bY[3]);
            }
        }

        // epilogue -> sSb (fp16 pairs, scaled)
        #pragma unroll
        for (int ma = 0; ma < 2; ma++) {
            #pragma unroll
            for (int na = 0; na < 2; na++) {
                int col = wn * 16 + na * 8 + tg * 2;
                int mg  = mt * 64 + col;
                float2 vm = *(const float2*)&vmask[bb * NOBJ + mg];
                #pragma unroll
                for (int h = 0; h < 2; h++) {
                    int row = wm * 32 + ma * 16 + g + h * 8;
                    int ng  = nt * 64 + row;
                    __half2 tmh = *(const __half2*)&tmrow[(size_t)ng * NOBJ + mg];
                    float2 tm = __half22float2(tmh);
                    float cG0 = accG[ma][na][h * 2], cG1 = accG[ma][na][h * 2 + 1];
                    float cS0 = accS[ma][na][h * 2], cS1 = accS[ma][na][h * 2 + 1];
                    float wg0 = fmaxf(fmaxf(cG0, 0.f) + tm.x, 1e-6f);
                    float wg1 = fmaxf(fmaxf(cG1, 0.f) + tm.y, 1e-6f);
                    float t0 = wg0 * __expf(fminf(cS0 * 0.125f, 8.f)) * S_SCALE;
                    float t1 = wg1 * __expf(fminf(cS1 * 0.125f, 8.f)) * S_SCALE;
                    t0 = fminf(t0, 60000.f);
                    t1 = fminf(t1, 60000.f);
                    if (vm.x == 0.f) t0 = 0.f;
                    if (vm.y == 0.f) t1 = 0.f;
                    *(uint32_t*)(sSb + row * SPH + mg) = pack_f16(t0, t1);
                }
            }
        }
    }
    __syncthreads();   // sSb complete; tiles dead

    // issue V^T cp.async into overlay (overlaps row-sum compute)
    #pragma unroll
    for (int p = 0; p < 8; p++) {
        int idx = t + p * 256;
        int dk = idx >> 5, m16 = (idx & 31) * 8;
        cp_async16(sb0 + (uint32_t)(dk * SPH + m16) * 2, Vth + dk * NOBJ + m16);
    }
    CP_COMMIT();

    // ---- row sums -> 1/sum ----
    {
        int rrow = t >> 2;
        int lanei = t & 3;
        const uint32_t* rp = (const uint32_t*)(sSb + rrow * SPH);
        float sum = 0.f;
        for (int i = lanei; i < 128; i += 4) {
            __half2 h = *(const __half2*)&rp[i];
            float2 f = __half22float2(h);
            sum += f.x + f.y;
        }
        sum += __shfl_xor_sync(0xffffffffu, sum, 1);
        sum += __shfl_xor_sync(0xffffffffu, sum, 2);
        if (lanei == 0) sInv[rrow] = 1.f / fmaxf(sum, 1e-30f);
    }
    CP_WAIT0();
    __syncthreads();

    // ---- PV ----
    float accO[2][2][4];
    #pragma unroll
    for (int i = 0; i < 2; i++)
        #pragma unroll
        for (int j = 0; j < 2; j++)
            #pragma unroll
            for (int q = 0; q < 4; q++) accO[i][j][q] = 0.f;

    #pragma unroll 4
    for (int ks = 0; ks < 16; ks++) {
        uint32_t kb = (uint32_t)(ks * 16 * 2);
        uint32_t aP[2][4], bV[4];
        #pragma unroll
        for (int ma = 0; ma < 2; ma++)
            ldsm_x4(aP[ma], sb0 + SS_B + aoffS + (uint32_t)(ma * 16 * SPH * 2) + kb);
        ldsm_x4(bV, sb0 + boffV + kb);
        #pragma unroll
        for (int ma = 0; ma < 2; ma++) {
            mma_f16(accO[ma][0][0], accO[ma][0][1], accO[ma][0][2], accO[ma][0][3],
                    aP[ma][0], aP[ma][1], aP[ma][2], aP[ma][3], bV[0], bV[1]);
            mma_f16(accO[ma][1][0], accO[ma][1][1], accO[ma][1][2], accO[ma][1][3],
                    aP[ma][0], aP[ma][1], aP[ma][2], aP[ma][3], bV[2], bV[3]);
        }
    }

    // ---- normalize + residual + store ----
    #pragma unroll
    for (int ma = 0; ma < 2; ma++) {
        #pragma unroll
        for (int h = 0; h < 2; h++) {
            int row = wm * 32 + ma * 16 + g + h * 8;
            int ng  = nt * 64 + row;
            float inv = sInv[row];
            size_t base = ((size_t)bb * NOBJ + ng) * DIM + r * DK;
            #pragma unroll
            for (int na = 0; na < 2; na++) {
                int d = wn * 16 + na * 8 + tg * 2;
                float2 vres = *(const float2*)&vin[base + d];
                float2 o;
                o.x = accO[ma][na][h * 2]     * inv + vres.x;
                o.y = accO[ma][na][h * 2 + 1] * inv + vres.y;
                *(float2*)&out[base + d] = o;
            }
        }
    }
}

// ============================================================
extern "C" void kernel_launch(void* const* d_in, const int* in_sizes, int n_in,
                              void* d_out, int out_size)
{
    const float* v      = (const float*)d_in[0];
    const float* bmat   = (const float*)d_in[1];
    const float* vmask  = (const float*)d_in[2];
    const float* t      = (const float*)d_in[3];
    const float* tmask  = (const float*)d_in[4];
    const float* WG1_w  = (const float*)d_in[5];
    const float* WG1_b  = (const float*)d_in[6];
    const float* WG2_w  = (const float*)d_in[7];
    const float* WG2_b  = (const float*)d_in[8];
    const float* WK_w   = (const float*)d_in[9];
    const float* WK_b   = (const float*)d_in[10];
    const float* WQ_w   = (const float*)d_in[11];
    const float* WQ_b   = (const float*)d_in[12];
    const float* WV_w   = (const float*)d_in[13];
    const float* WV_b   = (const float*)d_in[14];
    const float* tc_w   = (const float*)d_in[15];
    const float* tc_b   = (const float*)d_in[16];
    const float* tmap_w = (const float*)d_in[17];
    const float* tmap_b = (const float*)d_in[18];
    float* out = (float*)d_out;

    cudaFuncSetAttribute(projtmap_kernel, cudaFuncAttributeMaxDynamicSharedMemorySize, PJ_SMEM);
    cudaFuncSetAttribute(projtmap_kernel, cudaFuncAttributePreferredSharedMemoryCarveout, 100);
    cudaFuncSetAttribute(attn_kernel, cudaFuncAttributeMaxDynamicSharedMemorySize, ATTN_SMEM);
    cudaFuncSetAttribute(attn_kernel, cudaFuncAttributePreferredSharedMemoryCarveout, 100);

    prep_kernel<<<64 + 1280 + 8192, 256>>>(
        t, tmask, tc_w, tc_b, v, bmat,
        WG1_w, WG2_w, WK_w, WQ_w, WV_w);
    projtmap_kernel<<<3072, 256, PJ_SMEM>>>(
        vmask, WG1_b, WG2_b, WK_b, WQ_b, WV_b, tmap_w, tmap_b);
    attn_kernel<<<dim3(4, RREL, BSZ), 256, ATTN_SMEM>>>(vmask, v, out);
}